// round 6
// baseline (speedup 1.0000x reference)
#include <cuda_runtime.h>
#include <cuda_bf16.h>
#include <cstddef>
#include <cstdint>

// Problem constants: B=16, N=512, D=256, H=8, DH=32, E=16384
// d_out layout (floats):
//   attended_img   [0,        2097152)
//   attended_text  [2097152,  4194304)
//   cross_modal    [4194304,  6291456)
//   img_weights    [6291456, 10485760)
//   text_weights   [10485760,14680064)
//   img_cons       [14680064,14688256)
//   text_cons      [14688256,14696448)

#define OFF_WCAT   0u             // 256*1280
#define OFF_BIAS1  327680u        // 1280
#define OFF_WOT    328960u        // 256*256
#define OFF_PROJ   394496u        // 16384*1280  (reused as H for consistency)
#define OFF_CTX    21366016u      // 16384*256
#define OFF_QC     25560320u      // 8192*256
#define OFF_KVC    27657472u      // 8192*512
#define OFF_CTX2   31851776u      // 8192*256
#define SCRATCH_FLOATS 33948928u

__device__ float g_scratch[SCRATCH_FLOATS];

// ---------------------------------------------------------------------------
__device__ __forceinline__ uint32_t f2tf32(float f) {
    uint32_t r;
    asm("cvt.rna.tf32.f32 %0, %1;" : "=r"(r) : "f"(f));
    return r;
}

__device__ __forceinline__ void mma_tf32(float& d0, float& d1, float& d2, float& d3,
                                         uint32_t a0, uint32_t a1, uint32_t a2, uint32_t a3,
                                         uint32_t b0, uint32_t b1)
{
    asm volatile(
        "mma.sync.aligned.m16n8k8.row.col.f32.tf32.tf32.f32 "
        "{%0,%1,%2,%3}, {%4,%5,%6,%7}, {%8,%9}, {%0,%1,%2,%3};"
        : "+f"(d0), "+f"(d1), "+f"(d2), "+f"(d3)
        : "r"(a0), "r"(a1), "r"(a2), "r"(a3), "r"(b0), "r"(b1));
}

// ---------------------------------------------------------------------------
// Pack: wcat[k][c] (256 x 1280), bias1[1280], wot = out_w^T (256x256)
// ---------------------------------------------------------------------------
__global__ void pack_kernel(const float* __restrict__ w1, const float* __restrict__ b1,
                            const float* __restrict__ in_w, const float* __restrict__ in_b,
                            const float* __restrict__ out_w,
                            float* __restrict__ wcat, float* __restrict__ bias1,
                            float* __restrict__ wot)
{
    int idx = blockIdx.x * 256 + threadIdx.x;
    if (idx < 327680) {
        int k = idx / 1280, c = idx % 1280;
        float v;
        if (c < 256)       v = w1[k * 256 + c];
        else if (c < 512)  v = w1[(256 + k) * 256 + (c - 256)];
        else if (c < 768)  v = in_w[(c - 512) * 256 + k];
        else if (c < 1024) v = in_w[(c - 768 + 256) * 256 + k];
        else               v = in_w[(c - 1024 + 512) * 256 + k];
        wcat[idx] = v;
    } else if (idx < 328960) {
        int c = idx - 327680;
        float v = (c < 256) ? b1[c] : (c < 512 ? 0.0f : in_b[c - 512]);
        bias1[c] = v;
    } else if (idx < 394496) {
        int i = idx - 328960;
        int k = i / 256, n = i % 256;
        wot[i] = out_w[n * 256 + k];
    }
}

// ---------------------------------------------------------------------------
// Tensor-core tf32 GEMM with register-prefetch double buffering.
// ---------------------------------------------------------------------------
__global__ void gemm_tc(const float* __restrict__ X0, const float* __restrict__ X1,
                        int ldx,
                        const float* __restrict__ W, int ldw, int woff,
                        const float* __restrict__ bias, int boff,
                        float* __restrict__ C, int ldc, size_t czstride, int relu)
{
    __shared__ uint32_t As[128][36];
    __shared__ uint32_t Bs[32][136];

    int z = blockIdx.z;
    const float* X = z ? X1 : X0;
    float* Cz = C + (size_t)z * czstride;

    int t = threadIdx.x;
    int lane = t & 31, w = t >> 5;
    int gid = lane >> 2, tig = lane & 3;
    int wm = w >> 2, wn = w & 3;
    int m0 = blockIdx.x * 128, n0 = blockIdx.y * 128;

    int ar[4], ac[4], br4[4], bc4[4];
    #pragma unroll
    for (int i = 0; i < 4; i++) {
        int lin = i * 1024 + t * 4;
        ar[i] = lin >> 5;  ac[i]  = lin & 31;
        br4[i] = lin >> 7; bc4[i] = lin & 127;
    }

    float acc[4][4][4];
    #pragma unroll
    for (int mi = 0; mi < 4; mi++)
        #pragma unroll
        for (int ni = 0; ni < 4; ni++)
            #pragma unroll
            for (int q = 0; q < 4; q++) acc[mi][ni][q] = 0.0f;

    float4 xa[4], wb[4];
    #pragma unroll
    for (int i = 0; i < 4; i++) {
        xa[i] = *(const float4*)(X + (size_t)(m0 + ar[i]) * ldx + ac[i]);
        wb[i] = *(const float4*)(W + (size_t)br4[i] * ldw + woff + n0 + bc4[i]);
    }

    for (int ch = 0; ch < 8; ch++) {
        #pragma unroll
        for (int i = 0; i < 4; i++) {
            As[ar[i]][ac[i] + 0] = f2tf32(xa[i].x);
            As[ar[i]][ac[i] + 1] = f2tf32(xa[i].y);
            As[ar[i]][ac[i] + 2] = f2tf32(xa[i].z);
            As[ar[i]][ac[i] + 3] = f2tf32(xa[i].w);
            Bs[br4[i]][bc4[i] + 0] = f2tf32(wb[i].x);
            Bs[br4[i]][bc4[i] + 1] = f2tf32(wb[i].y);
            Bs[br4[i]][bc4[i] + 2] = f2tf32(wb[i].z);
            Bs[br4[i]][bc4[i] + 3] = f2tf32(wb[i].w);
        }
        __syncthreads();

        if (ch < 7) {
            int k0 = (ch + 1) * 32;
            #pragma unroll
            for (int i = 0; i < 4; i++) {
                xa[i] = *(const float4*)(X + (size_t)(m0 + ar[i]) * ldx + k0 + ac[i]);
                wb[i] = *(const float4*)(W + (size_t)(k0 + br4[i]) * ldw + woff + n0 + bc4[i]);
            }
        }

        #pragma unroll
        for (int ks = 0; ks < 4; ks++) {
            int kk = ks * 8;
            uint32_t a[4][4], b[4][2];
            #pragma unroll
            for (int mi = 0; mi < 4; mi++) {
                int rb = wm * 64 + mi * 16 + gid;
                a[mi][0] = As[rb][kk + tig];
                a[mi][1] = As[rb + 8][kk + tig];
                a[mi][2] = As[rb][kk + tig + 4];
                a[mi][3] = As[rb + 8][kk + tig + 4];
            }
            #pragma unroll
            for (int ni = 0; ni < 4; ni++) {
                int cb = wn * 32 + ni * 8 + gid;
                b[ni][0] = Bs[kk + tig][cb];
                b[ni][1] = Bs[kk + tig + 4][cb];
            }
            #pragma unroll
            for (int mi = 0; mi < 4; mi++)
                #pragma unroll
                for (int ni = 0; ni < 4; ni++)
                    mma_tf32(acc[mi][ni][0], acc[mi][ni][1], acc[mi][ni][2], acc[mi][ni][3],
                             a[mi][0], a[mi][1], a[mi][2], a[mi][3],
                             b[ni][0], b[ni][1]);
        }
        __syncthreads();
    }

    #pragma unroll
    for (int mi = 0; mi < 4; mi++) {
        int r0 = m0 + wm * 64 + mi * 16 + gid;
        #pragma unroll
        for (int ni = 0; ni < 4; ni++) {
            int col = n0 + wn * 32 + ni * 8 + 2 * tig;
            float bb0 = bias ? bias[boff + col]     : 0.0f;
            float bb1 = bias ? bias[boff + col + 1] : 0.0f;
            float2 v0, v1;
            v0.x = acc[mi][ni][0] + bb0; v0.y = acc[mi][ni][1] + bb1;
            v1.x = acc[mi][ni][2] + bb0; v1.y = acc[mi][ni][3] + bb1;
            if (relu) {
                v0.x = fmaxf(v0.x, 0.0f); v0.y = fmaxf(v0.y, 0.0f);
                v1.x = fmaxf(v1.x, 0.0f); v1.y = fmaxf(v1.y, 0.0f);
            }
            *(float2*)(Cz + (size_t)r0 * ldc + col)       = v0;
            *(float2*)(Cz + (size_t)(r0 + 8) * ldc + col) = v1;
        }
    }
}

// ---------------------------------------------------------------------------
// Edge scatter: one warp per (modality, batch, edge).
// ---------------------------------------------------------------------------
__global__ void edge_kernel(const float* __restrict__ proj,
                            const int* __restrict__ src, const int* __restrict__ dst,
                            const float* __restrict__ w2, const float* __restrict__ b2p,
                            float* __restrict__ wout)
{
    int gw   = (blockIdx.x * blockDim.x + threadIdx.x) >> 5;
    int lane = threadIdx.x & 31;
    int e = gw & 16383;
    int b = (gw >> 14) & 15;
    int m = gw >> 18;
    int s = src[e], d = dst[e];

    const float4* ar = (const float4*)(proj + ((size_t)m * 8192 + b * 512 + s) * 1280);
    const float4* br = (const float4*)(proj + ((size_t)m * 8192 + b * 512 + d) * 1280 + 256);
    const float4* w4 = (const float4*)w2;

    float p = 0.0f;
    #pragma unroll
    for (int u = 0; u < 2; u++) {
        int idx = u * 32 + lane;
        float4 a = ar[idx], bb = br[idx], w = w4[idx];
        p += fmaxf(a.x + bb.x, 0.0f) * w.x;
        p += fmaxf(a.y + bb.y, 0.0f) * w.y;
        p += fmaxf(a.z + bb.z, 0.0f) * w.z;
        p += fmaxf(a.w + bb.w, 0.0f) * w.w;
    }
    #pragma unroll
    for (int off = 16; off > 0; off >>= 1)
        p += __shfl_xor_sync(0xFFFFFFFFu, p, off);
    if (lane == 0) {
        float v = 1.0f / (1.0f + __expf(-(p + b2p[0])));
        wout[(size_t)m * 4194304 + (size_t)b * 262144 + (size_t)s * 512 + d] = v;
    }
}

// ---------------------------------------------------------------------------
// Streaming tensor-core attention. 256 threads = 8 warps, 128 query rows.
// K/V streamed in 32-key double-buffered tiles (V stored transposed).
// Static smem 36 KB; __launch_bounds__(256,3) -> 24 warps/SM.
// grid = (4 chunks, 8 heads, Z); z -> (b = z&15, mz = z>>4).
// ---------------------------------------------------------------------------
__global__ __launch_bounds__(256, 3)
void attn_kernel(const float* __restrict__ qbuf, int qld, int qoff, size_t qzs,
                 const float* __restrict__ kbuf, int kld, int koff, size_t kzs,
                 const float* __restrict__ vbuf, int vld, int voff, size_t vzs,
                 const float* __restrict__ mask, size_t mzs,
                 float* __restrict__ ctx, size_t czs)
{
    __shared__ uint32_t sm[9216];
    // Ks tiles: sm[0 .. 2*1152)      : [bi][key(32)][36]
    // Vt tiles: sm[2304 .. 2*1152)   : [bi][d(32)][36]  (transposed V)
    // P:        sm[4608 + w*576]     : [16][36] per warp

    int zb = blockIdx.z;
    int b = zb & 15, mz = zb >> 4;
    const float* Q = qbuf + (size_t)mz * qzs;
    const float* K = kbuf + (size_t)mz * kzs;
    const float* V = vbuf + (size_t)mz * vzs;
    const float* M = mask ? mask + (size_t)mz * mzs : nullptr;
    float* O = ctx + (size_t)mz * czs;

    int h = blockIdx.y, chunk = blockIdx.x;
    int t = threadIdx.x, lane = t & 31, w = t >> 5;
    int gid = lane >> 2, tig = lane & 3;

    uint32_t* Pw = sm + 4608 + w * 576;
    int i0 = chunk * 128 + w * 16;
    const float scale = 0.17677669529663687f;  // 1/sqrt(32)

    // Q fragments, pre-scaled (held for whole kernel)
    uint32_t qa[4][4];
    {
        const float* q0p = Q + (size_t)(b * 512 + i0 + gid) * qld + qoff + h * 32;
        const float* q1p = q0p + (size_t)8 * qld;
        #pragma unroll
        for (int ks = 0; ks < 4; ks++) {
            qa[ks][0] = f2tf32(q0p[ks * 8 + tig] * scale);
            qa[ks][1] = f2tf32(q1p[ks * 8 + tig] * scale);
            qa[ks][2] = f2tf32(q0p[ks * 8 + tig + 4] * scale);
            qa[ks][3] = f2tf32(q1p[ks * 8 + tig + 4] * scale);
        }
    }

    const float* mrow0 = M ? M + (size_t)b * 262144 + (size_t)(i0 + gid) * 512 : nullptr;
    const float* mrow1 = mrow0 ? mrow0 + 8 * 512 : nullptr;

    // staging coords: thread t loads key (tile*32 + key_l), dims c4..c4+3
    int key_l = t >> 3, c4 = (t & 7) * 4;
    const float* kbase = K + (size_t)(b * 512) * kld + koff + h * 32 + c4;
    const float* vbase = V + (size_t)(b * 512) * vld + voff + h * 32 + c4;

    float oacc[4][4];
    #pragma unroll
    for (int vt = 0; vt < 4; vt++)
        #pragma unroll
        for (int q = 0; q < 4; q++) oacc[vt][q] = 0.0f;
    float rsum0 = 0.0f, rsum1 = 0.0f;

    // prefetch tile 0
    float4 kreg = *(const float4*)(kbase + (size_t)key_l * kld);
    float4 vreg = *(const float4*)(vbase + (size_t)key_l * vld);

    for (int t16 = 0; t16 < 16; t16++) {
        uint32_t* Ks = sm + (t16 & 1) * 1152;
        uint32_t* Vt = sm + 2304 + (t16 & 1) * 1152;

        // store staged tile (K row-major, V transposed)
        {
            uint4 kt;
            kt.x = f2tf32(kreg.x); kt.y = f2tf32(kreg.y);
            kt.z = f2tf32(kreg.z); kt.w = f2tf32(kreg.w);
            *(uint4*)&Ks[key_l * 36 + c4] = kt;
            Vt[(c4 + 0) * 36 + key_l] = f2tf32(vreg.x);
            Vt[(c4 + 1) * 36 + key_l] = f2tf32(vreg.y);
            Vt[(c4 + 2) * 36 + key_l] = f2tf32(vreg.z);
            Vt[(c4 + 3) * 36 + key_l] = f2tf32(vreg.w);
        }
        __syncthreads();

        // prefetch next tile (latency hidden by compute)
        if (t16 < 15) {
            size_t off = (size_t)((t16 + 1) * 32 + key_l);
            kreg = *(const float4*)(kbase + off * kld);
            vreg = *(const float4*)(vbase + off * vld);
        }

        // mask loads for this tile (issued before mma block)
        float2 mc0[4], mc1[4];
        if (mrow0) {
            #pragma unroll
            for (int nt = 0; nt < 4; nt++) {
                int col = t16 * 32 + nt * 8 + 2 * tig;
                mc0[nt] = *(const float2*)(mrow0 + col);
                mc1[nt] = *(const float2*)(mrow1 + col);
            }
        }

        // S = Q K^T for 32 keys
        float sacc[4][4];
        #pragma unroll
        for (int nt = 0; nt < 4; nt++)
            #pragma unroll
            for (int q = 0; q < 4; q++) sacc[nt][q] = 0.0f;

        #pragma unroll
        for (int ks = 0; ks < 4; ks++) {
            #pragma unroll
            for (int nt = 0; nt < 4; nt++) {
                int key = nt * 8 + gid;
                uint32_t b0 = Ks[key * 36 + ks * 8 + tig];
                uint32_t b1 = Ks[key * 36 + ks * 8 + tig + 4];
                mma_tf32(sacc[nt][0], sacc[nt][1], sacc[nt][2], sacc[nt][3],
                         qa[ks][0], qa[ks][1], qa[ks][2], qa[ks][3], b0, b1);
            }
        }

        // exp (+mask), row sums, stash P (tf32)
        #pragma unroll
        for (int nt = 0; nt < 4; nt++) {
            float s0 = sacc[nt][0], s1 = sacc[nt][1];
            float s2 = sacc[nt][2], s3 = sacc[nt][3];
            if (mrow0) {
                s0 += mc0[nt].x; s1 += mc0[nt].y;
                s2 += mc1[nt].x; s3 += mc1[nt].y;
            }
            float p0 = __expf(s0), p1 = __expf(s1);
            float p2 = __expf(s2), p3 = __expf(s3);
            rsum0 += p0 + p1;
            rsum1 += p2 + p3;
            uint2 u0; u0.x = f2tf32(p0); u0.y = f2tf32(p1);
            uint2 u1; u1.x = f2tf32(p2); u1.y = f2tf32(p3);
            *(uint2*)&Pw[gid * 36 + nt * 8 + 2 * tig]       = u0;
            *(uint2*)&Pw[(gid + 8) * 36 + nt * 8 + 2 * tig] = u1;
        }
        __syncwarp();

        // O += P V
        #pragma unroll
        for (int ks2 = 0; ks2 < 4; ks2++) {
            uint32_t a0 = Pw[gid * 36 + ks2 * 8 + tig];
            uint32_t a1 = Pw[(gid + 8) * 36 + ks2 * 8 + tig];
            uint32_t a2 = Pw[gid * 36 + ks2 * 8 + tig + 4];
            uint32_t a3 = Pw[(gid + 8) * 36 + ks2 * 8 + tig + 4];
            #pragma unroll
            for (int vt = 0; vt < 4; vt++) {
                uint32_t b0 = Vt[(vt * 8 + gid) * 36 + ks2 * 8 + tig];
                uint32_t b1 = Vt[(vt * 8 + gid) * 36 + ks2 * 8 + tig + 4];
                mma_tf32(oacc[vt][0], oacc[vt][1], oacc[vt][2], oacc[vt][3],
                         a0, a1, a2, a3, b0, b1);
            }
        }
    }

    rsum0 += __shfl_xor_sync(0xFFFFFFFFu, rsum0, 1);
    rsum0 += __shfl_xor_sync(0xFFFFFFFFu, rsum0, 2);
    rsum1 += __shfl_xor_sync(0xFFFFFFFFu, rsum1, 1);
    rsum1 += __shfl_xor_sync(0xFFFFFFFFu, rsum1, 2);
    float inv0 = 1.0f / rsum0, inv1 = 1.0f / rsum1;

    size_t r0 = (size_t)(b * 512 + i0 + gid) * 256 + h * 32;
    size_t r1 = r0 + (size_t)8 * 256;
    #pragma unroll
    for (int vt = 0; vt < 4; vt++) {
        float2 v0; v0.x = oacc[vt][0] * inv0; v0.y = oacc[vt][1] * inv0;
        float2 v1; v1.x = oacc[vt][2] * inv1; v1.y = oacc[vt][3] * inv1;
        *(float2*)(O + r0 + vt * 8 + 2 * tig) = v0;
        *(float2*)(O + r1 + vt * 8 + 2 * tig) = v1;
    }
}

// ---------------------------------------------------------------------------
__global__ void cons_reduce(const float* __restrict__ H, const float* __restrict__ cw2,
                            const float* __restrict__ cb2, float* __restrict__ out)
{
    int gw   = (blockIdx.x * blockDim.x + threadIdx.x) >> 5;
    int lane = threadIdx.x & 31;
    const float4* h4 = (const float4*)(H + (size_t)gw * 256);
    const float4* w4 = (const float4*)cw2;
    float p = 0.0f;
    #pragma unroll
    for (int u = 0; u < 2; u++) {
        int idx = u * 32 + lane;
        float4 a = h4[idx], w = w4[idx];
        p += a.x * w.x + a.y * w.y + a.z * w.z + a.w * w.w;
    }
    #pragma unroll
    for (int off = 16; off > 0; off >>= 1)
        p += __shfl_xor_sync(0xFFFFFFFFu, p, off);
    if (lane == 0)
        out[gw] = 1.0f / (1.0f + __expf(-(p + cb2[0])));
}

// ---------------------------------------------------------------------------
extern "C" void kernel_launch(void* const* d_in, const int* in_sizes, int n_in,
                              void* d_out, int out_size)
{
    const float* img   = (const float*)d_in[0];
    const float* txt   = (const float*)d_in[1];
    const int*   src   = (const int*)  d_in[2];
    const int*   dst   = (const int*)  d_in[3];
    const float* w1    = (const float*)d_in[4];
    const float* b1    = (const float*)d_in[5];
    const float* w2    = (const float*)d_in[6];
    const float* b2    = (const float*)d_in[7];
    const float* in_w  = (const float*)d_in[8];
    const float* in_b  = (const float*)d_in[9];
    const float* out_w = (const float*)d_in[10];
    const float* out_b = (const float*)d_in[11];
    const float* cw1   = (const float*)d_in[12];
    const float* cb1   = (const float*)d_in[13];
    const float* cw2   = (const float*)d_in[14];
    const float* cb2   = (const float*)d_in[15];
    float* out = (float*)d_out;

    float* S = nullptr;
    cudaGetSymbolAddress((void**)&S, g_scratch);

    float* wcat  = S + OFF_WCAT;
    float* bias1 = S + OFF_BIAS1;
    float* wot   = S + OFF_WOT;
    float* proj  = S + OFF_PROJ;
    float* ctx   = S + OFF_CTX;
    float* qc    = S + OFF_QC;
    float* kvc   = S + OFF_KVC;
    float* ctx2  = S + OFF_CTX2;
    float* Hbuf  = proj;

    float* att_img = out;
    float* att_txt = out + 2097152;
    float* cross   = out + 4194304;
    float* wimg    = out + 6291456;
    float* cons    = out + 14680064;

    const size_t PSTRIDE = (size_t)8192 * 1280;
    const size_t CSTRIDE = (size_t)8192 * 256;
    const size_t MSTRIDE = (size_t)4194304;

    // 1. pack fused weights
    pack_kernel<<<1541, 256>>>(w1, b1, in_w, in_b, out_w, wcat, bias1, wot);

    // 2. zero both weight matrices
    cudaMemsetAsync(wimg, 0, (size_t)8388608 * 4);

    // 3. fused node projections (both modalities, grid.z=2)
    gemm_tc<<<dim3(64, 10, 2), 256>>>(img, txt, 256, wcat, 1280, 0, bias1, 0,
                                      proj, 1280, PSTRIDE, 0);

    // 4. per-edge causal weights (both modalities)
    edge_kernel<<<65536, 256>>>(proj, src, dst, w2, b2, wimg);

    // 5. masked self-attention, both modalities (grid.z=32, streaming blocks)
    attn_kernel<<<dim3(4, 8, 32), 256>>>(
        proj, 1280, 512, PSTRIDE,
        proj, 1280, 768, PSTRIDE,
        proj, 1280, 1024, PSTRIDE,
        wimg, MSTRIDE,
        ctx, CSTRIDE);

    // 6. out-proj for both modalities -> attended_*
    gemm_tc<<<dim3(128, 2, 1), 256>>>(ctx, ctx, 256, wot, 256, 0, out_b, 0,
                                      att_img, 256, 0, 0);

    // 7. consistency
    gemm_tc<<<dim3(128, 2, 1), 256>>>(att_img, att_img, 256, cw1, 256, 0, cb1, 0,
                                      Hbuf, 256, 0, 1);
    cons_reduce<<<2048, 256>>>(Hbuf, cw2, cb2, cons);

    // 8. cross-modal
    gemm_tc<<<dim3(64, 2, 1), 256>>>(att_img, att_img, 256, wcat, 1280, 512, bias1, 512,
                                     qc, 256, 0, 0);
    gemm_tc<<<dim3(64, 4, 1), 256>>>(att_txt, att_txt, 256, wcat, 1280, 768, bias1, 768,
                                     kvc, 512, 0, 0);
    attn_kernel<<<dim3(4, 8, 16), 256>>>(
        qc, 256, 0, 0,
        kvc, 512, 0, 0,
        kvc, 512, 256, 0,
        nullptr, 0,
        ctx2, 0);
    gemm_tc<<<dim3(64, 2, 1), 256>>>(ctx2, ctx2, 256, wot, 256, 0, out_b, 0,
                                     cross, 256, 0, 0);
}

// round 7
// speedup vs baseline: 1.0671x; 1.0671x over previous
#include <cuda_runtime.h>
#include <cuda_bf16.h>
#include <cstddef>
#include <cstdint>

// Problem constants: B=16, N=512, D=256, H=8, DH=32, E=16384
// d_out layout (floats):
//   attended_img   [0,        2097152)
//   attended_text  [2097152,  4194304)
//   cross_modal    [4194304,  6291456)
//   img_weights    [6291456, 10485760)
//   text_weights   [10485760,14680064)
//   img_cons       [14680064,14688256)
//   text_cons      [14688256,14696448)

#define OFF_WCAT   0u             // 256*1280
#define OFF_BIAS1  327680u        // 1280
#define OFF_WOT    328960u        // 256*256
#define OFF_PROJ   394496u        // 16384*1280  (reused as H for consistency)
#define OFF_CTX    21366016u      // 16384*256
#define OFF_QC     25560320u      // 8192*256
#define OFF_KVC    27657472u      // 8192*512
#define OFF_CTX2   31851776u      // 8192*256
#define OFF_BF     33948928u      // bf16 A|Bm buffer: 16384*512 bf16 = 4194304 floats
#define SCRATCH_FLOATS 38143232u

__device__ float g_scratch[SCRATCH_FLOATS];

// ---------------------------------------------------------------------------
__device__ __forceinline__ uint32_t f2tf32(float f) {
    uint32_t r;
    asm("cvt.rna.tf32.f32 %0, %1;" : "=r"(r) : "f"(f));
    return r;
}

__device__ __forceinline__ void mma_tf32(float& d0, float& d1, float& d2, float& d3,
                                         uint32_t a0, uint32_t a1, uint32_t a2, uint32_t a3,
                                         uint32_t b0, uint32_t b1)
{
    asm volatile(
        "mma.sync.aligned.m16n8k8.row.col.f32.tf32.tf32.f32 "
        "{%0,%1,%2,%3}, {%4,%5,%6,%7}, {%8,%9}, {%0,%1,%2,%3};"
        : "+f"(d0), "+f"(d1), "+f"(d2), "+f"(d3)
        : "r"(a0), "r"(a1), "r"(a2), "r"(a3), "r"(b0), "r"(b1));
}

// ---------------------------------------------------------------------------
// Pack: wcat[k][c] (256 x 1280), bias1[1280], wot = out_w^T (256x256)
// ---------------------------------------------------------------------------
__global__ void pack_kernel(const float* __restrict__ w1, const float* __restrict__ b1,
                            const float* __restrict__ in_w, const float* __restrict__ in_b,
                            const float* __restrict__ out_w,
                            float* __restrict__ wcat, float* __restrict__ bias1,
                            float* __restrict__ wot)
{
    int idx = blockIdx.x * 256 + threadIdx.x;
    if (idx < 327680) {
        int k = idx / 1280, c = idx % 1280;
        float v;
        if (c < 256)       v = w1[k * 256 + c];
        else if (c < 512)  v = w1[(256 + k) * 256 + (c - 256)];
        else if (c < 768)  v = in_w[(c - 512) * 256 + k];
        else if (c < 1024) v = in_w[(c - 768 + 256) * 256 + k];
        else               v = in_w[(c - 1024 + 512) * 256 + k];
        wcat[idx] = v;
    } else if (idx < 328960) {
        int c = idx - 327680;
        float v = (c < 256) ? b1[c] : (c < 512 ? 0.0f : in_b[c - 512]);
        bias1[c] = v;
    } else if (idx < 394496) {
        int i = idx - 328960;
        int k = i / 256, n = i % 256;
        wot[i] = out_w[n * 256 + k];
    }
}

// ---------------------------------------------------------------------------
// Tensor-core tf32 GEMM with register-prefetch double buffering.
// Optional bfaux: epilogue also stores cols < 512 as bf16 at
//   bfaux[(z*8192 + row)*512 + col]  (A|Bm copy for the edge kernel).
// ---------------------------------------------------------------------------
__global__ void gemm_tc(const float* __restrict__ X0, const float* __restrict__ X1,
                        int ldx,
                        const float* __restrict__ W, int ldw, int woff,
                        const float* __restrict__ bias, int boff,
                        float* __restrict__ C, int ldc, size_t czstride, int relu,
                        __nv_bfloat16* __restrict__ bfaux)
{
    __shared__ uint32_t As[128][36];
    __shared__ uint32_t Bs[32][136];

    int z = blockIdx.z;
    const float* X = z ? X1 : X0;
    float* Cz = C + (size_t)z * czstride;

    int t = threadIdx.x;
    int lane = t & 31, w = t >> 5;
    int gid = lane >> 2, tig = lane & 3;
    int wm = w >> 2, wn = w & 3;
    int m0 = blockIdx.x * 128, n0 = blockIdx.y * 128;

    int ar[4], ac[4], br4[4], bc4[4];
    #pragma unroll
    for (int i = 0; i < 4; i++) {
        int lin = i * 1024 + t * 4;
        ar[i] = lin >> 5;  ac[i]  = lin & 31;
        br4[i] = lin >> 7; bc4[i] = lin & 127;
    }

    float acc[4][4][4];
    #pragma unroll
    for (int mi = 0; mi < 4; mi++)
        #pragma unroll
        for (int ni = 0; ni < 4; ni++)
            #pragma unroll
            for (int q = 0; q < 4; q++) acc[mi][ni][q] = 0.0f;

    float4 xa[4], wb[4];
    #pragma unroll
    for (int i = 0; i < 4; i++) {
        xa[i] = *(const float4*)(X + (size_t)(m0 + ar[i]) * ldx + ac[i]);
        wb[i] = *(const float4*)(W + (size_t)br4[i] * ldw + woff + n0 + bc4[i]);
    }

    for (int ch = 0; ch < 8; ch++) {
        #pragma unroll
        for (int i = 0; i < 4; i++) {
            As[ar[i]][ac[i] + 0] = f2tf32(xa[i].x);
            As[ar[i]][ac[i] + 1] = f2tf32(xa[i].y);
            As[ar[i]][ac[i] + 2] = f2tf32(xa[i].z);
            As[ar[i]][ac[i] + 3] = f2tf32(xa[i].w);
            Bs[br4[i]][bc4[i] + 0] = f2tf32(wb[i].x);
            Bs[br4[i]][bc4[i] + 1] = f2tf32(wb[i].y);
            Bs[br4[i]][bc4[i] + 2] = f2tf32(wb[i].z);
            Bs[br4[i]][bc4[i] + 3] = f2tf32(wb[i].w);
        }
        __syncthreads();

        if (ch < 7) {
            int k0 = (ch + 1) * 32;
            #pragma unroll
            for (int i = 0; i < 4; i++) {
                xa[i] = *(const float4*)(X + (size_t)(m0 + ar[i]) * ldx + k0 + ac[i]);
                wb[i] = *(const float4*)(W + (size_t)(k0 + br4[i]) * ldw + woff + n0 + bc4[i]);
            }
        }

        #pragma unroll
        for (int ks = 0; ks < 4; ks++) {
            int kk = ks * 8;
            uint32_t a[4][4], b[4][2];
            #pragma unroll
            for (int mi = 0; mi < 4; mi++) {
                int rb = wm * 64 + mi * 16 + gid;
                a[mi][0] = As[rb][kk + tig];
                a[mi][1] = As[rb + 8][kk + tig];
                a[mi][2] = As[rb][kk + tig + 4];
                a[mi][3] = As[rb + 8][kk + tig + 4];
            }
            #pragma unroll
            for (int ni = 0; ni < 4; ni++) {
                int cb = wn * 32 + ni * 8 + gid;
                b[ni][0] = Bs[kk + tig][cb];
                b[ni][1] = Bs[kk + tig + 4][cb];
            }
            #pragma unroll
            for (int mi = 0; mi < 4; mi++)
                #pragma unroll
                for (int ni = 0; ni < 4; ni++)
                    mma_tf32(acc[mi][ni][0], acc[mi][ni][1], acc[mi][ni][2], acc[mi][ni][3],
                             a[mi][0], a[mi][1], a[mi][2], a[mi][3],
                             b[ni][0], b[ni][1]);
        }
        __syncthreads();
    }

    #pragma unroll
    for (int mi = 0; mi < 4; mi++) {
        int r0 = m0 + wm * 64 + mi * 16 + gid;
        #pragma unroll
        for (int ni = 0; ni < 4; ni++) {
            int col = n0 + wn * 32 + ni * 8 + 2 * tig;
            float bb0 = bias ? bias[boff + col]     : 0.0f;
            float bb1 = bias ? bias[boff + col + 1] : 0.0f;
            float2 v0, v1;
            v0.x = acc[mi][ni][0] + bb0; v0.y = acc[mi][ni][1] + bb1;
            v1.x = acc[mi][ni][2] + bb0; v1.y = acc[mi][ni][3] + bb1;
            if (relu) {
                v0.x = fmaxf(v0.x, 0.0f); v0.y = fmaxf(v0.y, 0.0f);
                v1.x = fmaxf(v1.x, 0.0f); v1.y = fmaxf(v1.y, 0.0f);
            }
            *(float2*)(Cz + (size_t)r0 * ldc + col)       = v0;
            *(float2*)(Cz + (size_t)(r0 + 8) * ldc + col) = v1;
            if (bfaux && col < 512) {
                __nv_bfloat162 h0 = __float22bfloat162_rn(v0);
                __nv_bfloat162 h1 = __float22bfloat162_rn(v1);
                *(__nv_bfloat162*)(bfaux + ((size_t)z * 8192 + r0) * 512 + col)       = h0;
                *(__nv_bfloat162*)(bfaux + ((size_t)z * 8192 + r0 + 8) * 512 + col)   = h1;
            }
        }
    }
}

// ---------------------------------------------------------------------------
// Edge scatter (bf16 activations): one warp per (modality, batch, edge).
// ab rows: [m*8192 + b*512 + node][512] bf16 = A(256) | Bm(256).
// ---------------------------------------------------------------------------
__global__ void edge_kernel(const __nv_bfloat16* __restrict__ ab,
                            const int* __restrict__ src, const int* __restrict__ dst,
                            const float* __restrict__ w2, const float* __restrict__ b2p,
                            float* __restrict__ wout)
{
    int gw   = (blockIdx.x * blockDim.x + threadIdx.x) >> 5;
    int lane = threadIdx.x & 31;
    int e = gw & 16383;
    int b = (gw >> 14) & 15;
    int m = gw >> 18;
    int s = src[e], d = dst[e];

    const uint4* arow = (const uint4*)(ab + ((size_t)m * 8192 + b * 512 + s) * 512);
    const uint4* brow = (const uint4*)(ab + ((size_t)m * 8192 + b * 512 + d) * 512 + 256);
    uint4 av = arow[lane];              // 8 bf16: elems lane*8 .. lane*8+7 of A
    uint4 bv = brow[lane];              // 8 bf16 of Bm
    float4 wlo = *(const float4*)(w2 + lane * 8);
    float4 whi = *(const float4*)(w2 + lane * 8 + 4);

    float2 a0 = __bfloat1622float2(*reinterpret_cast<const __nv_bfloat162*>(&av.x));
    float2 a1 = __bfloat1622float2(*reinterpret_cast<const __nv_bfloat162*>(&av.y));
    float2 a2 = __bfloat1622float2(*reinterpret_cast<const __nv_bfloat162*>(&av.z));
    float2 a3 = __bfloat1622float2(*reinterpret_cast<const __nv_bfloat162*>(&av.w));
    float2 b0 = __bfloat1622float2(*reinterpret_cast<const __nv_bfloat162*>(&bv.x));
    float2 b1 = __bfloat1622float2(*reinterpret_cast<const __nv_bfloat162*>(&bv.y));
    float2 b2v = __bfloat1622float2(*reinterpret_cast<const __nv_bfloat162*>(&bv.z));
    float2 b3 = __bfloat1622float2(*reinterpret_cast<const __nv_bfloat162*>(&bv.w));

    float p = 0.0f;
    p += fmaxf(a0.x + b0.x, 0.0f) * wlo.x;
    p += fmaxf(a0.y + b0.y, 0.0f) * wlo.y;
    p += fmaxf(a1.x + b1.x, 0.0f) * wlo.z;
    p += fmaxf(a1.y + b1.y, 0.0f) * wlo.w;
    p += fmaxf(a2.x + b2v.x, 0.0f) * whi.x;
    p += fmaxf(a2.y + b2v.y, 0.0f) * whi.y;
    p += fmaxf(a3.x + b3.x, 0.0f) * whi.z;
    p += fmaxf(a3.y + b3.y, 0.0f) * whi.w;

    #pragma unroll
    for (int off = 16; off > 0; off >>= 1)
        p += __shfl_xor_sync(0xFFFFFFFFu, p, off);
    if (lane == 0) {
        float v = 1.0f / (1.0f + __expf(-(p + b2p[0])));
        wout[(size_t)m * 4194304 + (size_t)b * 262144 + (size_t)s * 512 + d] = v;
    }
}

// ---------------------------------------------------------------------------
// Tensor-core attention, 512 threads / 16 warps per block (256 query rows).
// K/V resident per (b,h). grid = (2 chunks, 8 heads, Z); z -> (b, mz).
// Smem 225280 B. (Round-5 version — fastest measured.)
// ---------------------------------------------------------------------------
__global__ __launch_bounds__(512, 1)
void attn_kernel(const float* __restrict__ qbuf, int qld, int qoff, size_t qzs,
                 const float* __restrict__ kbuf, int kld, int koff, size_t kzs,
                 const float* __restrict__ vbuf, int vld, int voff, size_t vzs,
                 const float* __restrict__ mask, size_t mzs,
                 float* __restrict__ ctx, size_t czs)
{
    extern __shared__ uint32_t sm[];
    uint32_t* Ks = sm;               // [512][36]
    uint32_t* Vs = sm + 18432;       // [512][40]
    uint32_t* Pw = sm + 38912;       // 16 warps x [16][68]

    int zb = blockIdx.z;
    int b = zb & 15, mz = zb >> 4;
    const float* Q = qbuf + (size_t)mz * qzs;
    const float* K = kbuf + (size_t)mz * kzs;
    const float* V = vbuf + (size_t)mz * vzs;
    const float* M = mask ? mask + (size_t)mz * mzs : nullptr;
    float* O = ctx + (size_t)mz * czs;

    int h = blockIdx.y, chunk = blockIdx.x;
    int t = threadIdx.x, lane = t & 31, w = t >> 5;
    int gid = lane >> 2, tig = lane & 3;

    for (int i = t; i < 4096; i += 512) {
        int row = i >> 3, c4 = (i & 7) * 4;
        size_t rk = (size_t)(b * 512 + row);
        float4 kv = *(const float4*)(K + rk * kld + koff + h * 32 + c4);
        uint4 kt; kt.x = f2tf32(kv.x); kt.y = f2tf32(kv.y); kt.z = f2tf32(kv.z); kt.w = f2tf32(kv.w);
        *(uint4*)&Ks[row * 36 + c4] = kt;
        float4 vv = *(const float4*)(V + rk * vld + voff + h * 32 + c4);
        uint4 vt; vt.x = f2tf32(vv.x); vt.y = f2tf32(vv.y); vt.z = f2tf32(vv.z); vt.w = f2tf32(vv.w);
        *(uint4*)&Vs[row * 40 + c4] = vt;
    }
    __syncthreads();

    uint32_t* Ps = Pw + w * 1088;
    int i0 = chunk * 256 + w * 16;
    const float scale = 0.17677669529663687f;  // 1/sqrt(32)

    uint32_t qa[4][4];
    {
        const float* q0p = Q + (size_t)(b * 512 + i0 + gid) * qld + qoff + h * 32;
        const float* q1p = q0p + (size_t)8 * qld;
        #pragma unroll
        for (int ks = 0; ks < 4; ks++) {
            qa[ks][0] = f2tf32(q0p[ks * 8 + tig] * scale);
            qa[ks][1] = f2tf32(q1p[ks * 8 + tig] * scale);
            qa[ks][2] = f2tf32(q0p[ks * 8 + tig + 4] * scale);
            qa[ks][3] = f2tf32(q1p[ks * 8 + tig + 4] * scale);
        }
    }

    const float* mrow0 = M ? M + (size_t)b * 262144 + (size_t)(i0 + gid) * 512 : nullptr;
    const float* mrow1 = mrow0 ? mrow0 + 8 * 512 : nullptr;

    float oacc[4][4];
    #pragma unroll
    for (int vt = 0; vt < 4; vt++)
        #pragma unroll
        for (int q = 0; q < 4; q++) oacc[vt][q] = 0.0f;
    float rsum0 = 0.0f, rsum1 = 0.0f;

    for (int kc = 0; kc < 8; kc++) {
        float2 mv0[8], mv1[8];
        if (mrow0) {
            #pragma unroll
            for (int nt = 0; nt < 8; nt++) {
                int col = kc * 64 + nt * 8 + 2 * tig;
                mv0[nt] = *(const float2*)(mrow0 + col);
                mv1[nt] = *(const float2*)(mrow1 + col);
            }
        }

        float sacc[8][4];
        #pragma unroll
        for (int nt = 0; nt < 8; nt++)
            #pragma unroll
            for (int q = 0; q < 4; q++) sacc[nt][q] = 0.0f;

        #pragma unroll
        for (int ks = 0; ks < 4; ks++) {
            #pragma unroll
            for (int nt = 0; nt < 8; nt++) {
                int key = kc * 64 + nt * 8 + gid;
                uint32_t b0 = Ks[key * 36 + ks * 8 + tig];
                uint32_t b1 = Ks[key * 36 + ks * 8 + tig + 4];
                mma_tf32(sacc[nt][0], sacc[nt][1], sacc[nt][2], sacc[nt][3],
                         qa[ks][0], qa[ks][1], qa[ks][2], qa[ks][3], b0, b1);
            }
        }

        #pragma unroll
        for (int nt = 0; nt < 8; nt++) {
            float s0 = sacc[nt][0], s1 = sacc[nt][1];
            float s2 = sacc[nt][2], s3 = sacc[nt][3];
            if (mrow0) {
                s0 += mv0[nt].x; s1 += mv0[nt].y;
                s2 += mv1[nt].x; s3 += mv1[nt].y;
            }
            float p0 = __expf(s0), p1 = __expf(s1);
            float p2 = __expf(s2), p3 = __expf(s3);
            rsum0 += p0 + p1;
            rsum1 += p2 + p3;
            uint2 u0; u0.x = f2tf32(p0); u0.y = f2tf32(p1);
            uint2 u1; u1.x = f2tf32(p2); u1.y = f2tf32(p3);
            *(uint2*)&Ps[gid * 68 + nt * 8 + 2 * tig]       = u0;
            *(uint2*)&Ps[(gid + 8) * 68 + nt * 8 + 2 * tig] = u1;
        }
        __syncwarp();

        #pragma unroll
        for (int ks2 = 0; ks2 < 8; ks2++) {
            uint32_t a0 = Ps[gid * 68 + ks2 * 8 + tig];
            uint32_t a1 = Ps[(gid + 8) * 68 + ks2 * 8 + tig];
            uint32_t a2 = Ps[gid * 68 + ks2 * 8 + tig + 4];
            uint32_t a3 = Ps[(gid + 8) * 68 + ks2 * 8 + tig + 4];
            int keyb = kc * 64 + ks2 * 8;
            #pragma unroll
            for (int vt = 0; vt < 4; vt++) {
                uint32_t b0 = Vs[(keyb + tig) * 40 + vt * 8 + gid];
                uint32_t b1 = Vs[(keyb + tig + 4) * 40 + vt * 8 + gid];
                mma_tf32(oacc[vt][0], oacc[vt][1], oacc[vt][2], oacc[vt][3],
                         a0, a1, a2, a3, b0, b1);
            }
        }
        __syncwarp();
    }

    rsum0 += __shfl_xor_sync(0xFFFFFFFFu, rsum0, 1);
    rsum0 += __shfl_xor_sync(0xFFFFFFFFu, rsum0, 2);
    rsum1 += __shfl_xor_sync(0xFFFFFFFFu, rsum1, 1);
    rsum1 += __shfl_xor_sync(0xFFFFFFFFu, rsum1, 2);
    float inv0 = 1.0f / rsum0, inv1 = 1.0f / rsum1;

    size_t r0 = (size_t)(b * 512 + i0 + gid) * 256 + h * 32;
    size_t r1 = r0 + (size_t)8 * 256;
    #pragma unroll
    for (int vt = 0; vt < 4; vt++) {
        float2 v0; v0.x = oacc[vt][0] * inv0; v0.y = oacc[vt][1] * inv0;
        float2 v1; v1.x = oacc[vt][2] * inv1; v1.y = oacc[vt][3] * inv1;
        *(float2*)(O + r0 + vt * 8 + 2 * tig) = v0;
        *(float2*)(O + r1 + vt * 8 + 2 * tig) = v1;
    }
}

// ---------------------------------------------------------------------------
__global__ void cons_reduce(const float* __restrict__ H, const float* __restrict__ cw2,
                            const float* __restrict__ cb2, float* __restrict__ out)
{
    int gw   = (blockIdx.x * blockDim.x + threadIdx.x) >> 5;
    int lane = threadIdx.x & 31;
    const float4* h4 = (const float4*)(H + (size_t)gw * 256);
    const float4* w4 = (const float4*)cw2;
    float p = 0.0f;
    #pragma unroll
    for (int u = 0; u < 2; u++) {
        int idx = u * 32 + lane;
        float4 a = h4[idx], w = w4[idx];
        p += a.x * w.x + a.y * w.y + a.z * w.z + a.w * w.w;
    }
    #pragma unroll
    for (int off = 16; off > 0; off >>= 1)
        p += __shfl_xor_sync(0xFFFFFFFFu, p, off);
    if (lane == 0)
        out[gw] = 1.0f / (1.0f + __expf(-(p + cb2[0])));
}

// ---------------------------------------------------------------------------
extern "C" void kernel_launch(void* const* d_in, const int* in_sizes, int n_in,
                              void* d_out, int out_size)
{
    const float* img   = (const float*)d_in[0];
    const float* txt   = (const float*)d_in[1];
    const int*   src   = (const int*)  d_in[2];
    const int*   dst   = (const int*)  d_in[3];
    const float* w1    = (const float*)d_in[4];
    const float* b1    = (const float*)d_in[5];
    const float* w2    = (const float*)d_in[6];
    const float* b2    = (const float*)d_in[7];
    const float* in_w  = (const float*)d_in[8];
    const float* in_b  = (const float*)d_in[9];
    const float* out_w = (const float*)d_in[10];
    const float* out_b = (const float*)d_in[11];
    const float* cw1   = (const float*)d_in[12];
    const float* cb1   = (const float*)d_in[13];
    const float* cw2   = (const float*)d_in[14];
    const float* cb2   = (const float*)d_in[15];
    float* out = (float*)d_out;

    float* S = nullptr;
    cudaGetSymbolAddress((void**)&S, g_scratch);

    float* wcat  = S + OFF_WCAT;
    float* bias1 = S + OFF_BIAS1;
    float* wot   = S + OFF_WOT;
    float* proj  = S + OFF_PROJ;
    float* ctx   = S + OFF_CTX;
    float* qc    = S + OFF_QC;
    float* kvc   = S + OFF_KVC;
    float* ctx2  = S + OFF_CTX2;
    __nv_bfloat16* bfab = (__nv_bfloat16*)(S + OFF_BF);
    float* Hbuf  = proj;

    float* att_img = out;
    float* att_txt = out + 2097152;
    float* cross   = out + 4194304;
    float* wimg    = out + 6291456;
    float* cons    = out + 14680064;

    const int ATTN_SMEM = 225280;
    cudaFuncSetAttribute(attn_kernel, cudaFuncAttributeMaxDynamicSharedMemorySize, ATTN_SMEM);

    const size_t PSTRIDE = (size_t)8192 * 1280;
    const size_t CSTRIDE = (size_t)8192 * 256;
    const size_t MSTRIDE = (size_t)4194304;

    // 1. pack fused weights
    pack_kernel<<<1541, 256>>>(w1, b1, in_w, in_b, out_w, wcat, bias1, wot);

    // 2. zero both weight matrices
    cudaMemsetAsync(wimg, 0, (size_t)8388608 * 4);

    // 3. fused node projections (both modalities, grid.z=2) + bf16 A|Bm copy
    gemm_tc<<<dim3(64, 10, 2), 256>>>(img, txt, 256, wcat, 1280, 0, bias1, 0,
                                      proj, 1280, PSTRIDE, 0, bfab);

    // 4. per-edge causal weights (bf16 reads, halved traffic)
    edge_kernel<<<65536, 256>>>(bfab, src, dst, w2, b2, wimg);

    // 5. masked self-attention, both modalities (grid.z=32, resident K/V blocks)
    attn_kernel<<<dim3(2, 8, 32), 512, ATTN_SMEM>>>(
        proj, 1280, 512, PSTRIDE,
        proj, 1280, 768, PSTRIDE,
        proj, 1280, 1024, PSTRIDE,
        wimg, MSTRIDE,
        ctx, CSTRIDE);

    // 6. out-proj for both modalities -> attended_*
    gemm_tc<<<dim3(128, 2, 1), 256>>>(ctx, ctx, 256, wot, 256, 0, out_b, 0,
                                      att_img, 256, 0, 0, nullptr);

    // 7. consistency
    gemm_tc<<<dim3(128, 2, 1), 256>>>(att_img, att_img, 256, cw1, 256, 0, cb1, 0,
                                      Hbuf, 256, 0, 1, nullptr);
    cons_reduce<<<2048, 256>>>(Hbuf, cw2, cb2, cons);

    // 8. cross-modal
    gemm_tc<<<dim3(64, 2, 1), 256>>>(att_img, att_img, 256, wcat, 1280, 512, bias1, 512,
                                     qc, 256, 0, 0, nullptr);
    gemm_tc<<<dim3(64, 4, 1), 256>>>(att_txt, att_txt, 256, wcat, 1280, 768, bias1, 768,
                                     kvc, 512, 0, 0, nullptr);
    attn_kernel<<<dim3(2, 8, 16), 512, ATTN_SMEM>>>(
        qc, 256, 0, 0,
        kvc, 512, 0, 0,
        kvc, 512, 256, 0,
        nullptr, 0,
        ctx2, 0);
    gemm_tc<<<dim3(64, 2, 1), 256>>>(ctx2, ctx2, 256, wot, 256, 0, out_b, 0,
                                     cross, 256, 0, 0, nullptr);
}

// round 8
// speedup vs baseline: 1.0699x; 1.0026x over previous
#include <cuda_runtime.h>
#include <cuda_bf16.h>
#include <cstddef>
#include <cstdint>

// Problem constants: B=16, N=512, D=256, H=8, DH=32, E=16384
// d_out layout (floats):
//   attended_img   [0,        2097152)
//   attended_text  [2097152,  4194304)
//   cross_modal    [4194304,  6291456)
//   img_weights    [6291456, 10485760)
//   text_weights   [10485760,14680064)
//   img_cons       [14680064,14688256)
//   text_cons      [14688256,14696448)

#define OFF_WCAT   0u             // 256*1280
#define OFF_BIAS1  327680u        // 1280
#define OFF_WOT    328960u        // 256*256
#define OFF_PROJ   394496u        // 16384*1280  (reused as H for consistency)
#define OFF_CTX    21366016u      // 16384*256
#define OFF_QC     25560320u      // 8192*256
#define OFF_KVC    27657472u      // 8192*512
#define OFF_CTX2   31851776u      // 8192*256
#define OFF_BF     33948928u      // bf16 A|Bm buffer: 16384*512 bf16 = 4194304 floats
#define SCRATCH_FLOATS 38143232u

__device__ float g_scratch[SCRATCH_FLOATS];

// ---------------------------------------------------------------------------
__device__ __forceinline__ uint32_t f2tf32(float f) {
    uint32_t r;
    asm("cvt.rna.tf32.f32 %0, %1;" : "=r"(r) : "f"(f));
    return r;
}

__device__ __forceinline__ void mma_tf32(float& d0, float& d1, float& d2, float& d3,
                                         uint32_t a0, uint32_t a1, uint32_t a2, uint32_t a3,
                                         uint32_t b0, uint32_t b1)
{
    asm volatile(
        "mma.sync.aligned.m16n8k8.row.col.f32.tf32.tf32.f32 "
        "{%0,%1,%2,%3}, {%4,%5,%6,%7}, {%8,%9}, {%0,%1,%2,%3};"
        : "+f"(d0), "+f"(d1), "+f"(d2), "+f"(d3)
        : "r"(a0), "r"(a1), "r"(a2), "r"(a3), "r"(b0), "r"(b1));
}

// ---------------------------------------------------------------------------
// Pack: wcat[k][c] (256 x 1280), bias1[1280], wot = out_w^T (256x256)
// ---------------------------------------------------------------------------
__global__ void pack_kernel(const float* __restrict__ w1, const float* __restrict__ b1,
                            const float* __restrict__ in_w, const float* __restrict__ in_b,
                            const float* __restrict__ out_w,
                            float* __restrict__ wcat, float* __restrict__ bias1,
                            float* __restrict__ wot)
{
    int idx = blockIdx.x * 256 + threadIdx.x;
    if (idx < 327680) {
        int k = idx / 1280, c = idx % 1280;
        float v;
        if (c < 256)       v = w1[k * 256 + c];
        else if (c < 512)  v = w1[(256 + k) * 256 + (c - 256)];
        else if (c < 768)  v = in_w[(c - 512) * 256 + k];
        else if (c < 1024) v = in_w[(c - 768 + 256) * 256 + k];
        else               v = in_w[(c - 1024 + 512) * 256 + k];
        wcat[idx] = v;
    } else if (idx < 328960) {
        int c = idx - 327680;
        float v = (c < 256) ? b1[c] : (c < 512 ? 0.0f : in_b[c - 512]);
        bias1[c] = v;
    } else if (idx < 394496) {
        int i = idx - 328960;
        int k = i / 256, n = i % 256;
        wot[i] = out_w[n * 256 + k];
    }
}

// ---------------------------------------------------------------------------
// Tensor-core tf32 GEMM with register-prefetch double buffering.
// Optional bfaux: epilogue also stores cols < 512 as bf16 (A|Bm edge copy).
// ---------------------------------------------------------------------------
__global__ void gemm_tc(const float* __restrict__ X0, const float* __restrict__ X1,
                        int ldx,
                        const float* __restrict__ W, int ldw, int woff,
                        const float* __restrict__ bias, int boff,
                        float* __restrict__ C, int ldc, size_t czstride, int relu,
                        __nv_bfloat16* __restrict__ bfaux)
{
    __shared__ uint32_t As[128][36];
    __shared__ uint32_t Bs[32][136];

    int z = blockIdx.z;
    const float* X = z ? X1 : X0;
    float* Cz = C + (size_t)z * czstride;

    int t = threadIdx.x;
    int lane = t & 31, w = t >> 5;
    int gid = lane >> 2, tig = lane & 3;
    int wm = w >> 2, wn = w & 3;
    int m0 = blockIdx.x * 128, n0 = blockIdx.y * 128;

    int ar[4], ac[4], br4[4], bc4[4];
    #pragma unroll
    for (int i = 0; i < 4; i++) {
        int lin = i * 1024 + t * 4;
        ar[i] = lin >> 5;  ac[i]  = lin & 31;
        br4[i] = lin >> 7; bc4[i] = lin & 127;
    }

    float acc[4][4][4];
    #pragma unroll
    for (int mi = 0; mi < 4; mi++)
        #pragma unroll
        for (int ni = 0; ni < 4; ni++)
            #pragma unroll
            for (int q = 0; q < 4; q++) acc[mi][ni][q] = 0.0f;

    float4 xa[4], wb[4];
    #pragma unroll
    for (int i = 0; i < 4; i++) {
        xa[i] = *(const float4*)(X + (size_t)(m0 + ar[i]) * ldx + ac[i]);
        wb[i] = *(const float4*)(W + (size_t)br4[i] * ldw + woff + n0 + bc4[i]);
    }

    for (int ch = 0; ch < 8; ch++) {
        #pragma unroll
        for (int i = 0; i < 4; i++) {
            As[ar[i]][ac[i] + 0] = f2tf32(xa[i].x);
            As[ar[i]][ac[i] + 1] = f2tf32(xa[i].y);
            As[ar[i]][ac[i] + 2] = f2tf32(xa[i].z);
            As[ar[i]][ac[i] + 3] = f2tf32(xa[i].w);
            Bs[br4[i]][bc4[i] + 0] = f2tf32(wb[i].x);
            Bs[br4[i]][bc4[i] + 1] = f2tf32(wb[i].y);
            Bs[br4[i]][bc4[i] + 2] = f2tf32(wb[i].z);
            Bs[br4[i]][bc4[i] + 3] = f2tf32(wb[i].w);
        }
        __syncthreads();

        if (ch < 7) {
            int k0 = (ch + 1) * 32;
            #pragma unroll
            for (int i = 0; i < 4; i++) {
                xa[i] = *(const float4*)(X + (size_t)(m0 + ar[i]) * ldx + k0 + ac[i]);
                wb[i] = *(const float4*)(W + (size_t)(k0 + br4[i]) * ldw + woff + n0 + bc4[i]);
            }
        }

        #pragma unroll
        for (int ks = 0; ks < 4; ks++) {
            int kk = ks * 8;
            uint32_t a[4][4], b[4][2];
            #pragma unroll
            for (int mi = 0; mi < 4; mi++) {
                int rb = wm * 64 + mi * 16 + gid;
                a[mi][0] = As[rb][kk + tig];
                a[mi][1] = As[rb + 8][kk + tig];
                a[mi][2] = As[rb][kk + tig + 4];
                a[mi][3] = As[rb + 8][kk + tig + 4];
            }
            #pragma unroll
            for (int ni = 0; ni < 4; ni++) {
                int cb = wn * 32 + ni * 8 + gid;
                b[ni][0] = Bs[kk + tig][cb];
                b[ni][1] = Bs[kk + tig + 4][cb];
            }
            #pragma unroll
            for (int mi = 0; mi < 4; mi++)
                #pragma unroll
                for (int ni = 0; ni < 4; ni++)
                    mma_tf32(acc[mi][ni][0], acc[mi][ni][1], acc[mi][ni][2], acc[mi][ni][3],
                             a[mi][0], a[mi][1], a[mi][2], a[mi][3],
                             b[ni][0], b[ni][1]);
        }
        __syncthreads();
    }

    #pragma unroll
    for (int mi = 0; mi < 4; mi++) {
        int r0 = m0 + wm * 64 + mi * 16 + gid;
        #pragma unroll
        for (int ni = 0; ni < 4; ni++) {
            int col = n0 + wn * 32 + ni * 8 + 2 * tig;
            float bb0 = bias ? bias[boff + col]     : 0.0f;
            float bb1 = bias ? bias[boff + col + 1] : 0.0f;
            float2 v0, v1;
            v0.x = acc[mi][ni][0] + bb0; v0.y = acc[mi][ni][1] + bb1;
            v1.x = acc[mi][ni][2] + bb0; v1.y = acc[mi][ni][3] + bb1;
            if (relu) {
                v0.x = fmaxf(v0.x, 0.0f); v0.y = fmaxf(v0.y, 0.0f);
                v1.x = fmaxf(v1.x, 0.0f); v1.y = fmaxf(v1.y, 0.0f);
            }
            *(float2*)(Cz + (size_t)r0 * ldc + col)       = v0;
            *(float2*)(Cz + (size_t)(r0 + 8) * ldc + col) = v1;
            if (bfaux && col < 512) {
                __nv_bfloat162 h0 = __float22bfloat162_rn(v0);
                __nv_bfloat162 h1 = __float22bfloat162_rn(v1);
                *(__nv_bfloat162*)(bfaux + ((size_t)z * 8192 + r0) * 512 + col)       = h0;
                *(__nv_bfloat162*)(bfaux + ((size_t)z * 8192 + r0 + 8) * 512 + col)   = h1;
            }
        }
    }
}

// ---------------------------------------------------------------------------
// Edge scatter (bf16 activations): one warp per (modality, batch, edge).
// ---------------------------------------------------------------------------
__global__ void edge_kernel(const __nv_bfloat16* __restrict__ ab,
                            const int* __restrict__ src, const int* __restrict__ dst,
                            const float* __restrict__ w2, const float* __restrict__ b2p,
                            float* __restrict__ wout)
{
    int gw   = (blockIdx.x * blockDim.x + threadIdx.x) >> 5;
    int lane = threadIdx.x & 31;
    int e = gw & 16383;
    int b = (gw >> 14) & 15;
    int m = gw >> 18;
    int s = src[e], d = dst[e];

    const uint4* arow = (const uint4*)(ab + ((size_t)m * 8192 + b * 512 + s) * 512);
    const uint4* brow = (const uint4*)(ab + ((size_t)m * 8192 + b * 512 + d) * 512 + 256);
    uint4 av = arow[lane];
    uint4 bv = brow[lane];
    float4 wlo = *(const float4*)(w2 + lane * 8);
    float4 whi = *(const float4*)(w2 + lane * 8 + 4);

    float2 a0 = __bfloat1622float2(*reinterpret_cast<const __nv_bfloat162*>(&av.x));
    float2 a1 = __bfloat1622float2(*reinterpret_cast<const __nv_bfloat162*>(&av.y));
    float2 a2 = __bfloat1622float2(*reinterpret_cast<const __nv_bfloat162*>(&av.z));
    float2 a3 = __bfloat1622float2(*reinterpret_cast<const __nv_bfloat162*>(&av.w));
    float2 b0 = __bfloat1622float2(*reinterpret_cast<const __nv_bfloat162*>(&bv.x));
    float2 b1 = __bfloat1622float2(*reinterpret_cast<const __nv_bfloat162*>(&bv.y));
    float2 b2v = __bfloat1622float2(*reinterpret_cast<const __nv_bfloat162*>(&bv.z));
    float2 b3 = __bfloat1622float2(*reinterpret_cast<const __nv_bfloat162*>(&bv.w));

    float p = 0.0f;
    p += fmaxf(a0.x + b0.x, 0.0f) * wlo.x;
    p += fmaxf(a0.y + b0.y, 0.0f) * wlo.y;
    p += fmaxf(a1.x + b1.x, 0.0f) * wlo.z;
    p += fmaxf(a1.y + b1.y, 0.0f) * wlo.w;
    p += fmaxf(a2.x + b2v.x, 0.0f) * whi.x;
    p += fmaxf(a2.y + b2v.y, 0.0f) * whi.y;
    p += fmaxf(a3.x + b3.x, 0.0f) * whi.z;
    p += fmaxf(a3.y + b3.y, 0.0f) * whi.w;

    #pragma unroll
    for (int off = 16; off > 0; off >>= 1)
        p += __shfl_xor_sync(0xFFFFFFFFu, p, off);
    if (lane == 0) {
        float v = 1.0f / (1.0f + __expf(-(p + b2p[0])));
        wout[(size_t)m * 4194304 + (size_t)b * 262144 + (size_t)s * 512 + d] = v;
    }
}

// ---------------------------------------------------------------------------
// Tensor-core attention, 512 threads / 16 warps (256 query rows), K/V resident.
// Mask loads software-pipelined one kc ahead (consumed in exp, reloaded before
// PV so the PV mma block covers the L2 round trip). Q-frag + first mask loads
// overlap the K/V staging (issued before the barrier).
// ---------------------------------------------------------------------------
__global__ __launch_bounds__(512, 1)
void attn_kernel(const float* __restrict__ qbuf, int qld, int qoff, size_t qzs,
                 const float* __restrict__ kbuf, int kld, int koff, size_t kzs,
                 const float* __restrict__ vbuf, int vld, int voff, size_t vzs,
                 const float* __restrict__ mask, size_t mzs,
                 float* __restrict__ ctx, size_t czs)
{
    extern __shared__ uint32_t sm[];
    uint32_t* Ks = sm;               // [512][36]
    uint32_t* Vs = sm + 18432;       // [512][40]
    uint32_t* Pw = sm + 38912;       // 16 warps x [16][68]

    int zb = blockIdx.z;
    int b = zb & 15, mz = zb >> 4;
    const float* Q = qbuf + (size_t)mz * qzs;
    const float* K = kbuf + (size_t)mz * kzs;
    const float* V = vbuf + (size_t)mz * vzs;
    const float* M = mask ? mask + (size_t)mz * mzs : nullptr;
    float* O = ctx + (size_t)mz * czs;

    int h = blockIdx.y, chunk = blockIdx.x;
    int t = threadIdx.x, lane = t & 31, w = t >> 5;
    int gid = lane >> 2, tig = lane & 3;

    uint32_t* Ps = Pw + w * 1088;
    int i0 = chunk * 256 + w * 16;
    const float scale = 0.17677669529663687f;  // 1/sqrt(32)

    const float* mrow0 = M ? M + (size_t)b * 262144 + (size_t)(i0 + gid) * 512 : nullptr;
    const float* mrow1 = mrow0 ? mrow0 + 8 * 512 : nullptr;

    // Stage K, V (stores only; global loads issue early)
    for (int i = t; i < 4096; i += 512) {
        int row = i >> 3, c4 = (i & 7) * 4;
        size_t rk = (size_t)(b * 512 + row);
        float4 kv = *(const float4*)(K + rk * kld + koff + h * 32 + c4);
        uint4 kt; kt.x = f2tf32(kv.x); kt.y = f2tf32(kv.y); kt.z = f2tf32(kv.z); kt.w = f2tf32(kv.w);
        *(uint4*)&Ks[row * 36 + c4] = kt;
        float4 vv = *(const float4*)(V + rk * vld + voff + h * 32 + c4);
        uint4 vt; vt.x = f2tf32(vv.x); vt.y = f2tf32(vv.y); vt.z = f2tf32(vv.z); vt.w = f2tf32(vv.w);
        *(uint4*)&Vs[row * 40 + c4] = vt;
    }

    // Q fragments (global; overlap staging before barrier)
    uint32_t qa[4][4];
    {
        const float* q0p = Q + (size_t)(b * 512 + i0 + gid) * qld + qoff + h * 32;
        const float* q1p = q0p + (size_t)8 * qld;
        #pragma unroll
        for (int ks = 0; ks < 4; ks++) {
            qa[ks][0] = f2tf32(q0p[ks * 8 + tig] * scale);
            qa[ks][1] = f2tf32(q1p[ks * 8 + tig] * scale);
            qa[ks][2] = f2tf32(q0p[ks * 8 + tig + 4] * scale);
            qa[ks][3] = f2tf32(q1p[ks * 8 + tig + 4] * scale);
        }
    }

    // First mask tile (kc=0), also overlapping staging
    float2 mv0[8], mv1[8];
    if (mrow0) {
        #pragma unroll
        for (int nt = 0; nt < 8; nt++) {
            int col = nt * 8 + 2 * tig;
            mv0[nt] = *(const float2*)(mrow0 + col);
            mv1[nt] = *(const float2*)(mrow1 + col);
        }
    }

    __syncthreads();

    float oacc[4][4];
    #pragma unroll
    for (int vt = 0; vt < 4; vt++)
        #pragma unroll
        for (int q = 0; q < 4; q++) oacc[vt][q] = 0.0f;
    float rsum0 = 0.0f, rsum1 = 0.0f;

    for (int kc = 0; kc < 8; kc++) {
        float sacc[8][4];
        #pragma unroll
        for (int nt = 0; nt < 8; nt++)
            #pragma unroll
            for (int q = 0; q < 4; q++) sacc[nt][q] = 0.0f;

        #pragma unroll
        for (int ks = 0; ks < 4; ks++) {
            #pragma unroll
            for (int nt = 0; nt < 8; nt++) {
                int key = kc * 64 + nt * 8 + gid;
                uint32_t b0 = Ks[key * 36 + ks * 8 + tig];
                uint32_t b1 = Ks[key * 36 + ks * 8 + tig + 4];
                mma_tf32(sacc[nt][0], sacc[nt][1], sacc[nt][2], sacc[nt][3],
                         qa[ks][0], qa[ks][1], qa[ks][2], qa[ks][3], b0, b1);
            }
        }

        // exp (+mask), row sums, stash P (tf32)
        #pragma unroll
        for (int nt = 0; nt < 8; nt++) {
            float s0 = sacc[nt][0], s1 = sacc[nt][1];
            float s2 = sacc[nt][2], s3 = sacc[nt][3];
            if (mrow0) {
                s0 += mv0[nt].x; s1 += mv0[nt].y;
                s2 += mv1[nt].x; s3 += mv1[nt].y;
            }
            float p0 = __expf(s0), p1 = __expf(s1);
            float p2 = __expf(s2), p3 = __expf(s3);
            rsum0 += p0 + p1;
            rsum1 += p2 + p3;
            uint2 u0; u0.x = f2tf32(p0); u0.y = f2tf32(p1);
            uint2 u1; u1.x = f2tf32(p2); u1.y = f2tf32(p3);
            *(uint2*)&Ps[gid * 68 + nt * 8 + 2 * tig]       = u0;
            *(uint2*)&Ps[(gid + 8) * 68 + nt * 8 + 2 * tig] = u1;
        }

        // prefetch NEXT kc's mask now — PV mma block below covers the L2 latency
        if (mrow0 && kc < 7) {
            #pragma unroll
            for (int nt = 0; nt < 8; nt++) {
                int col = (kc + 1) * 64 + nt * 8 + 2 * tig;
                mv0[nt] = *(const float2*)(mrow0 + col);
                mv1[nt] = *(const float2*)(mrow1 + col);
            }
        }
        __syncwarp();

        #pragma unroll
        for (int ks2 = 0; ks2 < 8; ks2++) {
            uint32_t a0 = Ps[gid * 68 + ks2 * 8 + tig];
            uint32_t a1 = Ps[(gid + 8) * 68 + ks2 * 8 + tig];
            uint32_t a2 = Ps[gid * 68 + ks2 * 8 + tig + 4];
            uint32_t a3 = Ps[(gid + 8) * 68 + ks2 * 8 + tig + 4];
            int keyb = kc * 64 + ks2 * 8;
            #pragma unroll
            for (int vt = 0; vt < 4; vt++) {
                uint32_t b0 = Vs[(keyb + tig) * 40 + vt * 8 + gid];
                uint32_t b1 = Vs[(keyb + tig + 4) * 40 + vt * 8 + gid];
                mma_tf32(oacc[vt][0], oacc[vt][1], oacc[vt][2], oacc[vt][3],
                         a0, a1, a2, a3, b0, b1);
            }
        }
        __syncwarp();
    }

    rsum0 += __shfl_xor_sync(0xFFFFFFFFu, rsum0, 1);
    rsum0 += __shfl_xor_sync(0xFFFFFFFFu, rsum0, 2);
    rsum1 += __shfl_xor_sync(0xFFFFFFFFu, rsum1, 1);
    rsum1 += __shfl_xor_sync(0xFFFFFFFFu, rsum1, 2);
    float inv0 = 1.0f / rsum0, inv1 = 1.0f / rsum1;

    size_t r0 = (size_t)(b * 512 + i0 + gid) * 256 + h * 32;
    size_t r1 = r0 + (size_t)8 * 256;
    #pragma unroll
    for (int vt = 0; vt < 4; vt++) {
        float2 v0; v0.x = oacc[vt][0] * inv0; v0.y = oacc[vt][1] * inv0;
        float2 v1; v1.x = oacc[vt][2] * inv1; v1.y = oacc[vt][3] * inv1;
        *(float2*)(O + r0 + vt * 8 + 2 * tig) = v0;
        *(float2*)(O + r1 + vt * 8 + 2 * tig) = v1;
    }
}

// ---------------------------------------------------------------------------
__global__ void cons_reduce(const float* __restrict__ H, const float* __restrict__ cw2,
                            const float* __restrict__ cb2, float* __restrict__ out)
{
    int gw   = (blockIdx.x * blockDim.x + threadIdx.x) >> 5;
    int lane = threadIdx.x & 31;
    const float4* h4 = (const float4*)(H + (size_t)gw * 256);
    const float4* w4 = (const float4*)cw2;
    float p = 0.0f;
    #pragma unroll
    for (int u = 0; u < 2; u++) {
        int idx = u * 32 + lane;
        float4 a = h4[idx], w = w4[idx];
        p += a.x * w.x + a.y * w.y + a.z * w.z + a.w * w.w;
    }
    #pragma unroll
    for (int off = 16; off > 0; off >>= 1)
        p += __shfl_xor_sync(0xFFFFFFFFu, p, off);
    if (lane == 0)
        out[gw] = 1.0f / (1.0f + __expf(-(p + cb2[0])));
}

// ---------------------------------------------------------------------------
extern "C" void kernel_launch(void* const* d_in, const int* in_sizes, int n_in,
                              void* d_out, int out_size)
{
    const float* img   = (const float*)d_in[0];
    const float* txt   = (const float*)d_in[1];
    const int*   src   = (const int*)  d_in[2];
    const int*   dst   = (const int*)  d_in[3];
    const float* w1    = (const float*)d_in[4];
    const float* b1    = (const float*)d_in[5];
    const float* w2    = (const float*)d_in[6];
    const float* b2    = (const float*)d_in[7];
    const float* in_w  = (const float*)d_in[8];
    const float* in_b  = (const float*)d_in[9];
    const float* out_w = (const float*)d_in[10];
    const float* out_b = (const float*)d_in[11];
    const float* cw1   = (const float*)d_in[12];
    const float* cb1   = (const float*)d_in[13];
    const float* cw2   = (const float*)d_in[14];
    const float* cb2   = (const float*)d_in[15];
    float* out = (float*)d_out;

    float* S = nullptr;
    cudaGetSymbolAddress((void**)&S, g_scratch);

    float* wcat  = S + OFF_WCAT;
    float* bias1 = S + OFF_BIAS1;
    float* wot   = S + OFF_WOT;
    float* proj  = S + OFF_PROJ;
    float* ctx   = S + OFF_CTX;
    float* qc    = S + OFF_QC;
    float* kvc   = S + OFF_KVC;
    float* ctx2  = S + OFF_CTX2;
    __nv_bfloat16* bfab = (__nv_bfloat16*)(S + OFF_BF);
    float* Hbuf  = proj;

    float* att_img = out;
    float* att_txt = out + 2097152;
    float* cross   = out + 4194304;
    float* wimg    = out + 6291456;
    float* cons    = out + 14680064;

    const int ATTN_SMEM = 225280;
    cudaFuncSetAttribute(attn_kernel, cudaFuncAttributeMaxDynamicSharedMemorySize, ATTN_SMEM);

    const size_t PSTRIDE = (size_t)8192 * 1280;
    const size_t CSTRIDE = (size_t)8192 * 256;
    const size_t MSTRIDE = (size_t)4194304;

    // 1. pack fused weights
    pack_kernel<<<1541, 256>>>(w1, b1, in_w, in_b, out_w, wcat, bias1, wot);

    // 2. zero both weight matrices
    cudaMemsetAsync(wimg, 0, (size_t)8388608 * 4);

    // 3. fused node projections (both modalities, grid.z=2) + bf16 A|Bm copy
    gemm_tc<<<dim3(64, 10, 2), 256>>>(img, txt, 256, wcat, 1280, 0, bias1, 0,
                                      proj, 1280, PSTRIDE, 0, bfab);

    // 4. per-edge causal weights (bf16 reads)
    edge_kernel<<<65536, 256>>>(bfab, src, dst, w2, b2, wimg);

    // 5. masked self-attention, both modalities (grid.z=32)
    attn_kernel<<<dim3(2, 8, 32), 512, ATTN_SMEM>>>(
        proj, 1280, 512, PSTRIDE,
        proj, 1280, 768, PSTRIDE,
        proj, 1280, 1024, PSTRIDE,
        wimg, MSTRIDE,
        ctx, CSTRIDE);

    // 6. out-proj for both modalities -> attended_*
    gemm_tc<<<dim3(128, 2, 1), 256>>>(ctx, ctx, 256, wot, 256, 0, out_b, 0,
                                      att_img, 256, 0, 0, nullptr);

    // 7. consistency
    gemm_tc<<<dim3(128, 2, 1), 256>>>(att_img, att_img, 256, cw1, 256, 0, cb1, 0,
                                      Hbuf, 256, 0, 1, nullptr);
    cons_reduce<<<2048, 256>>>(Hbuf, cw2, cb2, cons);

    // 8. cross-modal
    gemm_tc<<<dim3(64, 2, 1), 256>>>(att_img, att_img, 256, wcat, 1280, 512, bias1, 512,
                                     qc, 256, 0, 0, nullptr);
    gemm_tc<<<dim3(64, 4, 1), 256>>>(att_txt, att_txt, 256, wcat, 1280, 768, bias1, 768,
                                     kvc, 512, 0, 0, nullptr);
    attn_kernel<<<dim3(2, 8, 16), 512, ATTN_SMEM>>>(
        qc, 256, 0, 0,
        kvc, 512, 0, 0,
        kvc, 512, 256, 0,
        nullptr, 0,
        ctx2, 0);
    gemm_tc<<<dim3(64, 2, 1), 256>>>(ctx2, ctx2, 256, wot, 256, 0, out_b, 0,
                                     cross, 256, 0, 0, nullptr);
}

// round 10
// speedup vs baseline: 1.0711x; 1.0011x over previous
#include <cuda_runtime.h>
#include <cuda_bf16.h>
#include <cstddef>
#include <cstdint>

// Problem constants: B=16, N=512, D=256, H=8, DH=32, E=16384
// d_out layout (floats):
//   attended_img   [0,        2097152)
//   attended_text  [2097152,  4194304)
//   cross_modal    [4194304,  6291456)
//   img_weights    [6291456, 10485760)
//   text_weights   [10485760,14680064)
//   img_cons       [14680064,14688256)
//   text_cons      [14688256,14696448)

#define OFF_WCAT   0u             // 256*1280
#define OFF_BIAS1  327680u        // 1280
#define OFF_WOT    328960u        // 256*256
#define OFF_PROJ   394496u        // 16384*1280  (reused as H for consistency)
#define OFF_CTX    21366016u      // 16384*256
#define OFF_QC     25560320u      // 8192*256
#define OFF_KVC    27657472u      // 8192*512
#define OFF_CTX2   31851776u      // 8192*256
#define OFF_BF     33948928u      // bf16 A|Bm buffer: 16384*512 bf16 = 4194304 floats
#define SCRATCH_FLOATS 38143232u

__device__ float g_scratch[SCRATCH_FLOATS];

// ---------------------------------------------------------------------------
__device__ __forceinline__ uint32_t f2tf32(float f) {
    uint32_t r;
    asm("cvt.rna.tf32.f32 %0, %1;" : "=r"(r) : "f"(f));
    return r;
}

__device__ __forceinline__ void mma_tf32(float& d0, float& d1, float& d2, float& d3,
                                         uint32_t a0, uint32_t a1, uint32_t a2, uint32_t a3,
                                         uint32_t b0, uint32_t b1)
{
    asm volatile(
        "mma.sync.aligned.m16n8k8.row.col.f32.tf32.tf32.f32 "
        "{%0,%1,%2,%3}, {%4,%5,%6,%7}, {%8,%9}, {%0,%1,%2,%3};"
        : "+f"(d0), "+f"(d1), "+f"(d2), "+f"(d3)
        : "r"(a0), "r"(a1), "r"(a2), "r"(a3), "r"(b0), "r"(b1));
}

__device__ __forceinline__ void cp16(uint32_t smem, const void* g) {
    asm volatile("cp.async.ca.shared.global [%0], [%1], 16;" :: "r"(smem), "l"(g));
}

// ---------------------------------------------------------------------------
// Pack: wcat[k][c] (256 x 1280), bias1[1280], wot = out_w^T (256x256)
// ---------------------------------------------------------------------------
__global__ void pack_kernel(const float* __restrict__ w1, const float* __restrict__ b1,
                            const float* __restrict__ in_w, const float* __restrict__ in_b,
                            const float* __restrict__ out_w,
                            float* __restrict__ wcat, float* __restrict__ bias1,
                            float* __restrict__ wot)
{
    int idx = blockIdx.x * 256 + threadIdx.x;
    if (idx < 327680) {
        int k = idx / 1280, c = idx % 1280;
        float v;
        if (c < 256)       v = w1[k * 256 + c];
        else if (c < 512)  v = w1[(256 + k) * 256 + (c - 256)];
        else if (c < 768)  v = in_w[(c - 512) * 256 + k];
        else if (c < 1024) v = in_w[(c - 768 + 256) * 256 + k];
        else               v = in_w[(c - 1024 + 512) * 256 + k];
        wcat[idx] = v;
    } else if (idx < 328960) {
        int c = idx - 327680;
        float v = (c < 256) ? b1[c] : (c < 512 ? 0.0f : in_b[c - 512]);
        bias1[c] = v;
    } else if (idx < 394496) {
        int i = idx - 328960;
        int k = i / 256, n = i % 256;
        wot[i] = out_w[n * 256 + k];
    }
}

// ---------------------------------------------------------------------------
// Tensor-core tf32 GEMM, cp.async double-buffered staging (no staging regs),
// __launch_bounds__(256,2) -> 2 blocks/SM. tf32 cvt at fragment-load time.
// Dynamic smem: 2*(128*36 + 32*136) floats = 71680 B.
// ---------------------------------------------------------------------------
__global__ __launch_bounds__(256, 2)
void gemm_tc(const float* __restrict__ X0, const float* __restrict__ X1,
             int ldx,
             const float* __restrict__ W, int ldw, int woff,
             const float* __restrict__ bias, int boff,
             float* __restrict__ C, int ldc, size_t czstride, int relu,
             __nv_bfloat16* __restrict__ bfaux)
{
    extern __shared__ float gsm[];
    float* Abuf[2] = { gsm, gsm + 4608 };                       // 128*36 each
    float* Bbuf[2] = { gsm + 9216, gsm + 9216 + 4352 };         // 32*136 each

    int z = blockIdx.z;
    const float* X = z ? X1 : X0;
    float* Cz = C + (size_t)z * czstride;

    int t = threadIdx.x;
    int lane = t & 31, w = t >> 5;
    int gid = lane >> 2, tig = lane & 3;
    int wm = w >> 2, wn = w & 3;
    int m0 = blockIdx.x * 128, n0 = blockIdx.y * 128;

    int ar[4], ac[4], br4[4], bc4[4];
    #pragma unroll
    for (int i = 0; i < 4; i++) {
        int lin = i * 1024 + t * 4;
        ar[i] = lin >> 5;  ac[i]  = lin & 31;
        br4[i] = lin >> 7; bc4[i] = lin & 127;
    }

    float acc[4][4][4];
    #pragma unroll
    for (int mi = 0; mi < 4; mi++)
        #pragma unroll
        for (int ni = 0; ni < 4; ni++)
            #pragma unroll
            for (int q = 0; q < 4; q++) acc[mi][ni][q] = 0.0f;

    // stage chunk 0 into buffer 0
    #pragma unroll
    for (int i = 0; i < 4; i++) {
        cp16((uint32_t)__cvta_generic_to_shared(Abuf[0] + ar[i] * 36 + ac[i]),
             X + (size_t)(m0 + ar[i]) * ldx + ac[i]);
        cp16((uint32_t)__cvta_generic_to_shared(Bbuf[0] + br4[i] * 136 + bc4[i]),
             W + (size_t)br4[i] * ldw + woff + n0 + bc4[i]);
    }
    asm volatile("cp.async.commit_group;");

    for (int ch = 0; ch < 8; ch++) {
        if (ch < 7) {
            int k0 = (ch + 1) * 32;
            int buf = (ch + 1) & 1;
            #pragma unroll
            for (int i = 0; i < 4; i++) {
                cp16((uint32_t)__cvta_generic_to_shared(Abuf[buf] + ar[i] * 36 + ac[i]),
                     X + (size_t)(m0 + ar[i]) * ldx + k0 + ac[i]);
                cp16((uint32_t)__cvta_generic_to_shared(Bbuf[buf] + br4[i] * 136 + bc4[i]),
                     W + (size_t)(k0 + br4[i]) * ldw + woff + n0 + bc4[i]);
            }
            asm volatile("cp.async.commit_group;");
            asm volatile("cp.async.wait_group 1;");
        } else {
            asm volatile("cp.async.wait_group 0;");
        }
        __syncthreads();

        const float* A = Abuf[ch & 1];
        const float* B = Bbuf[ch & 1];

        #pragma unroll
        for (int ks = 0; ks < 4; ks++) {
            int kk = ks * 8;
            uint32_t a[4][4], b[4][2];
            #pragma unroll
            for (int mi = 0; mi < 4; mi++) {
                int rb = wm * 64 + mi * 16 + gid;
                a[mi][0] = f2tf32(A[rb * 36 + kk + tig]);
                a[mi][1] = f2tf32(A[(rb + 8) * 36 + kk + tig]);
                a[mi][2] = f2tf32(A[rb * 36 + kk + tig + 4]);
                a[mi][3] = f2tf32(A[(rb + 8) * 36 + kk + tig + 4]);
            }
            #pragma unroll
            for (int ni = 0; ni < 4; ni++) {
                int cb = wn * 32 + ni * 8 + gid;
                b[ni][0] = f2tf32(B[(kk + tig) * 136 + cb]);
                b[ni][1] = f2tf32(B[(kk + tig + 4) * 136 + cb]);
            }
            #pragma unroll
            for (int mi = 0; mi < 4; mi++)
                #pragma unroll
                for (int ni = 0; ni < 4; ni++)
                    mma_tf32(acc[mi][ni][0], acc[mi][ni][1], acc[mi][ni][2], acc[mi][ni][3],
                             a[mi][0], a[mi][1], a[mi][2], a[mi][3],
                             b[ni][0], b[ni][1]);
        }
        __syncthreads();
    }

    #pragma unroll
    for (int mi = 0; mi < 4; mi++) {
        int r0 = m0 + wm * 64 + mi * 16 + gid;
        #pragma unroll
        for (int ni = 0; ni < 4; ni++) {
            int col = n0 + wn * 32 + ni * 8 + 2 * tig;
            float bb0 = bias ? bias[boff + col]     : 0.0f;
            float bb1 = bias ? bias[boff + col + 1] : 0.0f;
            float2 v0, v1;
            v0.x = acc[mi][ni][0] + bb0; v0.y = acc[mi][ni][1] + bb1;
            v1.x = acc[mi][ni][2] + bb0; v1.y = acc[mi][ni][3] + bb1;
            if (relu) {
                v0.x = fmaxf(v0.x, 0.0f); v0.y = fmaxf(v0.y, 0.0f);
                v1.x = fmaxf(v1.x, 0.0f); v1.y = fmaxf(v1.y, 0.0f);
            }
            *(float2*)(Cz + (size_t)r0 * ldc + col)       = v0;
            *(float2*)(Cz + (size_t)(r0 + 8) * ldc + col) = v1;
            if (bfaux && col < 512) {
                __nv_bfloat162 h0 = __float22bfloat162_rn(v0);
                __nv_bfloat162 h1 = __float22bfloat162_rn(v1);
                *(__nv_bfloat162*)(bfaux + ((size_t)z * 8192 + r0) * 512 + col)       = h0;
                *(__nv_bfloat162*)(bfaux + ((size_t)z * 8192 + r0 + 8) * 512 + col)   = h1;
            }
        }
    }
}

// ---------------------------------------------------------------------------
// Edge scatter (bf16 activations): one warp per (modality, batch, edge).
// ---------------------------------------------------------------------------
__global__ void edge_kernel(const __nv_bfloat16* __restrict__ ab,
                            const int* __restrict__ src, const int* __restrict__ dst,
                            const float* __restrict__ w2, const float* __restrict__ b2p,
                            float* __restrict__ wout)
{
    int gw   = (blockIdx.x * blockDim.x + threadIdx.x) >> 5;
    int lane = threadIdx.x & 31;
    int e = gw & 16383;
    int b = (gw >> 14) & 15;
    int m = gw >> 18;
    int s = src[e], d = dst[e];

    const uint4* arow = (const uint4*)(ab + ((size_t)m * 8192 + b * 512 + s) * 512);
    const uint4* brow = (const uint4*)(ab + ((size_t)m * 8192 + b * 512 + d) * 512 + 256);
    uint4 av = arow[lane];
    uint4 bv = brow[lane];
    float4 wlo = *(const float4*)(w2 + lane * 8);
    float4 whi = *(const float4*)(w2 + lane * 8 + 4);

    float2 a0 = __bfloat1622float2(*reinterpret_cast<const __nv_bfloat162*>(&av.x));
    float2 a1 = __bfloat1622float2(*reinterpret_cast<const __nv_bfloat162*>(&av.y));
    float2 a2 = __bfloat1622float2(*reinterpret_cast<const __nv_bfloat162*>(&av.z));
    float2 a3 = __bfloat1622float2(*reinterpret_cast<const __nv_bfloat162*>(&av.w));
    float2 b0 = __bfloat1622float2(*reinterpret_cast<const __nv_bfloat162*>(&bv.x));
    float2 b1 = __bfloat1622float2(*reinterpret_cast<const __nv_bfloat162*>(&bv.y));
    float2 b2v = __bfloat1622float2(*reinterpret_cast<const __nv_bfloat162*>(&bv.z));
    float2 b3 = __bfloat1622float2(*reinterpret_cast<const __nv_bfloat162*>(&bv.w));

    float p = 0.0f;
    p += fmaxf(a0.x + b0.x, 0.0f) * wlo.x;
    p += fmaxf(a0.y + b0.y, 0.0f) * wlo.y;
    p += fmaxf(a1.x + b1.x, 0.0f) * wlo.z;
    p += fmaxf(a1.y + b1.y, 0.0f) * wlo.w;
    p += fmaxf(a2.x + b2v.x, 0.0f) * whi.x;
    p += fmaxf(a2.y + b2v.y, 0.0f) * whi.y;
    p += fmaxf(a3.x + b3.x, 0.0f) * whi.z;
    p += fmaxf(a3.y + b3.y, 0.0f) * whi.w;

    #pragma unroll
    for (int off = 16; off > 0; off >>= 1)
        p += __shfl_xor_sync(0xFFFFFFFFu, p, off);
    if (lane == 0) {
        float v = 1.0f / (1.0f + __expf(-(p + b2p[0])));
        wout[(size_t)m * 4194304 + (size_t)b * 262144 + (size_t)s * 512 + d] = v;
    }
}

// ---------------------------------------------------------------------------
// Tensor-core attention, 512 threads / 16 warps (256 query rows), K/V resident.
// K k-pair permuted (stride 40) -> single LDS.64 per S-phase B-fragment.
// P buffer [16][36]/warp, PV in two 32-key halves. Mask prefetch for kc+1
// happens AFTER the second half's exp (all current-kc consumers done),
// covered by the second PV mma block. Smem 200704 B.
// ---------------------------------------------------------------------------
__global__ __launch_bounds__(512, 1)
void attn_kernel(const float* __restrict__ qbuf, int qld, int qoff, size_t qzs,
                 const float* __restrict__ kbuf, int kld, int koff, size_t kzs,
                 const float* __restrict__ vbuf, int vld, int voff, size_t vzs,
                 const float* __restrict__ mask, size_t mzs,
                 float* __restrict__ ctx, size_t czs)
{
    extern __shared__ uint32_t sm[];
    uint32_t* Ks = sm;               // [512][40], k-pair permuted columns
    uint32_t* Vs = sm + 20480;       // [512][40], row-major
    uint32_t* Pw = sm + 40960;       // 16 warps x [16][36]

    int zb = blockIdx.z;
    int b = zb & 15, mz = zb >> 4;
    const float* Q = qbuf + (size_t)mz * qzs;
    const float* K = kbuf + (size_t)mz * kzs;
    const float* V = vbuf + (size_t)mz * vzs;
    const float* M = mask ? mask + (size_t)mz * mzs : nullptr;
    float* O = ctx + (size_t)mz * czs;

    int h = blockIdx.y, chunk = blockIdx.x;
    int t = threadIdx.x, lane = t & 31, w = t >> 5;
    int gid = lane >> 2, tig = lane & 3;

    uint32_t* Ps = Pw + w * 576;
    int i0 = chunk * 256 + w * 16;
    const float scale = 0.17677669529663687f;  // 1/sqrt(32)

    const float* mrow0 = M ? M + (size_t)b * 262144 + (size_t)(i0 + gid) * 512 : nullptr;
    const float* mrow1 = mrow0 ? mrow0 + 8 * 512 : nullptr;

    // Stage K (k-pair permuted: pair (k,k+4) adjacent within each 8-group) and V.
    for (int i = t; i < 4096; i += 512) {
        int row = i >> 3, j = i & 7, c4 = j * 4;
        size_t rk = (size_t)(b * 512 + row);
        float4 kv = *(const float4*)(K + rk * kld + koff + h * 32 + c4);
        int kb = row * 40 + ((j >> 1) << 3) + (j & 1);
        Ks[kb + 0] = f2tf32(kv.x);
        Ks[kb + 2] = f2tf32(kv.y);
        Ks[kb + 4] = f2tf32(kv.z);
        Ks[kb + 6] = f2tf32(kv.w);
        float4 vv = *(const float4*)(V + rk * vld + voff + h * 32 + c4);
        uint4 vt4; vt4.x = f2tf32(vv.x); vt4.y = f2tf32(vv.y);
        vt4.z = f2tf32(vv.z); vt4.w = f2tf32(vv.w);
        *(uint4*)&Vs[row * 40 + c4] = vt4;
    }

    // Q fragments (global; overlap staging before barrier)
    uint32_t qa[4][4];
    {
        const float* q0p = Q + (size_t)(b * 512 + i0 + gid) * qld + qoff + h * 32;
        const float* q1p = q0p + (size_t)8 * qld;
        #pragma unroll
        for (int ks = 0; ks < 4; ks++) {
            qa[ks][0] = f2tf32(q0p[ks * 8 + tig] * scale);
            qa[ks][1] = f2tf32(q1p[ks * 8 + tig] * scale);
            qa[ks][2] = f2tf32(q0p[ks * 8 + tig + 4] * scale);
            qa[ks][3] = f2tf32(q1p[ks * 8 + tig + 4] * scale);
        }
    }

    // First mask tile (kc=0), overlapping staging
    float2 mv0[8], mv1[8];
    if (mrow0) {
        #pragma unroll
        for (int nt = 0; nt < 8; nt++) {
            int col = nt * 8 + 2 * tig;
            mv0[nt] = *(const float2*)(mrow0 + col);
            mv1[nt] = *(const float2*)(mrow1 + col);
        }
    }

    __syncthreads();

    float oacc[4][4];
    #pragma unroll
    for (int vt = 0; vt < 4; vt++)
        #pragma unroll
        for (int q = 0; q < 4; q++) oacc[vt][q] = 0.0f;
    float rsum0 = 0.0f, rsum1 = 0.0f;

    for (int kc = 0; kc < 8; kc++) {
        float sacc[8][4];
        #pragma unroll
        for (int nt = 0; nt < 8; nt++)
            #pragma unroll
            for (int q = 0; q < 4; q++) sacc[nt][q] = 0.0f;

        // S = Q K^T : paired 64-bit K-fragment loads
        #pragma unroll
        for (int ks = 0; ks < 4; ks++) {
            #pragma unroll
            for (int nt = 0; nt < 8; nt++) {
                int key = kc * 64 + nt * 8 + gid;
                uint2 kb2 = *(const uint2*)&Ks[key * 40 + ks * 8 + 2 * tig];
                mma_tf32(sacc[nt][0], sacc[nt][1], sacc[nt][2], sacc[nt][3],
                         qa[ks][0], qa[ks][1], qa[ks][2], qa[ks][3], kb2.x, kb2.y);
            }
        }

        // two 32-key halves: exp + P store + PV
        #pragma unroll
        for (int hh = 0; hh < 2; hh++) {
            #pragma unroll
            for (int nt2 = 0; nt2 < 4; nt2++) {
                int nt = hh * 4 + nt2;
                float s0 = sacc[nt][0], s1 = sacc[nt][1];
                float s2 = sacc[nt][2], s3 = sacc[nt][3];
                if (mrow0) {
                    s0 += mv0[nt].x; s1 += mv0[nt].y;
                    s2 += mv1[nt].x; s3 += mv1[nt].y;
                }
                float p0 = __expf(s0), p1 = __expf(s1);
                float p2 = __expf(s2), p3 = __expf(s3);
                rsum0 += p0 + p1;
                rsum1 += p2 + p3;
                uint2 u0; u0.x = f2tf32(p0); u0.y = f2tf32(p1);
                uint2 u1; u1.x = f2tf32(p2); u1.y = f2tf32(p3);
                *(uint2*)&Ps[gid * 36 + nt2 * 8 + 2 * tig]       = u0;
                *(uint2*)&Ps[(gid + 8) * 36 + nt2 * 8 + 2 * tig] = u1;
            }
            // prefetch next kc's mask ONLY after the second half's exp has
            // consumed all current-kc mask registers; PV below covers latency
            if (hh == 1 && mrow0 && kc < 7) {
                #pragma unroll
                for (int nt = 0; nt < 8; nt++) {
                    int col = (kc + 1) * 64 + nt * 8 + 2 * tig;
                    mv0[nt] = *(const float2*)(mrow0 + col);
                    mv1[nt] = *(const float2*)(mrow1 + col);
                }
            }
            __syncwarp();

            #pragma unroll
            for (int ks2 = 0; ks2 < 4; ks2++) {
                uint32_t a0 = Ps[gid * 36 + ks2 * 8 + tig];
                uint32_t a1 = Ps[(gid + 8) * 36 + ks2 * 8 + tig];
                uint32_t a2 = Ps[gid * 36 + ks2 * 8 + tig + 4];
                uint32_t a3 = Ps[(gid + 8) * 36 + ks2 * 8 + tig + 4];
                int keyb = kc * 64 + (hh * 4 + ks2) * 8;
                #pragma unroll
                for (int vt = 0; vt < 4; vt++) {
                    uint32_t b0 = Vs[(keyb + tig) * 40 + vt * 8 + gid];
                    uint32_t b1 = Vs[(keyb + tig + 4) * 40 + vt * 8 + gid];
                    mma_tf32(oacc[vt][0], oacc[vt][1], oacc[vt][2], oacc[vt][3],
                             a0, a1, a2, a3, b0, b1);
                }
            }
            __syncwarp();
        }
    }

    rsum0 += __shfl_xor_sync(0xFFFFFFFFu, rsum0, 1);
    rsum0 += __shfl_xor_sync(0xFFFFFFFFu, rsum0, 2);
    rsum1 += __shfl_xor_sync(0xFFFFFFFFu, rsum1, 1);
    rsum1 += __shfl_xor_sync(0xFFFFFFFFu, rsum1, 2);
    float inv0 = 1.0f / rsum0, inv1 = 1.0f / rsum1;

    size_t r0 = (size_t)(b * 512 + i0 + gid) * 256 + h * 32;
    size_t r1 = r0 + (size_t)8 * 256;
    #pragma unroll
    for (int vt = 0; vt < 4; vt++) {
        float2 v0; v0.x = oacc[vt][0] * inv0; v0.y = oacc[vt][1] * inv0;
        float2 v1; v1.x = oacc[vt][2] * inv1; v1.y = oacc[vt][3] * inv1;
        *(float2*)(O + r0 + vt * 8 + 2 * tig) = v0;
        *(float2*)(O + r1 + vt * 8 + 2 * tig) = v1;
    }
}

// ---------------------------------------------------------------------------
__global__ void cons_reduce(const float* __restrict__ H, const float* __restrict__ cw2,
                            const float* __restrict__ cb2, float* __restrict__ out)
{
    int gw   = (blockIdx.x * blockDim.x + threadIdx.x) >> 5;
    int lane = threadIdx.x & 31;
    const float4* h4 = (const float4*)(H + (size_t)gw * 256);
    const float4* w4 = (const float4*)cw2;
    float p = 0.0f;
    #pragma unroll
    for (int u = 0; u < 2; u++) {
        int idx = u * 32 + lane;
        float4 a = h4[idx], w = w4[idx];
        p += a.x * w.x + a.y * w.y + a.z * w.z + a.w * w.w;
    }
    #pragma unroll
    for (int off = 16; off > 0; off >>= 1)
        p += __shfl_xor_sync(0xFFFFFFFFu, p, off);
    if (lane == 0)
        out[gw] = 1.0f / (1.0f + __expf(-(p + cb2[0])));
}

// ---------------------------------------------------------------------------
extern "C" void kernel_launch(void* const* d_in, const int* in_sizes, int n_in,
                              void* d_out, int out_size)
{
    const float* img   = (const float*)d_in[0];
    const float* txt   = (const float*)d_in[1];
    const int*   src   = (const int*)  d_in[2];
    const int*   dst   = (const int*)  d_in[3];
    const float* w1    = (const float*)d_in[4];
    const float* b1    = (const float*)d_in[5];
    const float* w2    = (const float*)d_in[6];
    const float* b2    = (const float*)d_in[7];
    const float* in_w  = (const float*)d_in[8];
    const float* in_b  = (const float*)d_in[9];
    const float* out_w = (const float*)d_in[10];
    const float* out_b = (const float*)d_in[11];
    const float* cw1   = (const float*)d_in[12];
    const float* cb1   = (const float*)d_in[13];
    const float* cw2   = (const float*)d_in[14];
    const float* cb2   = (const float*)d_in[15];
    float* out = (float*)d_out;

    float* S = nullptr;
    cudaGetSymbolAddress((void**)&S, g_scratch);

    float* wcat  = S + OFF_WCAT;
    float* bias1 = S + OFF_BIAS1;
    float* wot   = S + OFF_WOT;
    float* proj  = S + OFF_PROJ;
    float* ctx   = S + OFF_CTX;
    float* qc    = S + OFF_QC;
    float* kvc   = S + OFF_KVC;
    float* ctx2  = S + OFF_CTX2;
    __nv_bfloat16* bfab = (__nv_bfloat16*)(S + OFF_BF);
    float* Hbuf  = proj;

    float* att_img = out;
    float* att_txt = out + 2097152;
    float* cross   = out + 4194304;
    float* wimg    = out + 6291456;
    float* cons    = out + 14680064;

    const int ATTN_SMEM = 200704;
    const int GEMM_SMEM = 71680;
    cudaFuncSetAttribute(attn_kernel, cudaFuncAttributeMaxDynamicSharedMemorySize, ATTN_SMEM);
    cudaFuncSetAttribute(gemm_tc,     cudaFuncAttributeMaxDynamicSharedMemorySize, GEMM_SMEM);

    const size_t PSTRIDE = (size_t)8192 * 1280;
    const size_t CSTRIDE = (size_t)8192 * 256;
    const size_t MSTRIDE = (size_t)4194304;

    // 1. pack fused weights
    pack_kernel<<<1541, 256>>>(w1, b1, in_w, in_b, out_w, wcat, bias1, wot);

    // 2. zero both weight matrices
    cudaMemsetAsync(wimg, 0, (size_t)8388608 * 4);

    // 3. fused node projections (both modalities, grid.z=2) + bf16 A|Bm copy
    gemm_tc<<<dim3(64, 10, 2), 256, GEMM_SMEM>>>(img, txt, 256, wcat, 1280, 0, bias1, 0,
                                                 proj, 1280, PSTRIDE, 0, bfab);

    // 4. per-edge causal weights (bf16 reads)
    edge_kernel<<<65536, 256>>>(bfab, src, dst, w2, b2, wimg);

    // 5. masked self-attention, both modalities (grid.z=32)
    attn_kernel<<<dim3(2, 8, 32), 512, ATTN_SMEM>>>(
        proj, 1280, 512, PSTRIDE,
        proj, 1280, 768, PSTRIDE,
        proj, 1280, 1024, PSTRIDE,
        wimg, MSTRIDE,
        ctx, CSTRIDE);

    // 6. out-proj for both modalities -> attended_*
    gemm_tc<<<dim3(128, 2, 1), 256, GEMM_SMEM>>>(ctx, ctx, 256, wot, 256, 0, out_b, 0,
                                                 att_img, 256, 0, 0, nullptr);

    // 7. consistency
    gemm_tc<<<dim3(128, 2, 1), 256, GEMM_SMEM>>>(att_img, att_img, 256, cw1, 256, 0, cb1, 0,
                                                 Hbuf, 256, 0, 1, nullptr);
    cons_reduce<<<2048, 256>>>(Hbuf, cw2, cb2, cons);

    // 8. cross-modal
    gemm_tc<<<dim3(64, 2, 1), 256, GEMM_SMEM>>>(att_img, att_img, 256, wcat, 1280, 512, bias1, 512,
                                                qc, 256, 0, 0, nullptr);
    gemm_tc<<<dim3(64, 4, 1), 256, GEMM_SMEM>>>(att_txt, att_txt, 256, wcat, 1280, 768, bias1, 768,
                                                kvc, 512, 0, 0, nullptr);
    attn_kernel<<<dim3(2, 8, 16), 512, ATTN_SMEM>>>(
        qc, 256, 0, 0,
        kvc, 512, 0, 0,
        kvc, 512, 256, 0,
        nullptr, 0,
        ctx2, 0);
    gemm_tc<<<dim3(64, 2, 1), 256, GEMM_SMEM>>>(ctx2, ctx2, 256, wot, 256, 0, out_b, 0,
                                                cross, 256, 0, 0, nullptr);
}

// round 11
// speedup vs baseline: 1.0812x; 1.0095x over previous
#include <cuda_runtime.h>
#include <cuda_bf16.h>
#include <cstddef>
#include <cstdint>

// Problem constants: B=16, N=512, D=256, H=8, DH=32, E=16384
// d_out layout (floats):
//   attended_img   [0,        2097152)
//   attended_text  [2097152,  4194304)
//   cross_modal    [4194304,  6291456)
//   img_weights    [6291456, 10485760)
//   text_weights   [10485760,14680064)
//   img_cons       [14680064,14688256)
//   text_cons      [14688256,14696448)

#define OFF_WCAT   0u             // 256*1280   (tf32-rounded)
#define OFF_BIAS1  327680u        // 1280       (fp32)
#define OFF_WOT    328960u        // 256*256    (tf32-rounded)
#define OFF_PROJ   394496u        // 16384*1280 (reused as H for consistency)
#define OFF_CTX    21366016u      // 16384*256  (tf32-rounded by attn)
#define OFF_QC     25560320u      // 8192*256
#define OFF_KVC    27657472u      // 8192*512
#define OFF_CTX2   31851776u      // 8192*256   (tf32-rounded by attn)
#define OFF_BF     33948928u      // bf16 A|Bm buffer: 16384*512 bf16 = 4194304 floats
#define OFF_INT    38143232u      // tf32-rounded img|txt: 8388608 floats
#define OFF_ATTF   46531840u      // tf32-rounded att_img|att_txt: 4194304 floats
#define OFF_CW1T   50726144u      // tf32-rounded cw1: 65536 floats
#define SCRATCH_FLOATS 50791680u

__device__ float g_scratch[SCRATCH_FLOATS];

// ---------------------------------------------------------------------------
__device__ __forceinline__ uint32_t f2tf32(float f) {
    uint32_t r;
    asm("cvt.rna.tf32.f32 %0, %1;" : "=r"(r) : "f"(f));
    return r;
}

__device__ __forceinline__ void mma_tf32(float& d0, float& d1, float& d2, float& d3,
                                         uint32_t a0, uint32_t a1, uint32_t a2, uint32_t a3,
                                         uint32_t b0, uint32_t b1)
{
    asm volatile(
        "mma.sync.aligned.m16n8k8.row.col.f32.tf32.tf32.f32 "
        "{%0,%1,%2,%3}, {%4,%5,%6,%7}, {%8,%9}, {%0,%1,%2,%3};"
        : "+f"(d0), "+f"(d1), "+f"(d2), "+f"(d3)
        : "r"(a0), "r"(a1), "r"(a2), "r"(a3), "r"(b0), "r"(b1));
}

__device__ __forceinline__ void cp16(uint32_t smem, const void* g) {
    asm volatile("cp.async.ca.shared.global [%0], [%1], 16;" :: "r"(smem), "l"(g));
}

// ---------------------------------------------------------------------------
// Pack: wcat (tf32-rounded), bias1 (fp32), wot (tf32-rounded), cw1t (rounded)
// ---------------------------------------------------------------------------
__global__ void pack_kernel(const float* __restrict__ w1, const float* __restrict__ b1,
                            const float* __restrict__ in_w, const float* __restrict__ in_b,
                            const float* __restrict__ out_w, const float* __restrict__ cw1,
                            float* __restrict__ wcat, float* __restrict__ bias1,
                            float* __restrict__ wot, float* __restrict__ cw1t)
{
    int idx = blockIdx.x * 256 + threadIdx.x;
    if (idx < 327680) {
        int k = idx / 1280, c = idx % 1280;
        float v;
        if (c < 256)       v = w1[k * 256 + c];
        else if (c < 512)  v = w1[(256 + k) * 256 + (c - 256)];
        else if (c < 768)  v = in_w[(c - 512) * 256 + k];
        else if (c < 1024) v = in_w[(c - 768 + 256) * 256 + k];
        else               v = in_w[(c - 1024 + 512) * 256 + k];
        ((uint32_t*)wcat)[idx] = f2tf32(v);
    } else if (idx < 328960) {
        int c = idx - 327680;
        float v = (c < 256) ? b1[c] : (c < 512 ? 0.0f : in_b[c - 512]);
        bias1[c] = v;
    } else if (idx < 394496) {
        int i = idx - 328960;
        int k = i / 256, n = i % 256;
        ((uint32_t*)wot)[i] = f2tf32(out_w[n * 256 + k]);
    } else if (idx < 460032) {
        int i = idx - 394496;
        ((uint32_t*)cw1t)[i] = f2tf32(cw1[i]);
    }
}

// ---------------------------------------------------------------------------
// Round img|txt inputs to tf32 (consumers rounded them anyway -> bit-exact).
// ---------------------------------------------------------------------------
__global__ void cvt_in(const float* __restrict__ a, const float* __restrict__ b,
                       float* __restrict__ o)
{
    int i = blockIdx.x * 256 + threadIdx.x;   // float4 index, 2097152 total
    float4 v = (i < 1048576) ? ((const float4*)a)[i] : ((const float4*)b)[i - 1048576];
    uint4 u; u.x = f2tf32(v.x); u.y = f2tf32(v.y); u.z = f2tf32(v.z); u.w = f2tf32(v.w);
    ((uint4*)o)[i] = u;
}

// ---------------------------------------------------------------------------
// Tensor-core tf32 GEMM. ALL operands pre-rounded to tf32 -> fragment loads
// are bare LDS (no cvt in inner loop). cp.async double-buffered staging,
// __launch_bounds__(256,2). Dynamic smem 71680 B.
// Optional bfaux: bf16 copy of cols<512 (edge A|Bm). Optional tfaux: tf32-
// rounded copy of output (for att -> cons/qc/kvc chaining).
// ---------------------------------------------------------------------------
__global__ __launch_bounds__(256, 2)
void gemm_tc(const float* __restrict__ X0, const float* __restrict__ X1,
             int ldx,
             const float* __restrict__ W, int ldw, int woff,
             const float* __restrict__ bias, int boff,
             float* __restrict__ C, int ldc, size_t czstride, int relu,
             __nv_bfloat16* __restrict__ bfaux, float* __restrict__ tfaux)
{
    extern __shared__ float gsm[];
    float* Abuf[2] = { gsm, gsm + 4608 };                       // 128*36 each
    float* Bbuf[2] = { gsm + 9216, gsm + 9216 + 4352 };         // 32*136 each

    int z = blockIdx.z;
    const float* X = z ? X1 : X0;
    float* Cz = C + (size_t)z * czstride;

    int t = threadIdx.x;
    int lane = t & 31, w = t >> 5;
    int gid = lane >> 2, tig = lane & 3;
    int wm = w >> 2, wn = w & 3;
    int m0 = blockIdx.x * 128, n0 = blockIdx.y * 128;

    int ar[4], ac[4], br4[4], bc4[4];
    #pragma unroll
    for (int i = 0; i < 4; i++) {
        int lin = i * 1024 + t * 4;
        ar[i] = lin >> 5;  ac[i]  = lin & 31;
        br4[i] = lin >> 7; bc4[i] = lin & 127;
    }

    float acc[4][4][4];
    #pragma unroll
    for (int mi = 0; mi < 4; mi++)
        #pragma unroll
        for (int ni = 0; ni < 4; ni++)
            #pragma unroll
            for (int q = 0; q < 4; q++) acc[mi][ni][q] = 0.0f;

    #pragma unroll
    for (int i = 0; i < 4; i++) {
        cp16((uint32_t)__cvta_generic_to_shared(Abuf[0] + ar[i] * 36 + ac[i]),
             X + (size_t)(m0 + ar[i]) * ldx + ac[i]);
        cp16((uint32_t)__cvta_generic_to_shared(Bbuf[0] + br4[i] * 136 + bc4[i]),
             W + (size_t)br4[i] * ldw + woff + n0 + bc4[i]);
    }
    asm volatile("cp.async.commit_group;");

    for (int ch = 0; ch < 8; ch++) {
        if (ch < 7) {
            int k0 = (ch + 1) * 32;
            int buf = (ch + 1) & 1;
            #pragma unroll
            for (int i = 0; i < 4; i++) {
                cp16((uint32_t)__cvta_generic_to_shared(Abuf[buf] + ar[i] * 36 + ac[i]),
                     X + (size_t)(m0 + ar[i]) * ldx + k0 + ac[i]);
                cp16((uint32_t)__cvta_generic_to_shared(Bbuf[buf] + br4[i] * 136 + bc4[i]),
                     W + (size_t)(k0 + br4[i]) * ldw + woff + n0 + bc4[i]);
            }
            asm volatile("cp.async.commit_group;");
            asm volatile("cp.async.wait_group 1;");
        } else {
            asm volatile("cp.async.wait_group 0;");
        }
        __syncthreads();

        const uint32_t* A = (const uint32_t*)Abuf[ch & 1];
        const uint32_t* B = (const uint32_t*)Bbuf[ch & 1];

        #pragma unroll
        for (int ks = 0; ks < 4; ks++) {
            int kk = ks * 8;
            uint32_t a[4][4], b[4][2];
            #pragma unroll
            for (int mi = 0; mi < 4; mi++) {
                int rb = wm * 64 + mi * 16 + gid;
                a[mi][0] = A[rb * 36 + kk + tig];
                a[mi][1] = A[(rb + 8) * 36 + kk + tig];
                a[mi][2] = A[rb * 36 + kk + tig + 4];
                a[mi][3] = A[(rb + 8) * 36 + kk + tig + 4];
            }
            #pragma unroll
            for (int ni = 0; ni < 4; ni++) {
                int cb = wn * 32 + ni * 8 + gid;
                b[ni][0] = B[(kk + tig) * 136 + cb];
                b[ni][1] = B[(kk + tig + 4) * 136 + cb];
            }
            #pragma unroll
            for (int mi = 0; mi < 4; mi++)
                #pragma unroll
                for (int ni = 0; ni < 4; ni++)
                    mma_tf32(acc[mi][ni][0], acc[mi][ni][1], acc[mi][ni][2], acc[mi][ni][3],
                             a[mi][0], a[mi][1], a[mi][2], a[mi][3],
                             b[ni][0], b[ni][1]);
        }
        __syncthreads();
    }

    #pragma unroll
    for (int mi = 0; mi < 4; mi++) {
        int r0 = m0 + wm * 64 + mi * 16 + gid;
        #pragma unroll
        for (int ni = 0; ni < 4; ni++) {
            int col = n0 + wn * 32 + ni * 8 + 2 * tig;
            float bb0 = bias ? bias[boff + col]     : 0.0f;
            float bb1 = bias ? bias[boff + col + 1] : 0.0f;
            float2 v0, v1;
            v0.x = acc[mi][ni][0] + bb0; v0.y = acc[mi][ni][1] + bb1;
            v1.x = acc[mi][ni][2] + bb0; v1.y = acc[mi][ni][3] + bb1;
            if (relu) {
                v0.x = fmaxf(v0.x, 0.0f); v0.y = fmaxf(v0.y, 0.0f);
                v1.x = fmaxf(v1.x, 0.0f); v1.y = fmaxf(v1.y, 0.0f);
            }
            *(float2*)(Cz + (size_t)r0 * ldc + col)       = v0;
            *(float2*)(Cz + (size_t)(r0 + 8) * ldc + col) = v1;
            if (bfaux && col < 512) {
                __nv_bfloat162 h0 = __float22bfloat162_rn(v0);
                __nv_bfloat162 h1 = __float22bfloat162_rn(v1);
                *(__nv_bfloat162*)(bfaux + ((size_t)z * 8192 + r0) * 512 + col)       = h0;
                *(__nv_bfloat162*)(bfaux + ((size_t)z * 8192 + r0 + 8) * 512 + col)   = h1;
            }
            if (tfaux) {
                uint2 t0; t0.x = f2tf32(v0.x); t0.y = f2tf32(v0.y);
                uint2 t1; t1.x = f2tf32(v1.x); t1.y = f2tf32(v1.y);
                *(uint2*)(tfaux + (size_t)r0 * ldc + col)       = t0;
                *(uint2*)(tfaux + (size_t)(r0 + 8) * ldc + col) = t1;
            }
        }
    }
}

// ---------------------------------------------------------------------------
// Edge scatter (bf16 activations): one warp per (modality, batch, edge).
// ---------------------------------------------------------------------------
__global__ void edge_kernel(const __nv_bfloat16* __restrict__ ab,
                            const int* __restrict__ src, const int* __restrict__ dst,
                            const float* __restrict__ w2, const float* __restrict__ b2p,
                            float* __restrict__ wout)
{
    int gw   = (blockIdx.x * blockDim.x + threadIdx.x) >> 5;
    int lane = threadIdx.x & 31;
    int e = gw & 16383;
    int b = (gw >> 14) & 15;
    int m = gw >> 18;
    int s = src[e], d = dst[e];

    const uint4* arow = (const uint4*)(ab + ((size_t)m * 8192 + b * 512 + s) * 512);
    const uint4* brow = (const uint4*)(ab + ((size_t)m * 8192 + b * 512 + d) * 512 + 256);
    uint4 av = arow[lane];
    uint4 bv = brow[lane];
    float4 wlo = *(const float4*)(w2 + lane * 8);
    float4 whi = *(const float4*)(w2 + lane * 8 + 4);

    float2 a0 = __bfloat1622float2(*reinterpret_cast<const __nv_bfloat162*>(&av.x));
    float2 a1 = __bfloat1622float2(*reinterpret_cast<const __nv_bfloat162*>(&av.y));
    float2 a2 = __bfloat1622float2(*reinterpret_cast<const __nv_bfloat162*>(&av.z));
    float2 a3 = __bfloat1622float2(*reinterpret_cast<const __nv_bfloat162*>(&av.w));
    float2 b0 = __bfloat1622float2(*reinterpret_cast<const __nv_bfloat162*>(&bv.x));
    float2 b1 = __bfloat1622float2(*reinterpret_cast<const __nv_bfloat162*>(&bv.y));
    float2 b2v = __bfloat1622float2(*reinterpret_cast<const __nv_bfloat162*>(&bv.z));
    float2 b3 = __bfloat1622float2(*reinterpret_cast<const __nv_bfloat162*>(&bv.w));

    float p = 0.0f;
    p += fmaxf(a0.x + b0.x, 0.0f) * wlo.x;
    p += fmaxf(a0.y + b0.y, 0.0f) * wlo.y;
    p += fmaxf(a1.x + b1.x, 0.0f) * wlo.z;
    p += fmaxf(a1.y + b1.y, 0.0f) * wlo.w;
    p += fmaxf(a2.x + b2v.x, 0.0f) * whi.x;
    p += fmaxf(a2.y + b2v.y, 0.0f) * whi.y;
    p += fmaxf(a3.x + b3.x, 0.0f) * whi.z;
    p += fmaxf(a3.y + b3.y, 0.0f) * whi.w;

    #pragma unroll
    for (int off = 16; off > 0; off >>= 1)
        p += __shfl_xor_sync(0xFFFFFFFFu, p, off);
    if (lane == 0) {
        float v = 1.0f / (1.0f + __expf(-(p + b2p[0])));
        wout[(size_t)m * 4194304 + (size_t)b * 262144 + (size_t)s * 512 + d] = v;
    }
}

// ---------------------------------------------------------------------------
// Tensor-core attention, 512 threads / 16 warps (256 query rows), K/V resident.
// K k-pair permuted (stride 40), LDS.64 S-phase fragments, two-half PV.
// ctx stored tf32-rounded (consumers round anyway -> bit-exact). Smem 200704 B.
// ---------------------------------------------------------------------------
__global__ __launch_bounds__(512, 1)
void attn_kernel(const float* __restrict__ qbuf, int qld, int qoff, size_t qzs,
                 const float* __restrict__ kbuf, int kld, int koff, size_t kzs,
                 const float* __restrict__ vbuf, int vld, int voff, size_t vzs,
                 const float* __restrict__ mask, size_t mzs,
                 float* __restrict__ ctx, size_t czs)
{
    extern __shared__ uint32_t sm[];
    uint32_t* Ks = sm;               // [512][40], k-pair permuted columns
    uint32_t* Vs = sm + 20480;       // [512][40], row-major
    uint32_t* Pw = sm + 40960;       // 16 warps x [16][36]

    int zb = blockIdx.z;
    int b = zb & 15, mz = zb >> 4;
    const float* Q = qbuf + (size_t)mz * qzs;
    const float* K = kbuf + (size_t)mz * kzs;
    const float* V = vbuf + (size_t)mz * vzs;
    const float* M = mask ? mask + (size_t)mz * mzs : nullptr;
    float* O = ctx + (size_t)mz * czs;

    int h = blockIdx.y, chunk = blockIdx.x;
    int t = threadIdx.x, lane = t & 31, w = t >> 5;
    int gid = lane >> 2, tig = lane & 3;

    uint32_t* Ps = Pw + w * 576;
    int i0 = chunk * 256 + w * 16;
    const float scale = 0.17677669529663687f;  // 1/sqrt(32)

    const float* mrow0 = M ? M + (size_t)b * 262144 + (size_t)(i0 + gid) * 512 : nullptr;
    const float* mrow1 = mrow0 ? mrow0 + 8 * 512 : nullptr;

    for (int i = t; i < 4096; i += 512) {
        int row = i >> 3, j = i & 7, c4 = j * 4;
        size_t rk = (size_t)(b * 512 + row);
        float4 kv = *(const float4*)(K + rk * kld + koff + h * 32 + c4);
        int kb = row * 40 + ((j >> 1) << 3) + (j & 1);
        Ks[kb + 0] = f2tf32(kv.x);
        Ks[kb + 2] = f2tf32(kv.y);
        Ks[kb + 4] = f2tf32(kv.z);
        Ks[kb + 6] = f2tf32(kv.w);
        float4 vv = *(const float4*)(V + rk * vld + voff + h * 32 + c4);
        uint4 vt4; vt4.x = f2tf32(vv.x); vt4.y = f2tf32(vv.y);
        vt4.z = f2tf32(vv.z); vt4.w = f2tf32(vv.w);
        *(uint4*)&Vs[row * 40 + c4] = vt4;
    }

    uint32_t qa[4][4];
    {
        const float* q0p = Q + (size_t)(b * 512 + i0 + gid) * qld + qoff + h * 32;
        const float* q1p = q0p + (size_t)8 * qld;
        #pragma unroll
        for (int ks = 0; ks < 4; ks++) {
            qa[ks][0] = f2tf32(q0p[ks * 8 + tig] * scale);
            qa[ks][1] = f2tf32(q1p[ks * 8 + tig] * scale);
            qa[ks][2] = f2tf32(q0p[ks * 8 + tig + 4] * scale);
            qa[ks][3] = f2tf32(q1p[ks * 8 + tig + 4] * scale);
        }
    }

    float2 mv0[8], mv1[8];
    if (mrow0) {
        #pragma unroll
        for (int nt = 0; nt < 8; nt++) {
            int col = nt * 8 + 2 * tig;
            mv0[nt] = *(const float2*)(mrow0 + col);
            mv1[nt] = *(const float2*)(mrow1 + col);
        }
    }

    __syncthreads();

    float oacc[4][4];
    #pragma unroll
    for (int vt = 0; vt < 4; vt++)
        #pragma unroll
        for (int q = 0; q < 4; q++) oacc[vt][q] = 0.0f;
    float rsum0 = 0.0f, rsum1 = 0.0f;

    for (int kc = 0; kc < 8; kc++) {
        float sacc[8][4];
        #pragma unroll
        for (int nt = 0; nt < 8; nt++)
            #pragma unroll
            for (int q = 0; q < 4; q++) sacc[nt][q] = 0.0f;

        #pragma unroll
        for (int ks = 0; ks < 4; ks++) {
            #pragma unroll
            for (int nt = 0; nt < 8; nt++) {
                int key = kc * 64 + nt * 8 + gid;
                uint2 kb2 = *(const uint2*)&Ks[key * 40 + ks * 8 + 2 * tig];
                mma_tf32(sacc[nt][0], sacc[nt][1], sacc[nt][2], sacc[nt][3],
                         qa[ks][0], qa[ks][1], qa[ks][2], qa[ks][3], kb2.x, kb2.y);
            }
        }

        #pragma unroll
        for (int hh = 0; hh < 2; hh++) {
            #pragma unroll
            for (int nt2 = 0; nt2 < 4; nt2++) {
                int nt = hh * 4 + nt2;
                float s0 = sacc[nt][0], s1 = sacc[nt][1];
                float s2 = sacc[nt][2], s3 = sacc[nt][3];
                if (mrow0) {
                    s0 += mv0[nt].x; s1 += mv0[nt].y;
                    s2 += mv1[nt].x; s3 += mv1[nt].y;
                }
                float p0 = __expf(s0), p1 = __expf(s1);
                float p2 = __expf(s2), p3 = __expf(s3);
                rsum0 += p0 + p1;
                rsum1 += p2 + p3;
                uint2 u0; u0.x = f2tf32(p0); u0.y = f2tf32(p1);
                uint2 u1; u1.x = f2tf32(p2); u1.y = f2tf32(p3);
                *(uint2*)&Ps[gid * 36 + nt2 * 8 + 2 * tig]       = u0;
                *(uint2*)&Ps[(gid + 8) * 36 + nt2 * 8 + 2 * tig] = u1;
            }
            if (hh == 1 && mrow0 && kc < 7) {
                #pragma unroll
                for (int nt = 0; nt < 8; nt++) {
                    int col = (kc + 1) * 64 + nt * 8 + 2 * tig;
                    mv0[nt] = *(const float2*)(mrow0 + col);
                    mv1[nt] = *(const float2*)(mrow1 + col);
                }
            }
            __syncwarp();

            #pragma unroll
            for (int ks2 = 0; ks2 < 4; ks2++) {
                uint32_t a0 = Ps[gid * 36 + ks2 * 8 + tig];
                uint32_t a1 = Ps[(gid + 8) * 36 + ks2 * 8 + tig];
                uint32_t a2 = Ps[gid * 36 + ks2 * 8 + tig + 4];
                uint32_t a3 = Ps[(gid + 8) * 36 + ks2 * 8 + tig + 4];
                int keyb = kc * 64 + (hh * 4 + ks2) * 8;
                #pragma unroll
                for (int vt = 0; vt < 4; vt++) {
                    uint32_t b0 = Vs[(keyb + tig) * 40 + vt * 8 + gid];
                    uint32_t b1 = Vs[(keyb + tig + 4) * 40 + vt * 8 + gid];
                    mma_tf32(oacc[vt][0], oacc[vt][1], oacc[vt][2], oacc[vt][3],
                             a0, a1, a2, a3, b0, b1);
                }
            }
            __syncwarp();
        }
    }

    rsum0 += __shfl_xor_sync(0xFFFFFFFFu, rsum0, 1);
    rsum0 += __shfl_xor_sync(0xFFFFFFFFu, rsum0, 2);
    rsum1 += __shfl_xor_sync(0xFFFFFFFFu, rsum1, 1);
    rsum1 += __shfl_xor_sync(0xFFFFFFFFu, rsum1, 2);
    float inv0 = 1.0f / rsum0, inv1 = 1.0f / rsum1;

    size_t r0 = (size_t)(b * 512 + i0 + gid) * 256 + h * 32;
    size_t r1 = r0 + (size_t)8 * 256;
    #pragma unroll
    for (int vt = 0; vt < 4; vt++) {
        uint2 v0; v0.x = f2tf32(oacc[vt][0] * inv0); v0.y = f2tf32(oacc[vt][1] * inv0);
        uint2 v1; v1.x = f2tf32(oacc[vt][2] * inv1); v1.y = f2tf32(oacc[vt][3] * inv1);
        *(uint2*)(O + r0 + vt * 8 + 2 * tig) = v0;
        *(uint2*)(O + r1 + vt * 8 + 2 * tig) = v1;
    }
}

// ---------------------------------------------------------------------------
__global__ void cons_reduce(const float* __restrict__ H, const float* __restrict__ cw2,
                            const float* __restrict__ cb2, float* __restrict__ out)
{
    int gw   = (blockIdx.x * blockDim.x + threadIdx.x) >> 5;
    int lane = threadIdx.x & 31;
    const float4* h4 = (const float4*)(H + (size_t)gw * 256);
    const float4* w4 = (const float4*)cw2;
    float p = 0.0f;
    #pragma unroll
    for (int u = 0; u < 2; u++) {
        int idx = u * 32 + lane;
        float4 a = h4[idx], w = w4[idx];
        p += a.x * w.x + a.y * w.y + a.z * w.z + a.w * w.w;
    }
    #pragma unroll
    for (int off = 16; off > 0; off >>= 1)
        p += __shfl_xor_sync(0xFFFFFFFFu, p, off);
    if (lane == 0)
        out[gw] = 1.0f / (1.0f + __expf(-(p + cb2[0])));
}

// ---------------------------------------------------------------------------
extern "C" void kernel_launch(void* const* d_in, const int* in_sizes, int n_in,
                              void* d_out, int out_size)
{
    const float* img   = (const float*)d_in[0];
    const float* txt   = (const float*)d_in[1];
    const int*   src   = (const int*)  d_in[2];
    const int*   dst   = (const int*)  d_in[3];
    const float* w1    = (const float*)d_in[4];
    const float* b1    = (const float*)d_in[5];
    const float* w2    = (const float*)d_in[6];
    const float* b2    = (const float*)d_in[7];
    const float* in_w  = (const float*)d_in[8];
    const float* in_b  = (const float*)d_in[9];
    const float* out_w = (const float*)d_in[10];
    const float* out_b = (const float*)d_in[11];
    const float* cw1   = (const float*)d_in[12];
    const float* cb1   = (const float*)d_in[13];
    const float* cw2   = (const float*)d_in[14];
    const float* cb2   = (const float*)d_in[15];
    float* out = (float*)d_out;

    float* S = nullptr;
    cudaGetSymbolAddress((void**)&S, g_scratch);

    float* wcat  = S + OFF_WCAT;
    float* bias1 = S + OFF_BIAS1;
    float* wot   = S + OFF_WOT;
    float* proj  = S + OFF_PROJ;
    float* ctx   = S + OFF_CTX;
    float* qc    = S + OFF_QC;
    float* kvc   = S + OFF_KVC;
    float* ctx2  = S + OFF_CTX2;
    __nv_bfloat16* bfab = (__nv_bfloat16*)(S + OFF_BF);
    float* intf  = S + OFF_INT;
    float* attf  = S + OFF_ATTF;
    float* cw1t  = S + OFF_CW1T;
    float* Hbuf  = proj;

    float* att_img = out;
    float* att_txt = out + 2097152;
    float* cross   = out + 4194304;
    float* wimg    = out + 6291456;
    float* cons    = out + 14680064;

    const int ATTN_SMEM = 200704;
    const int GEMM_SMEM = 71680;
    cudaFuncSetAttribute(attn_kernel, cudaFuncAttributeMaxDynamicSharedMemorySize, ATTN_SMEM);
    cudaFuncSetAttribute(gemm_tc,     cudaFuncAttributeMaxDynamicSharedMemorySize, GEMM_SMEM);

    const size_t PSTRIDE = (size_t)8192 * 1280;
    const size_t CSTRIDE = (size_t)8192 * 256;
    const size_t MSTRIDE = (size_t)4194304;

    // 1. pack fused weights (tf32-rounded) + rounded inputs
    pack_kernel<<<1797, 256>>>(w1, b1, in_w, in_b, out_w, cw1, wcat, bias1, wot, cw1t);
    cvt_in<<<8192, 256>>>(img, txt, intf);

    // 2. zero both weight matrices
    cudaMemsetAsync(wimg, 0, (size_t)8388608 * 4);

    // 3. fused node projections (both modalities, grid.z=2) + bf16 A|Bm copy
    gemm_tc<<<dim3(64, 10, 2), 256, GEMM_SMEM>>>(intf, intf + 4194304, 256,
                                                 wcat, 1280, 0, bias1, 0,
                                                 proj, 1280, PSTRIDE, 0, bfab, nullptr);

    // 4. per-edge causal weights (bf16 reads)
    edge_kernel<<<65536, 256>>>(bfab, src, dst, w2, b2, wimg);

    // 5. masked self-attention, both modalities (grid.z=32)
    attn_kernel<<<dim3(2, 8, 32), 512, ATTN_SMEM>>>(
        proj, 1280, 512, PSTRIDE,
        proj, 1280, 768, PSTRIDE,
        proj, 1280, 1024, PSTRIDE,
        wimg, MSTRIDE,
        ctx, CSTRIDE);

    // 6. out-proj -> attended_* (fp32) + tf32 side-copy attf
    gemm_tc<<<dim3(128, 2, 1), 256, GEMM_SMEM>>>(ctx, ctx, 256, wot, 256, 0, out_b, 0,
                                                 att_img, 256, 0, 0, nullptr, attf);

    // 7. consistency (X = rounded attf, W = rounded cw1t)
    gemm_tc<<<dim3(128, 2, 1), 256, GEMM_SMEM>>>(attf, attf, 256, cw1t, 256, 0, cb1, 0,
                                                 Hbuf, 256, 0, 1, nullptr, nullptr);
    cons_reduce<<<2048, 256>>>(Hbuf, cw2, cb2, cons);

    // 8. cross-modal (X from rounded attf halves)
    gemm_tc<<<dim3(64, 2, 1), 256, GEMM_SMEM>>>(attf, attf, 256, wcat, 1280, 512, bias1, 512,
                                                qc, 256, 0, 0, nullptr, nullptr);
    gemm_tc<<<dim3(64, 4, 1), 256, GEMM_SMEM>>>(attf + (size_t)8192 * 256, attf, 256,
                                                wcat, 1280, 768, bias1, 768,
                                                kvc, 512, 0, 0, nullptr, nullptr);
    attn_kernel<<<dim3(2, 8, 16), 512, ATTN_SMEM>>>(
        qc, 256, 0, 0,
        kvc, 512, 0, 0,
        kvc, 512, 256, 0,
        nullptr, 0,
        ctx2, 0);
    gemm_tc<<<dim3(64, 2, 1), 256, GEMM_SMEM>>>(ctx2, ctx2, 256, wot, 256, 0, out_b, 0,
                                                cross, 256, 0, 0, nullptr, nullptr);
}

// round 12
// speedup vs baseline: 1.1397x; 1.0540x over previous
#include <cuda_runtime.h>
#include <cuda_bf16.h>
#include <cstddef>
#include <cstdint>

// Problem constants: B=16, N=512, D=256, H=8, DH=32, E=16384
// d_out layout (floats):
//   attended_img   [0,        2097152)
//   attended_text  [2097152,  4194304)
//   cross_modal    [4194304,  6291456)
//   img_weights    [6291456, 10485760)
//   text_weights   [10485760,14680064)
//   img_cons       [14680064,14688256)
//   text_cons      [14688256,14696448)

#define OFF_WCAT   0u             // 256*1280   (tf32-rounded)
#define OFF_BIAS1  327680u        // 1280       (fp32)
#define OFF_WOT    328960u        // 256*256    (tf32-rounded)
#define OFF_PROJ   394496u        // 16384*1280 (reused as H for consistency)
#define OFF_CTX    21366016u      // 16384*256  (tf32-rounded by attn)
#define OFF_QC     25560320u      // 8192*256
#define OFF_KVC    27657472u      // 8192*512
#define OFF_CTX2   31851776u      // 8192*256   (tf32-rounded by attn)
#define OFF_BF     33948928u      // bf16 A|Bm buffer: 16384*512 bf16 = 4194304 floats
#define OFF_INT    38143232u      // tf32-rounded img|txt: 8388608 floats
#define OFF_ATTF   46531840u      // tf32-rounded att_img|att_txt: 4194304 floats
#define OFF_CW1T   50726144u      // tf32-rounded cw1: 65536 floats
#define SCRATCH_FLOATS 50791680u

__device__ float g_scratch[SCRATCH_FLOATS];

// ---------------------------------------------------------------------------
__device__ __forceinline__ uint32_t f2tf32(float f) {
    uint32_t r;
    asm("cvt.rna.tf32.f32 %0, %1;" : "=r"(r) : "f"(f));
    return r;
}

__device__ __forceinline__ void mma_tf32(float& d0, float& d1, float& d2, float& d3,
                                         uint32_t a0, uint32_t a1, uint32_t a2, uint32_t a3,
                                         uint32_t b0, uint32_t b1)
{
    asm volatile(
        "mma.sync.aligned.m16n8k8.row.col.f32.tf32.tf32.f32 "
        "{%0,%1,%2,%3}, {%4,%5,%6,%7}, {%8,%9}, {%0,%1,%2,%3};"
        : "+f"(d0), "+f"(d1), "+f"(d2), "+f"(d3)
        : "r"(a0), "r"(a1), "r"(a2), "r"(a3), "r"(b0), "r"(b1));
}

__device__ __forceinline__ void cp16(uint32_t smem, const void* g) {
    asm volatile("cp.async.ca.shared.global [%0], [%1], 16;" :: "r"(smem), "l"(g));
}

// ---------------------------------------------------------------------------
// prep: [blocks 0..8192) tf32-round img|txt -> intf (float4 per thread)
//       [blocks 8192..)  pack wcat/bias1/wot/cw1t (tf32-rounded weights)
// ---------------------------------------------------------------------------
__global__ void prep_kernel(const float* __restrict__ img, const float* __restrict__ txt,
                            float* __restrict__ intf,
                            const float* __restrict__ w1, const float* __restrict__ b1,
                            const float* __restrict__ in_w, const float* __restrict__ in_b,
                            const float* __restrict__ out_w, const float* __restrict__ cw1,
                            float* __restrict__ wcat, float* __restrict__ bias1,
                            float* __restrict__ wot, float* __restrict__ cw1t)
{
    if (blockIdx.x < 8192) {
        int i = blockIdx.x * 256 + threadIdx.x;   // float4 index, 2097152 total
        float4 v = (i < 1048576) ? ((const float4*)img)[i]
                                 : ((const float4*)txt)[i - 1048576];
        uint4 u; u.x = f2tf32(v.x); u.y = f2tf32(v.y); u.z = f2tf32(v.z); u.w = f2tf32(v.w);
        ((uint4*)intf)[i] = u;
        return;
    }
    int idx = (blockIdx.x - 8192) * 256 + threadIdx.x;
    if (idx < 327680) {
        int k = idx / 1280, c = idx % 1280;
        float v;
        if (c < 256)       v = w1[k * 256 + c];
        else if (c < 512)  v = w1[(256 + k) * 256 + (c - 256)];
        else if (c < 768)  v = in_w[(c - 512) * 256 + k];
        else if (c < 1024) v = in_w[(c - 768 + 256) * 256 + k];
        else               v = in_w[(c - 1024 + 512) * 256 + k];
        ((uint32_t*)wcat)[idx] = f2tf32(v);
    } else if (idx < 328960) {
        int c = idx - 327680;
        float v = (c < 256) ? b1[c] : (c < 512 ? 0.0f : in_b[c - 512]);
        bias1[c] = v;
    } else if (idx < 394496) {
        int i = idx - 328960;
        int k = i / 256, n = i % 256;
        ((uint32_t*)wot)[i] = f2tf32(out_w[n * 256 + k]);
    } else if (idx < 460032) {
        int i = idx - 394496;
        ((uint32_t*)cw1t)[i] = f2tf32(cw1[i]);
    }
}

// ---------------------------------------------------------------------------
// Tensor-core tf32 GEMM. All operands pre-rounded -> bare LDS fragments.
// cp.async double-buffered, __launch_bounds__(256,2). Smem 71680 B.
// ---------------------------------------------------------------------------
__global__ __launch_bounds__(256, 2)
void gemm_tc(const float* __restrict__ X0, const float* __restrict__ X1,
             int ldx,
             const float* __restrict__ W, int ldw, int woff,
             const float* __restrict__ bias, int boff,
             float* __restrict__ C, int ldc, size_t czstride, int relu,
             __nv_bfloat16* __restrict__ bfaux, float* __restrict__ tfaux)
{
    extern __shared__ float gsm[];
    float* Abuf[2] = { gsm, gsm + 4608 };
    float* Bbuf[2] = { gsm + 9216, gsm + 9216 + 4352 };

    int z = blockIdx.z;
    const float* X = z ? X1 : X0;
    float* Cz = C + (size_t)z * czstride;

    int t = threadIdx.x;
    int lane = t & 31, w = t >> 5;
    int gid = lane >> 2, tig = lane & 3;
    int wm = w >> 2, wn = w & 3;
    int m0 = blockIdx.x * 128, n0 = blockIdx.y * 128;

    int ar[4], ac[4], br4[4], bc4[4];
    #pragma unroll
    for (int i = 0; i < 4; i++) {
        int lin = i * 1024 + t * 4;
        ar[i] = lin >> 5;  ac[i]  = lin & 31;
        br4[i] = lin >> 7; bc4[i] = lin & 127;
    }

    float acc[4][4][4];
    #pragma unroll
    for (int mi = 0; mi < 4; mi++)
        #pragma unroll
        for (int ni = 0; ni < 4; ni++)
            #pragma unroll
            for (int q = 0; q < 4; q++) acc[mi][ni][q] = 0.0f;

    #pragma unroll
    for (int i = 0; i < 4; i++) {
        cp16((uint32_t)__cvta_generic_to_shared(Abuf[0] + ar[i] * 36 + ac[i]),
             X + (size_t)(m0 + ar[i]) * ldx + ac[i]);
        cp16((uint32_t)__cvta_generic_to_shared(Bbuf[0] + br4[i] * 136 + bc4[i]),
             W + (size_t)br4[i] * ldw + woff + n0 + bc4[i]);
    }
    asm volatile("cp.async.commit_group;");

    for (int ch = 0; ch < 8; ch++) {
        if (ch < 7) {
            int k0 = (ch + 1) * 32;
            int buf = (ch + 1) & 1;
            #pragma unroll
            for (int i = 0; i < 4; i++) {
                cp16((uint32_t)__cvta_generic_to_shared(Abuf[buf] + ar[i] * 36 + ac[i]),
                     X + (size_t)(m0 + ar[i]) * ldx + k0 + ac[i]);
                cp16((uint32_t)__cvta_generic_to_shared(Bbuf[buf] + br4[i] * 136 + bc4[i]),
                     W + (size_t)(k0 + br4[i]) * ldw + woff + n0 + bc4[i]);
            }
            asm volatile("cp.async.commit_group;");
            asm volatile("cp.async.wait_group 1;");
        } else {
            asm volatile("cp.async.wait_group 0;");
        }
        __syncthreads();

        const uint32_t* A = (const uint32_t*)Abuf[ch & 1];
        const uint32_t* B = (const uint32_t*)Bbuf[ch & 1];

        #pragma unroll
        for (int ks = 0; ks < 4; ks++) {
            int kk = ks * 8;
            uint32_t a[4][4], b[4][2];
            #pragma unroll
            for (int mi = 0; mi < 4; mi++) {
                int rb = wm * 64 + mi * 16 + gid;
                a[mi][0] = A[rb * 36 + kk + tig];
                a[mi][1] = A[(rb + 8) * 36 + kk + tig];
                a[mi][2] = A[rb * 36 + kk + tig + 4];
                a[mi][3] = A[(rb + 8) * 36 + kk + tig + 4];
            }
            #pragma unroll
            for (int ni = 0; ni < 4; ni++) {
                int cb = wn * 32 + ni * 8 + gid;
                b[ni][0] = B[(kk + tig) * 136 + cb];
                b[ni][1] = B[(kk + tig + 4) * 136 + cb];
            }
            #pragma unroll
            for (int mi = 0; mi < 4; mi++)
                #pragma unroll
                for (int ni = 0; ni < 4; ni++)
                    mma_tf32(acc[mi][ni][0], acc[mi][ni][1], acc[mi][ni][2], acc[mi][ni][3],
                             a[mi][0], a[mi][1], a[mi][2], a[mi][3],
                             b[ni][0], b[ni][1]);
        }
        __syncthreads();
    }

    #pragma unroll
    for (int mi = 0; mi < 4; mi++) {
        int r0 = m0 + wm * 64 + mi * 16 + gid;
        #pragma unroll
        for (int ni = 0; ni < 4; ni++) {
            int col = n0 + wn * 32 + ni * 8 + 2 * tig;
            float bb0 = bias ? bias[boff + col]     : 0.0f;
            float bb1 = bias ? bias[boff + col + 1] : 0.0f;
            float2 v0, v1;
            v0.x = acc[mi][ni][0] + bb0; v0.y = acc[mi][ni][1] + bb1;
            v1.x = acc[mi][ni][2] + bb0; v1.y = acc[mi][ni][3] + bb1;
            if (relu) {
                v0.x = fmaxf(v0.x, 0.0f); v0.y = fmaxf(v0.y, 0.0f);
                v1.x = fmaxf(v1.x, 0.0f); v1.y = fmaxf(v1.y, 0.0f);
            }
            *(float2*)(Cz + (size_t)r0 * ldc + col)       = v0;
            *(float2*)(Cz + (size_t)(r0 + 8) * ldc + col) = v1;
            if (bfaux && col < 512) {
                __nv_bfloat162 h0 = __float22bfloat162_rn(v0);
                __nv_bfloat162 h1 = __float22bfloat162_rn(v1);
                *(__nv_bfloat162*)(bfaux + ((size_t)z * 8192 + r0) * 512 + col)       = h0;
                *(__nv_bfloat162*)(bfaux + ((size_t)z * 8192 + r0 + 8) * 512 + col)   = h1;
            }
            if (tfaux) {
                uint2 t0; t0.x = f2tf32(v0.x); t0.y = f2tf32(v0.y);
                uint2 t1; t1.x = f2tf32(v1.x); t1.y = f2tf32(v1.y);
                *(uint2*)(tfaux + (size_t)r0 * ldc + col)       = t0;
                *(uint2*)(tfaux + (size_t)(r0 + 8) * ldc + col) = t1;
            }
        }
    }
}

// ---------------------------------------------------------------------------
// Edge scatter v2: one warp per (batch, edge), BOTH modalities per warp.
// bf16x2 SIMD add+relu (one extra bf16 rounding on a+b; negligible per
// round-7 measurement). Interleaved dual reductions.
// ---------------------------------------------------------------------------
__device__ __forceinline__ float dot8_bf(uint4 av, uint4 bv,
                                         float4 wlo, float4 whi)
{
    const __nv_bfloat162* a2 = reinterpret_cast<const __nv_bfloat162*>(&av);
    const __nv_bfloat162* b2 = reinterpret_cast<const __nv_bfloat162*>(&bv);
    __nv_bfloat162 z2 = __float2bfloat162_rn(0.0f);
    float2 f0 = __bfloat1622float2(__hmax2(__hadd2(a2[0], b2[0]), z2));
    float2 f1 = __bfloat1622float2(__hmax2(__hadd2(a2[1], b2[1]), z2));
    float2 f2 = __bfloat1622float2(__hmax2(__hadd2(a2[2], b2[2]), z2));
    float2 f3 = __bfloat1622float2(__hmax2(__hadd2(a2[3], b2[3]), z2));
    float p = f0.x * wlo.x + f0.y * wlo.y;
    p += f1.x * wlo.z + f1.y * wlo.w;
    p += f2.x * whi.x + f2.y * whi.y;
    p += f3.x * whi.z + f3.y * whi.w;
    return p;
}

__global__ void edge_kernel(const __nv_bfloat16* __restrict__ ab,
                            const int* __restrict__ src, const int* __restrict__ dst,
                            const float* __restrict__ w2, const float* __restrict__ b2p,
                            float* __restrict__ wout)
{
    int gw   = (blockIdx.x * blockDim.x + threadIdx.x) >> 5;  // (b,e): 0..262143
    int lane = threadIdx.x & 31;
    int e = gw & 16383;
    int b = gw >> 14;
    int s = src[e], d = dst[e];

    const size_t rowA = ((size_t)b * 512 + s) * 512;
    const size_t rowB = ((size_t)b * 512 + d) * 512 + 256;
    const size_t MOFF = (size_t)8192 * 512;

    uint4 avi = ((const uint4*)(ab + rowA))[lane];
    uint4 bvi = ((const uint4*)(ab + rowB))[lane];
    uint4 avt = ((const uint4*)(ab + MOFF + rowA))[lane];
    uint4 bvt = ((const uint4*)(ab + MOFF + rowB))[lane];
    float4 wlo = *(const float4*)(w2 + lane * 8);
    float4 whi = *(const float4*)(w2 + lane * 8 + 4);

    float pi = dot8_bf(avi, bvi, wlo, whi);
    float pt = dot8_bf(avt, bvt, wlo, whi);

    #pragma unroll
    for (int off = 16; off > 0; off >>= 1) {
        pi += __shfl_xor_sync(0xFFFFFFFFu, pi, off);
        pt += __shfl_xor_sync(0xFFFFFFFFu, pt, off);
    }
    if (lane == 0) {
        float bb = b2p[0];
        size_t base = (size_t)b * 262144 + (size_t)s * 512 + d;
        wout[base]           = 1.0f / (1.0f + __expf(-(pi + bb)));
        wout[base + 4194304] = 1.0f / (1.0f + __expf(-(pt + bb)));
    }
}

// ---------------------------------------------------------------------------
// Tensor-core attention, 512 threads / 16 warps (256 query rows), K/V resident.
// K k-pair permuted (stride 40), LDS.64 S-phase fragments, two-half PV.
// ctx stored tf32-rounded. Smem 200704 B.
// ---------------------------------------------------------------------------
__global__ __launch_bounds__(512, 1)
void attn_kernel(const float* __restrict__ qbuf, int qld, int qoff, size_t qzs,
                 const float* __restrict__ kbuf, int kld, int koff, size_t kzs,
                 const float* __restrict__ vbuf, int vld, int voff, size_t vzs,
                 const float* __restrict__ mask, size_t mzs,
                 float* __restrict__ ctx, size_t czs)
{
    extern __shared__ uint32_t sm[];
    uint32_t* Ks = sm;               // [512][40], k-pair permuted columns
    uint32_t* Vs = sm + 20480;       // [512][40], row-major
    uint32_t* Pw = sm + 40960;       // 16 warps x [16][36]

    int zb = blockIdx.z;
    int b = zb & 15, mz = zb >> 4;
    const float* Q = qbuf + (size_t)mz * qzs;
    const float* K = kbuf + (size_t)mz * kzs;
    const float* V = vbuf + (size_t)mz * vzs;
    const float* M = mask ? mask + (size_t)mz * mzs : nullptr;
    float* O = ctx + (size_t)mz * czs;

    int h = blockIdx.y, chunk = blockIdx.x;
    int t = threadIdx.x, lane = t & 31, w = t >> 5;
    int gid = lane >> 2, tig = lane & 3;

    uint32_t* Ps = Pw + w * 576;
    int i0 = chunk * 256 + w * 16;
    const float scale = 0.17677669529663687f;  // 1/sqrt(32)

    const float* mrow0 = M ? M + (size_t)b * 262144 + (size_t)(i0 + gid) * 512 : nullptr;
    const float* mrow1 = mrow0 ? mrow0 + 8 * 512 : nullptr;

    for (int i = t; i < 4096; i += 512) {
        int row = i >> 3, j = i & 7, c4 = j * 4;
        size_t rk = (size_t)(b * 512 + row);
        float4 kv = *(const float4*)(K + rk * kld + koff + h * 32 + c4);
        int kb = row * 40 + ((j >> 1) << 3) + (j & 1);
        Ks[kb + 0] = f2tf32(kv.x);
        Ks[kb + 2] = f2tf32(kv.y);
        Ks[kb + 4] = f2tf32(kv.z);
        Ks[kb + 6] = f2tf32(kv.w);
        float4 vv = *(const float4*)(V + rk * vld + voff + h * 32 + c4);
        uint4 vt4; vt4.x = f2tf32(vv.x); vt4.y = f2tf32(vv.y);
        vt4.z = f2tf32(vv.z); vt4.w = f2tf32(vv.w);
        *(uint4*)&Vs[row * 40 + c4] = vt4;
    }

    uint32_t qa[4][4];
    {
        const float* q0p = Q + (size_t)(b * 512 + i0 + gid) * qld + qoff + h * 32;
        const float* q1p = q0p + (size_t)8 * qld;
        #pragma unroll
        for (int ks = 0; ks < 4; ks++) {
            qa[ks][0] = f2tf32(q0p[ks * 8 + tig] * scale);
            qa[ks][1] = f2tf32(q1p[ks * 8 + tig] * scale);
            qa[ks][2] = f2tf32(q0p[ks * 8 + tig + 4] * scale);
            qa[ks][3] = f2tf32(q1p[ks * 8 + tig + 4] * scale);
        }
    }

    float2 mv0[8], mv1[8];
    if (mrow0) {
        #pragma unroll
        for (int nt = 0; nt < 8; nt++) {
            int col = nt * 8 + 2 * tig;
            mv0[nt] = *(const float2*)(mrow0 + col);
            mv1[nt] = *(const float2*)(mrow1 + col);
        }
    }

    __syncthreads();

    float oacc[4][4];
    #pragma unroll
    for (int vt = 0; vt < 4; vt++)
        #pragma unroll
        for (int q = 0; q < 4; q++) oacc[vt][q] = 0.0f;
    float rsum0 = 0.0f, rsum1 = 0.0f;

    for (int kc = 0; kc < 8; kc++) {
        float sacc[8][4];
        #pragma unroll
        for (int nt = 0; nt < 8; nt++)
            #pragma unroll
            for (int q = 0; q < 4; q++) sacc[nt][q] = 0.0f;

        #pragma unroll
        for (int ks = 0; ks < 4; ks++) {
            #pragma unroll
            for (int nt = 0; nt < 8; nt++) {
                int key = kc * 64 + nt * 8 + gid;
                uint2 kb2 = *(const uint2*)&Ks[key * 40 + ks * 8 + 2 * tig];
                mma_tf32(sacc[nt][0], sacc[nt][1], sacc[nt][2], sacc[nt][3],
                         qa[ks][0], qa[ks][1], qa[ks][2], qa[ks][3], kb2.x, kb2.y);
            }
        }

        #pragma unroll
        for (int hh = 0; hh < 2; hh++) {
            #pragma unroll
            for (int nt2 = 0; nt2 < 4; nt2++) {
                int nt = hh * 4 + nt2;
                float s0 = sacc[nt][0], s1 = sacc[nt][1];
                float s2 = sacc[nt][2], s3 = sacc[nt][3];
                if (mrow0) {
                    s0 += mv0[nt].x; s1 += mv0[nt].y;
                    s2 += mv1[nt].x; s3 += mv1[nt].y;
                }
                float p0 = __expf(s0), p1 = __expf(s1);
                float p2 = __expf(s2), p3 = __expf(s3);
                rsum0 += p0 + p1;
                rsum1 += p2 + p3;
                uint2 u0; u0.x = f2tf32(p0); u0.y = f2tf32(p1);
                uint2 u1; u1.x = f2tf32(p2); u1.y = f2tf32(p3);
                *(uint2*)&Ps[gid * 36 + nt2 * 8 + 2 * tig]       = u0;
                *(uint2*)&Ps[(gid + 8) * 36 + nt2 * 8 + 2 * tig] = u1;
            }
            if (hh == 1 && mrow0 && kc < 7) {
                #pragma unroll
                for (int nt = 0; nt < 8; nt++) {
                    int col = (kc + 1) * 64 + nt * 8 + 2 * tig;
                    mv0[nt] = *(const float2*)(mrow0 + col);
                    mv1[nt] = *(const float2*)(mrow1 + col);
                }
            }
            __syncwarp();

            #pragma unroll
            for (int ks2 = 0; ks2 < 4; ks2++) {
                uint32_t a0 = Ps[gid * 36 + ks2 * 8 + tig];
                uint32_t a1 = Ps[(gid + 8) * 36 + ks2 * 8 + tig];
                uint32_t a2 = Ps[gid * 36 + ks2 * 8 + tig + 4];
                uint32_t a3 = Ps[(gid + 8) * 36 + ks2 * 8 + tig + 4];
                int keyb = kc * 64 + (hh * 4 + ks2) * 8;
                #pragma unroll
                for (int vt = 0; vt < 4; vt++) {
                    uint32_t b0 = Vs[(keyb + tig) * 40 + vt * 8 + gid];
                    uint32_t b1 = Vs[(keyb + tig + 4) * 40 + vt * 8 + gid];
                    mma_tf32(oacc[vt][0], oacc[vt][1], oacc[vt][2], oacc[vt][3],
                             a0, a1, a2, a3, b0, b1);
                }
            }
            __syncwarp();
        }
    }

    rsum0 += __shfl_xor_sync(0xFFFFFFFFu, rsum0, 1);
    rsum0 += __shfl_xor_sync(0xFFFFFFFFu, rsum0, 2);
    rsum1 += __shfl_xor_sync(0xFFFFFFFFu, rsum1, 1);
    rsum1 += __shfl_xor_sync(0xFFFFFFFFu, rsum1, 2);
    float inv0 = 1.0f / rsum0, inv1 = 1.0f / rsum1;

    size_t r0 = (size_t)(b * 512 + i0 + gid) * 256 + h * 32;
    size_t r1 = r0 + (size_t)8 * 256;
    #pragma unroll
    for (int vt = 0; vt < 4; vt++) {
        uint2 v0; v0.x = f2tf32(oacc[vt][0] * inv0); v0.y = f2tf32(oacc[vt][1] * inv0);
        uint2 v1; v1.x = f2tf32(oacc[vt][2] * inv1); v1.y = f2tf32(oacc[vt][3] * inv1);
        *(uint2*)(O + r0 + vt * 8 + 2 * tig) = v0;
        *(uint2*)(O + r1 + vt * 8 + 2 * tig) = v1;
    }
}

// ---------------------------------------------------------------------------
__global__ void cons_reduce(const float* __restrict__ H, const float* __restrict__ cw2,
                            const float* __restrict__ cb2, float* __restrict__ out)
{
    int gw   = (blockIdx.x * blockDim.x + threadIdx.x) >> 5;
    int lane = threadIdx.x & 31;
    const float4* h4 = (const float4*)(H + (size_t)gw * 256);
    const float4* w4 = (const float4*)cw2;
    float p = 0.0f;
    #pragma unroll
    for (int u = 0; u < 2; u++) {
        int idx = u * 32 + lane;
        float4 a = h4[idx], w = w4[idx];
        p += a.x * w.x + a.y * w.y + a.z * w.z + a.w * w.w;
    }
    #pragma unroll
    for (int off = 16; off > 0; off >>= 1)
        p += __shfl_xor_sync(0xFFFFFFFFu, p, off);
    if (lane == 0)
        out[gw] = 1.0f / (1.0f + __expf(-(p + cb2[0])));
}

// ---------------------------------------------------------------------------
extern "C" void kernel_launch(void* const* d_in, const int* in_sizes, int n_in,
                              void* d_out, int out_size)
{
    const float* img   = (const float*)d_in[0];
    const float* txt   = (const float*)d_in[1];
    const int*   src   = (const int*)  d_in[2];
    const int*   dst   = (const int*)  d_in[3];
    const float* w1    = (const float*)d_in[4];
    const float* b1    = (const float*)d_in[5];
    const float* w2    = (const float*)d_in[6];
    const float* b2    = (const float*)d_in[7];
    const float* in_w  = (const float*)d_in[8];
    const float* in_b  = (const float*)d_in[9];
    const float* out_w = (const float*)d_in[10];
    const float* out_b = (const float*)d_in[11];
    const float* cw1   = (const float*)d_in[12];
    const float* cb1   = (const float*)d_in[13];
    const float* cw2   = (const float*)d_in[14];
    const float* cb2   = (const float*)d_in[15];
    float* out = (float*)d_out;

    float* S = nullptr;
    cudaGetSymbolAddress((void**)&S, g_scratch);

    float* wcat  = S + OFF_WCAT;
    float* bias1 = S + OFF_BIAS1;
    float* wot   = S + OFF_WOT;
    float* proj  = S + OFF_PROJ;
    float* ctx   = S + OFF_CTX;
    float* qc    = S + OFF_QC;
    float* kvc   = S + OFF_KVC;
    float* ctx2  = S + OFF_CTX2;
    __nv_bfloat16* bfab = (__nv_bfloat16*)(S + OFF_BF);
    float* intf  = S + OFF_INT;
    float* attf  = S + OFF_ATTF;
    float* cw1t  = S + OFF_CW1T;
    float* Hbuf  = proj;

    float* att_img = out;
    float* att_txt = out + 2097152;
    float* cross   = out + 4194304;
    float* wimg    = out + 6291456;
    float* cons    = out + 14680064;

    const int ATTN_SMEM = 200704;
    const int GEMM_SMEM = 71680;
    cudaFuncSetAttribute(attn_kernel, cudaFuncAttributeMaxDynamicSharedMemorySize, ATTN_SMEM);
    cudaFuncSetAttribute(gemm_tc,     cudaFuncAttributeMaxDynamicSharedMemorySize, GEMM_SMEM);

    const size_t PSTRIDE = (size_t)8192 * 1280;
    const size_t CSTRIDE = (size_t)8192 * 256;
    const size_t MSTRIDE = (size_t)4194304;

    // 1. prep: tf32-rounded inputs + packed/rounded weights (one launch)
    prep_kernel<<<9989, 256>>>(img, txt, intf,
                               w1, b1, in_w, in_b, out_w, cw1,
                               wcat, bias1, wot, cw1t);

    // 2. zero both weight matrices
    cudaMemsetAsync(wimg, 0, (size_t)8388608 * 4);

    // 3. fused node projections (both modalities, grid.z=2) + bf16 A|Bm copy
    gemm_tc<<<dim3(64, 10, 2), 256, GEMM_SMEM>>>(intf, intf + 4194304, 256,
                                                 wcat, 1280, 0, bias1, 0,
                                                 proj, 1280, PSTRIDE, 0, bfab, nullptr);

    // 4. per-edge causal weights (one warp = both modalities)
    edge_kernel<<<32768, 256>>>(bfab, src, dst, w2, b2, wimg);

    // 5. masked self-attention, both modalities (grid.z=32)
    attn_kernel<<<dim3(2, 8, 32), 512, ATTN_SMEM>>>(
        proj, 1280, 512, PSTRIDE,
        proj, 1280, 768, PSTRIDE,
        proj, 1280, 1024, PSTRIDE,
        wimg, MSTRIDE,
        ctx, CSTRIDE);

    // 6. out-proj -> attended_* (fp32) + tf32 side-copy attf
    gemm_tc<<<dim3(128, 2, 1), 256, GEMM_SMEM>>>(ctx, ctx, 256, wot, 256, 0, out_b, 0,
                                                 att_img, 256, 0, 0, nullptr, attf);

    // 7. consistency
    gemm_tc<<<dim3(128, 2, 1), 256, GEMM_SMEM>>>(attf, attf, 256, cw1t, 256, 0, cb1, 0,
                                                 Hbuf, 256, 0, 1, nullptr, nullptr);
    cons_reduce<<<2048, 256>>>(Hbuf, cw2, cb2, cons);

    // 8. cross-modal
    gemm_tc<<<dim3(64, 2, 1), 256, GEMM_SMEM>>>(attf, attf, 256, wcat, 1280, 512, bias1, 512,
                                                qc, 256, 0, 0, nullptr, nullptr);
    gemm_tc<<<dim3(64, 4, 1), 256, GEMM_SMEM>>>(attf + (size_t)8192 * 256, attf, 256,
                                                wcat, 1280, 768, bias1, 768,
                                                kvc, 512, 0, 0, nullptr, nullptr);
    attn_kernel<<<dim3(2, 8, 16), 512, ATTN_SMEM>>>(
        qc, 256, 0, 0,
        kvc, 512, 0, 0,
        kvc, 512, 256, 0,
        nullptr, 0,
        ctx2, 0);
    gemm_tc<<<dim3(64, 2, 1), 256, GEMM_SMEM>>>(ctx2, ctx2, 256, wot, 256, 0, out_b, 0,
                                                cross, 256, 0, 0, nullptr, nullptr);
}

// round 13
// speedup vs baseline: 1.4182x; 1.2444x over previous
#include <cuda_runtime.h>
#include <cuda_bf16.h>
#include <cuda_fp16.h>
#include <cstddef>
#include <cstdint>

// Problem constants: B=16, N=512, D=256, H=8, DH=32, E=16384
// d_out layout (floats):
//   attended_img   [0,        2097152)
//   attended_text  [2097152,  4194304)
//   cross_modal    [4194304,  6291456)
//   img_weights    [6291456, 10485760)
//   text_weights   [10485760,14680064)
//   img_cons       [14680064,14688256)
//   text_cons      [14688256,14696448)

// Scratch offsets in floats (regions sized for their old fp32 use; fp16 users
// occupy a prefix of their region).
#define OFF_WCAT   0u             // fp16 k-paired [128 k2][1280]: 163840 words
#define OFF_BIAS1  327680u        // 1280 fp32
#define OFF_WOT    328960u        // fp16 k-paired [128 k2][256]: 32768 words
#define OFF_PROJ   394496u        // fp32 16384x1280 (reused as H for consistency)
#define OFF_CTX    21366016u      // fp16 16384x256 (written by attn)
#define OFF_QC     25560320u      // fp32 8192x256
#define OFF_KVC    27657472u      // fp32 8192x512
#define OFF_CTX2   31851776u      // fp16 8192x256 (written by attn)
#define OFF_BF     33948928u      // bf16 A|Bm buffer: 16384*512 bf16
#define OFF_INT    38143232u      // fp16 img|txt: 16384x256 halfs
#define OFF_ATTF   46531840u      // fp16 att_img|att_txt: 16384x256 halfs
#define OFF_CW1T   50726144u      // fp16 k-paired [128 k2][256]: 32768 words
#define SCRATCH_FLOATS 50791680u

__device__ float g_scratch[SCRATCH_FLOATS];

// ---------------------------------------------------------------------------
__device__ __forceinline__ uint32_t f2tf32(float f) {
    uint32_t r;
    asm("cvt.rna.tf32.f32 %0, %1;" : "=r"(r) : "f"(f));
    return r;
}

__device__ __forceinline__ uint32_t pack_h2(float a, float b) {
    __half2 h = __floats2half2_rn(a, b);
    return *reinterpret_cast<uint32_t*>(&h);
}

// tf32 mma (attention)
__device__ __forceinline__ void mma_tf32(float& d0, float& d1, float& d2, float& d3,
                                         uint32_t a0, uint32_t a1, uint32_t a2, uint32_t a3,
                                         uint32_t b0, uint32_t b1)
{
    asm volatile(
        "mma.sync.aligned.m16n8k8.row.col.f32.tf32.tf32.f32 "
        "{%0,%1,%2,%3}, {%4,%5,%6,%7}, {%8,%9}, {%0,%1,%2,%3};"
        : "+f"(d0), "+f"(d1), "+f"(d2), "+f"(d3)
        : "r"(a0), "r"(a1), "r"(a2), "r"(a3), "r"(b0), "r"(b1));
}

// fp16 mma (GEMMs): m16n8k16, fp32 accumulate
__device__ __forceinline__ void mma_f16(float& d0, float& d1, float& d2, float& d3,
                                        uint32_t a0, uint32_t a1, uint32_t a2, uint32_t a3,
                                        uint32_t b0, uint32_t b1)
{
    asm volatile(
        "mma.sync.aligned.m16n8k16.row.col.f32.f16.f16.f32 "
        "{%0,%1,%2,%3}, {%4,%5,%6,%7}, {%8,%9}, {%0,%1,%2,%3};"
        : "+f"(d0), "+f"(d1), "+f"(d2), "+f"(d3)
        : "r"(a0), "r"(a1), "r"(a2), "r"(a3), "r"(b0), "r"(b1));
}

__device__ __forceinline__ void cp16(uint32_t smem, const void* g) {
    asm volatile("cp.async.ca.shared.global [%0], [%1], 16;" :: "r"(smem), "l"(g));
}

// ---------------------------------------------------------------------------
// prep: blocks [0,4096): img|txt -> fp16 row-major intf (uint4 = 8 halfs)
//       blocks [4096,...): fp16 k-paired weights wcat/wot/cw1t + fp32 bias1
// ---------------------------------------------------------------------------
__device__ __forceinline__ float wcat_src(const float* w1, const float* in_w,
                                          int k, int c)
{
    if (c < 256)  return w1[k * 256 + c];
    if (c < 512)  return w1[(256 + k) * 256 + (c - 256)];
    if (c < 768)  return in_w[(c - 512) * 256 + k];
    if (c < 1024) return in_w[(c - 768 + 256) * 256 + k];
    return in_w[(c - 1024 + 512) * 256 + k];
}

__global__ void prep_kernel(const float* __restrict__ img, const float* __restrict__ txt,
                            uint32_t* __restrict__ intf,
                            const float* __restrict__ w1, const float* __restrict__ b1,
                            const float* __restrict__ in_w, const float* __restrict__ in_b,
                            const float* __restrict__ out_w, const float* __restrict__ cw1,
                            uint32_t* __restrict__ wcat, float* __restrict__ bias1,
                            uint32_t* __restrict__ wot, uint32_t* __restrict__ cw1t)
{
    if (blockIdx.x < 4096) {
        int i = blockIdx.x * 256 + threadIdx.x;      // uint4 index (8 halfs)
        const float* srcp = (i < 524288) ? img : txt;
        int j = (i < 524288) ? i : i - 524288;
        float4 v0 = ((const float4*)srcp)[j * 2];
        float4 v1 = ((const float4*)srcp)[j * 2 + 1];
        uint4 u;
        u.x = pack_h2(v0.x, v0.y); u.y = pack_h2(v0.z, v0.w);
        u.z = pack_h2(v1.x, v1.y); u.w = pack_h2(v1.z, v1.w);
        ((uint4*)intf)[i] = u;
        return;
    }
    int idx = (blockIdx.x - 4096) * 256 + threadIdx.x;
    if (idx < 163840) {
        int k2 = idx / 1280, c = idx % 1280;
        float v0 = wcat_src(w1, in_w, 2 * k2, c);
        float v1 = wcat_src(w1, in_w, 2 * k2 + 1, c);
        wcat[idx] = pack_h2(v0, v1);
    } else if (idx < 165120) {
        int c = idx - 163840;
        bias1[c] = (c < 256) ? b1[c] : (c < 512 ? 0.0f : in_b[c - 512]);
    } else if (idx < 197888) {
        int i = idx - 165120;
        int k2 = i >> 8, n = i & 255;
        float2 v = *(const float2*)(out_w + n * 256 + 2 * k2);
        wot[i] = pack_h2(v.x, v.y);
    } else if (idx < 230656) {
        int i = idx - 197888;
        int k2 = i >> 8, n = i & 255;
        cw1t[i] = pack_h2(cw1[(2 * k2) * 256 + n], cw1[(2 * k2 + 1) * 256 + n]);
    }
}

// ---------------------------------------------------------------------------
// fp16 tensor-core GEMM: C[Mx Nc] = X[M x 256] * W[256 x Nc] (+bias)(opt relu)
// X: fp16 row-major (uint32 = k-pair), ldx words/row.
// W: fp16 k-paired [k2][n] uint32, ldw words/row (n-columns).
// As[128][20] words, Bs[16][136] words, double buffered (static 37888 B).
// Block tile 128x128, K-chunk 32 (2 x k16 mma steps). 256 thr, 2 blocks/SM.
// ---------------------------------------------------------------------------
__global__ __launch_bounds__(256, 2)
void gemm_f16(const uint32_t* __restrict__ X0, const uint32_t* __restrict__ X1,
              int ldx,
              const uint32_t* __restrict__ W, int ldw, int woff,
              const float* __restrict__ bias, int boff,
              float* __restrict__ C, int ldc, size_t czstride, int relu,
              __nv_bfloat16* __restrict__ bfaux, __half* __restrict__ f16aux)
{
    __shared__ __align__(16) uint32_t As[2][2560];   // 128 x 20
    __shared__ __align__(16) uint32_t Bs[2][2176];   // 16 x 136

    int z = blockIdx.z;
    const uint32_t* X = z ? X1 : X0;
    float* Cz = C + (size_t)z * czstride;

    int t = threadIdx.x;
    int lane = t & 31, w = t >> 5;
    int gid = lane >> 2, tig = lane & 3;
    int wm = w >> 2, wn = w & 3;
    int m0 = blockIdx.x * 128, n0 = blockIdx.y * 128;

    // staging coords (words)
    int ar[2], ac[2], br[2], bc[2];
    #pragma unroll
    for (int i = 0; i < 2; i++) {
        int lin = i * 1024 + t * 4;
        ar[i] = lin >> 4;  ac[i] = lin & 15;
        br[i] = lin >> 7;  bc[i] = lin & 127;
    }

    float acc[4][4][4];
    #pragma unroll
    for (int mi = 0; mi < 4; mi++)
        #pragma unroll
        for (int ni = 0; ni < 4; ni++)
            #pragma unroll
            for (int q = 0; q < 4; q++) acc[mi][ni][q] = 0.0f;

    #pragma unroll
    for (int i = 0; i < 2; i++) {
        cp16((uint32_t)__cvta_generic_to_shared(&As[0][ar[i] * 20 + ac[i]]),
             X + (size_t)(m0 + ar[i]) * ldx + ac[i]);
        cp16((uint32_t)__cvta_generic_to_shared(&Bs[0][br[i] * 136 + bc[i]]),
             W + (size_t)br[i] * ldw + woff + n0 + bc[i]);
    }
    asm volatile("cp.async.commit_group;");

    for (int ch = 0; ch < 8; ch++) {
        if (ch < 7) {
            int k0w = (ch + 1) * 16;
            int buf = (ch + 1) & 1;
            #pragma unroll
            for (int i = 0; i < 2; i++) {
                cp16((uint32_t)__cvta_generic_to_shared(&As[buf][ar[i] * 20 + ac[i]]),
                     X + (size_t)(m0 + ar[i]) * ldx + k0w + ac[i]);
                cp16((uint32_t)__cvta_generic_to_shared(&Bs[buf][br[i] * 136 + bc[i]]),
                     W + (size_t)(k0w + br[i]) * ldw + woff + n0 + bc[i]);
            }
            asm volatile("cp.async.commit_group;");
            asm volatile("cp.async.wait_group 1;");
        } else {
            asm volatile("cp.async.wait_group 0;");
        }
        __syncthreads();

        const uint32_t* A = As[ch & 1];
        const uint32_t* B = Bs[ch & 1];

        #pragma unroll
        for (int ks = 0; ks < 2; ks++) {
            int kk = ks * 8;
            uint32_t a[4][4], b[4][2];
            #pragma unroll
            for (int mi = 0; mi < 4; mi++) {
                int rb = wm * 64 + mi * 16 + gid;
                a[mi][0] = A[rb * 20 + kk + tig];
                a[mi][1] = A[(rb + 8) * 20 + kk + tig];
                a[mi][2] = A[rb * 20 + kk + tig + 4];
                a[mi][3] = A[(rb + 8) * 20 + kk + tig + 4];
            }
            #pragma unroll
            for (int ni = 0; ni < 4; ni++) {
                int cb = wn * 32 + ni * 8 + gid;
                b[ni][0] = B[(kk + tig) * 136 + cb];
                b[ni][1] = B[(kk + tig + 4) * 136 + cb];
            }
            #pragma unroll
            for (int mi = 0; mi < 4; mi++)
                #pragma unroll
                for (int ni = 0; ni < 4; ni++)
                    mma_f16(acc[mi][ni][0], acc[mi][ni][1], acc[mi][ni][2], acc[mi][ni][3],
                            a[mi][0], a[mi][1], a[mi][2], a[mi][3],
                            b[ni][0], b[ni][1]);
        }
        __syncthreads();
    }

    #pragma unroll
    for (int mi = 0; mi < 4; mi++) {
        int r0 = m0 + wm * 64 + mi * 16 + gid;
        #pragma unroll
        for (int ni = 0; ni < 4; ni++) {
            int col = n0 + wn * 32 + ni * 8 + 2 * tig;
            float bb0 = bias ? bias[boff + col]     : 0.0f;
            float bb1 = bias ? bias[boff + col + 1] : 0.0f;
            float2 v0, v1;
            v0.x = acc[mi][ni][0] + bb0; v0.y = acc[mi][ni][1] + bb1;
            v1.x = acc[mi][ni][2] + bb0; v1.y = acc[mi][ni][3] + bb1;
            if (relu) {
                v0.x = fmaxf(v0.x, 0.0f); v0.y = fmaxf(v0.y, 0.0f);
                v1.x = fmaxf(v1.x, 0.0f); v1.y = fmaxf(v1.y, 0.0f);
            }
            *(float2*)(Cz + (size_t)r0 * ldc + col)       = v0;
            *(float2*)(Cz + (size_t)(r0 + 8) * ldc + col) = v1;
            if (bfaux && col < 512) {
                __nv_bfloat162 h0 = __float22bfloat162_rn(v0);
                __nv_bfloat162 h1 = __float22bfloat162_rn(v1);
                *(__nv_bfloat162*)(bfaux + ((size_t)z * 8192 + r0) * 512 + col)     = h0;
                *(__nv_bfloat162*)(bfaux + ((size_t)z * 8192 + r0 + 8) * 512 + col) = h1;
            }
            if (f16aux) {
                *(__half2*)(f16aux + (size_t)r0 * ldc + col)       = __floats2half2_rn(v0.x, v0.y);
                *(__half2*)(f16aux + (size_t)(r0 + 8) * ldc + col) = __floats2half2_rn(v1.x, v1.y);
            }
        }
    }
}

// ---------------------------------------------------------------------------
// Edge scatter: one warp per (batch, edge), both modalities. bf16x2 SIMD.
// ---------------------------------------------------------------------------
__device__ __forceinline__ float dot8_bf(uint4 av, uint4 bv,
                                         float4 wlo, float4 whi)
{
    const __nv_bfloat162* a2 = reinterpret_cast<const __nv_bfloat162*>(&av);
    const __nv_bfloat162* b2 = reinterpret_cast<const __nv_bfloat162*>(&bv);
    __nv_bfloat162 z2 = __float2bfloat162_rn(0.0f);
    float2 f0 = __bfloat1622float2(__hmax2(__hadd2(a2[0], b2[0]), z2));
    float2 f1 = __bfloat1622float2(__hmax2(__hadd2(a2[1], b2[1]), z2));
    float2 f2 = __bfloat1622float2(__hmax2(__hadd2(a2[2], b2[2]), z2));
    float2 f3 = __bfloat1622float2(__hmax2(__hadd2(a2[3], b2[3]), z2));
    float p = f0.x * wlo.x + f0.y * wlo.y;
    p += f1.x * wlo.z + f1.y * wlo.w;
    p += f2.x * whi.x + f2.y * whi.y;
    p += f3.x * whi.z + f3.y * whi.w;
    return p;
}

__global__ void edge_kernel(const __nv_bfloat16* __restrict__ ab,
                            const int* __restrict__ src, const int* __restrict__ dst,
                            const float* __restrict__ w2, const float* __restrict__ b2p,
                            float* __restrict__ wout)
{
    int gw   = (blockIdx.x * blockDim.x + threadIdx.x) >> 5;
    int lane = threadIdx.x & 31;
    int e = gw & 16383;
    int b = gw >> 14;
    int s = src[e], d = dst[e];

    const size_t rowA = ((size_t)b * 512 + s) * 512;
    const size_t rowB = ((size_t)b * 512 + d) * 512 + 256;
    const size_t MOFF = (size_t)8192 * 512;

    uint4 avi = ((const uint4*)(ab + rowA))[lane];
    uint4 bvi = ((const uint4*)(ab + rowB))[lane];
    uint4 avt = ((const uint4*)(ab + MOFF + rowA))[lane];
    uint4 bvt = ((const uint4*)(ab + MOFF + rowB))[lane];
    float4 wlo = *(const float4*)(w2 + lane * 8);
    float4 whi = *(const float4*)(w2 + lane * 8 + 4);

    float pi = dot8_bf(avi, bvi, wlo, whi);
    float pt = dot8_bf(avt, bvt, wlo, whi);

    #pragma unroll
    for (int off = 16; off > 0; off >>= 1) {
        pi += __shfl_xor_sync(0xFFFFFFFFu, pi, off);
        pt += __shfl_xor_sync(0xFFFFFFFFu, pt, off);
    }
    if (lane == 0) {
        float bb = b2p[0];
        size_t base = (size_t)b * 262144 + (size_t)s * 512 + d;
        wout[base]           = 1.0f / (1.0f + __expf(-(pi + bb)));
        wout[base + 4194304] = 1.0f / (1.0f + __expf(-(pt + bb)));
    }
}

// ---------------------------------------------------------------------------
// Tensor-core attention (tf32), output written as fp16 (feeds fp16 GEMMs).
// 512 threads / 16 warps (256 query rows), K/V resident, K k-pair permuted.
// Smem 200704 B.
// ---------------------------------------------------------------------------
__global__ __launch_bounds__(512, 1)
void attn_kernel(const float* __restrict__ qbuf, int qld, int qoff, size_t qzs,
                 const float* __restrict__ kbuf, int kld, int koff, size_t kzs,
                 const float* __restrict__ vbuf, int vld, int voff, size_t vzs,
                 const float* __restrict__ mask, size_t mzs,
                 __half* __restrict__ ctx, size_t czs)
{
    extern __shared__ uint32_t sm[];
    uint32_t* Ks = sm;               // [512][40], k-pair permuted columns
    uint32_t* Vs = sm + 20480;       // [512][40], row-major
    uint32_t* Pw = sm + 40960;       // 16 warps x [16][36]

    int zb = blockIdx.z;
    int b = zb & 15, mz = zb >> 4;
    const float* Q = qbuf + (size_t)mz * qzs;
    const float* K = kbuf + (size_t)mz * kzs;
    const float* V = vbuf + (size_t)mz * vzs;
    const float* M = mask ? mask + (size_t)mz * mzs : nullptr;
    __half* O = ctx + (size_t)mz * czs;

    int h = blockIdx.y, chunk = blockIdx.x;
    int t = threadIdx.x, lane = t & 31, w = t >> 5;
    int gid = lane >> 2, tig = lane & 3;

    uint32_t* Ps = Pw + w * 576;
    int i0 = chunk * 256 + w * 16;
    const float scale = 0.17677669529663687f;  // 1/sqrt(32)

    const float* mrow0 = M ? M + (size_t)b * 262144 + (size_t)(i0 + gid) * 512 : nullptr;
    const float* mrow1 = mrow0 ? mrow0 + 8 * 512 : nullptr;

    for (int i = t; i < 4096; i += 512) {
        int row = i >> 3, j = i & 7, c4 = j * 4;
        size_t rk = (size_t)(b * 512 + row);
        float4 kv = *(const float4*)(K + rk * kld + koff + h * 32 + c4);
        int kb = row * 40 + ((j >> 1) << 3) + (j & 1);
        Ks[kb + 0] = f2tf32(kv.x);
        Ks[kb + 2] = f2tf32(kv.y);
        Ks[kb + 4] = f2tf32(kv.z);
        Ks[kb + 6] = f2tf32(kv.w);
        float4 vv = *(const float4*)(V + rk * vld + voff + h * 32 + c4);
        uint4 vt4; vt4.x = f2tf32(vv.x); vt4.y = f2tf32(vv.y);
        vt4.z = f2tf32(vv.z); vt4.w = f2tf32(vv.w);
        *(uint4*)&Vs[row * 40 + c4] = vt4;
    }

    uint32_t qa[4][4];
    {
        const float* q0p = Q + (size_t)(b * 512 + i0 + gid) * qld + qoff + h * 32;
        const float* q1p = q0p + (size_t)8 * qld;
        #pragma unroll
        for (int ks = 0; ks < 4; ks++) {
            qa[ks][0] = f2tf32(q0p[ks * 8 + tig] * scale);
            qa[ks][1] = f2tf32(q1p[ks * 8 + tig] * scale);
            qa[ks][2] = f2tf32(q0p[ks * 8 + tig + 4] * scale);
            qa[ks][3] = f2tf32(q1p[ks * 8 + tig + 4] * scale);
        }
    }

    float2 mv0[8], mv1[8];
    if (mrow0) {
        #pragma unroll
        for (int nt = 0; nt < 8; nt++) {
            int col = nt * 8 + 2 * tig;
            mv0[nt] = *(const float2*)(mrow0 + col);
            mv1[nt] = *(const float2*)(mrow1 + col);
        }
    }

    __syncthreads();

    float oacc[4][4];
    #pragma unroll
    for (int vt = 0; vt < 4; vt++)
        #pragma unroll
        for (int q = 0; q < 4; q++) oacc[vt][q] = 0.0f;
    float rsum0 = 0.0f, rsum1 = 0.0f;

    for (int kc = 0; kc < 8; kc++) {
        float sacc[8][4];
        #pragma unroll
        for (int nt = 0; nt < 8; nt++)
            #pragma unroll
            for (int q = 0; q < 4; q++) sacc[nt][q] = 0.0f;

        #pragma unroll
        for (int ks = 0; ks < 4; ks++) {
            #pragma unroll
            for (int nt = 0; nt < 8; nt++) {
                int key = kc * 64 + nt * 8 + gid;
                uint2 kb2 = *(const uint2*)&Ks[key * 40 + ks * 8 + 2 * tig];
                mma_tf32(sacc[nt][0], sacc[nt][1], sacc[nt][2], sacc[nt][3],
                         qa[ks][0], qa[ks][1], qa[ks][2], qa[ks][3], kb2.x, kb2.y);
            }
        }

        #pragma unroll
        for (int hh = 0; hh < 2; hh++) {
            #pragma unroll
            for (int nt2 = 0; nt2 < 4; nt2++) {
                int nt = hh * 4 + nt2;
                float s0 = sacc[nt][0], s1 = sacc[nt][1];
                float s2 = sacc[nt][2], s3 = sacc[nt][3];
                if (mrow0) {
                    s0 += mv0[nt].x; s1 += mv0[nt].y;
                    s2 += mv1[nt].x; s3 += mv1[nt].y;
                }
                float p0 = __expf(s0), p1 = __expf(s1);
                float p2 = __expf(s2), p3 = __expf(s3);
                rsum0 += p0 + p1;
                rsum1 += p2 + p3;
                uint2 u0; u0.x = f2tf32(p0); u0.y = f2tf32(p1);
                uint2 u1; u1.x = f2tf32(p2); u1.y = f2tf32(p3);
                *(uint2*)&Ps[gid * 36 + nt2 * 8 + 2 * tig]       = u0;
                *(uint2*)&Ps[(gid + 8) * 36 + nt2 * 8 + 2 * tig] = u1;
            }
            if (hh == 1 && mrow0 && kc < 7) {
                #pragma unroll
                for (int nt = 0; nt < 8; nt++) {
                    int col = (kc + 1) * 64 + nt * 8 + 2 * tig;
                    mv0[nt] = *(const float2*)(mrow0 + col);
                    mv1[nt] = *(const float2*)(mrow1 + col);
                }
            }
            __syncwarp();

            #pragma unroll
            for (int ks2 = 0; ks2 < 4; ks2++) {
                uint32_t a0 = Ps[gid * 36 + ks2 * 8 + tig];
                uint32_t a1 = Ps[(gid + 8) * 36 + ks2 * 8 + tig];
                uint32_t a2 = Ps[gid * 36 + ks2 * 8 + tig + 4];
                uint32_t a3 = Ps[(gid + 8) * 36 + ks2 * 8 + tig + 4];
                int keyb = kc * 64 + (hh * 4 + ks2) * 8;
                #pragma unroll
                for (int vt = 0; vt < 4; vt++) {
                    uint32_t b0 = Vs[(keyb + tig) * 40 + vt * 8 + gid];
                    uint32_t b1 = Vs[(keyb + tig + 4) * 40 + vt * 8 + gid];
                    mma_tf32(oacc[vt][0], oacc[vt][1], oacc[vt][2], oacc[vt][3],
                             a0, a1, a2, a3, b0, b1);
                }
            }
            __syncwarp();
        }
    }

    rsum0 += __shfl_xor_sync(0xFFFFFFFFu, rsum0, 1);
    rsum0 += __shfl_xor_sync(0xFFFFFFFFu, rsum0, 2);
    rsum1 += __shfl_xor_sync(0xFFFFFFFFu, rsum1, 1);
    rsum1 += __shfl_xor_sync(0xFFFFFFFFu, rsum1, 2);
    float inv0 = 1.0f / rsum0, inv1 = 1.0f / rsum1;

    size_t r0 = (size_t)(b * 512 + i0 + gid) * 256 + h * 32;
    size_t r1 = r0 + (size_t)8 * 256;
    #pragma unroll
    for (int vt = 0; vt < 4; vt++) {
        *(__half2*)(O + r0 + vt * 8 + 2 * tig) =
            __floats2half2_rn(oacc[vt][0] * inv0, oacc[vt][1] * inv0);
        *(__half2*)(O + r1 + vt * 8 + 2 * tig) =
            __floats2half2_rn(oacc[vt][2] * inv1, oacc[vt][3] * inv1);
    }
}

// ---------------------------------------------------------------------------
__global__ void cons_reduce(const float* __restrict__ H, const float* __restrict__ cw2,
                            const float* __restrict__ cb2, float* __restrict__ out)
{
    int gw   = (blockIdx.x * blockDim.x + threadIdx.x) >> 5;
    int lane = threadIdx.x & 31;
    const float4* h4 = (const float4*)(H + (size_t)gw * 256);
    const float4* w4 = (const float4*)cw2;
    float p = 0.0f;
    #pragma unroll
    for (int u = 0; u < 2; u++) {
        int idx = u * 32 + lane;
        float4 a = h4[idx], w = w4[idx];
        p += a.x * w.x + a.y * w.y + a.z * w.z + a.w * w.w;
    }
    #pragma unroll
    for (int off = 16; off > 0; off >>= 1)
        p += __shfl_xor_sync(0xFFFFFFFFu, p, off);
    if (lane == 0)
        out[gw] = 1.0f / (1.0f + __expf(-(p + cb2[0])));
}

// ---------------------------------------------------------------------------
extern "C" void kernel_launch(void* const* d_in, const int* in_sizes, int n_in,
                              void* d_out, int out_size)
{
    const float* img   = (const float*)d_in[0];
    const float* txt   = (const float*)d_in[1];
    const int*   src   = (const int*)  d_in[2];
    const int*   dst   = (const int*)  d_in[3];
    const float* w1    = (const float*)d_in[4];
    const float* b1    = (const float*)d_in[5];
    const float* w2    = (const float*)d_in[6];
    const float* b2    = (const float*)d_in[7];
    const float* in_w  = (const float*)d_in[8];
    const float* in_b  = (const float*)d_in[9];
    const float* out_w = (const float*)d_in[10];
    const float* out_b = (const float*)d_in[11];
    const float* cw1   = (const float*)d_in[12];
    const float* cb1   = (const float*)d_in[13];
    const float* cw2   = (const float*)d_in[14];
    const float* cb2   = (const float*)d_in[15];
    float* out = (float*)d_out;

    float* S = nullptr;
    cudaGetSymbolAddress((void**)&S, g_scratch);

    uint32_t* wcat  = (uint32_t*)(S + OFF_WCAT);
    float*    bias1 = S + OFF_BIAS1;
    uint32_t* wot   = (uint32_t*)(S + OFF_WOT);
    float*    proj  = S + OFF_PROJ;
    __half*   ctx   = (__half*)(S + OFF_CTX);
    float*    qc    = S + OFF_QC;
    float*    kvc   = S + OFF_KVC;
    __half*   ctx2  = (__half*)(S + OFF_CTX2);
    __nv_bfloat16* bfab = (__nv_bfloat16*)(S + OFF_BF);
    uint32_t* intf  = (uint32_t*)(S + OFF_INT);
    __half*   attf  = (__half*)(S + OFF_ATTF);
    uint32_t* cw1t  = (uint32_t*)(S + OFF_CW1T);
    float*    Hbuf  = proj;

    float* att_img = out;
    float* att_txt = out + 2097152;
    float* cross   = out + 4194304;
    float* wimg    = out + 6291456;
    float* cons    = out + 14680064;

    const int ATTN_SMEM = 200704;
    cudaFuncSetAttribute(attn_kernel, cudaFuncAttributeMaxDynamicSharedMemorySize, ATTN_SMEM);

    const size_t PSTRIDE = (size_t)8192 * 1280;   // proj fp32 words
    const size_t CSTRIDE = (size_t)8192 * 256;    // ctx fp16 elements
    const size_t MSTRIDE = (size_t)4194304;

    // 1. prep: fp16 inputs + packed fp16 weights (one launch)
    prep_kernel<<<4997, 256>>>(img, txt, intf,
                               w1, b1, in_w, in_b, out_w, cw1,
                               wcat, bias1, wot, cw1t);

    // 2. zero both weight matrices
    cudaMemsetAsync(wimg, 0, (size_t)8388608 * 4);

    // 3. fused node projections (both modalities) -> proj fp32 + bf16 A|Bm
    gemm_f16<<<dim3(64, 10, 2), 256>>>(intf, intf + (size_t)8192 * 128, 128,
                                       wcat, 1280, 0, bias1, 0,
                                       proj, 1280, PSTRIDE, 0, bfab, nullptr);

    // 4. per-edge causal weights (one warp = both modalities)
    edge_kernel<<<32768, 256>>>(bfab, src, dst, w2, b2, wimg);

    // 5. masked self-attention, both modalities -> ctx fp16
    attn_kernel<<<dim3(2, 8, 32), 512, ATTN_SMEM>>>(
        proj, 1280, 512, PSTRIDE,
        proj, 1280, 768, PSTRIDE,
        proj, 1280, 1024, PSTRIDE,
        wimg, MSTRIDE,
        ctx, CSTRIDE);

    // 6. out-proj -> attended_* (fp32) + fp16 side-copy attf
    gemm_f16<<<dim3(128, 2, 1), 256>>>((const uint32_t*)ctx, (const uint32_t*)ctx, 128,
                                       wot, 256, 0, out_b, 0,
                                       att_img, 256, 0, 0, nullptr, attf);

    // 7. consistency: H = relu(attf @ cw1t + cb1) fp32; cons = sigmoid(H.cw2+cb2)
    gemm_f16<<<dim3(128, 2, 1), 256>>>((const uint32_t*)attf, (const uint32_t*)attf, 128,
                                       cw1t, 256, 0, cb1, 0,
                                       Hbuf, 256, 0, 1, nullptr, nullptr);
    cons_reduce<<<2048, 256>>>(Hbuf, cw2, cb2, cons);

    // 8. cross-modal: qc/kvc fp32 (attention reads fp32), ctx2 fp16
    gemm_f16<<<dim3(64, 2, 1), 256>>>((const uint32_t*)attf, (const uint32_t*)attf, 128,
                                      wcat, 1280, 512, bias1, 512,
                                      qc, 256, 0, 0, nullptr, nullptr);
    gemm_f16<<<dim3(64, 4, 1), 256>>>((const uint32_t*)(attf + (size_t)8192 * 256),
                                      (const uint32_t*)attf, 128,
                                      wcat, 1280, 768, bias1, 768,
                                      kvc, 512, 0, 0, nullptr, nullptr);
    attn_kernel<<<dim3(2, 8, 16), 512, ATTN_SMEM>>>(
        qc, 256, 0, 0,
        kvc, 512, 0, 0,
        kvc, 512, 256, 0,
        nullptr, 0,
        ctx2, 0);
    gemm_f16<<<dim3(64, 2, 1), 256>>>((const uint32_t*)ctx2, (const uint32_t*)ctx2, 128,
                                      wot, 256, 0, out_b, 0,
                                      cross, 256, 0, 0, nullptr, nullptr);
}

// round 15
// speedup vs baseline: 1.8290x; 1.2897x over previous
#include <cuda_runtime.h>
#include <cuda_bf16.h>
#include <cuda_fp16.h>
#include <cstddef>
#include <cstdint>

// Problem constants: B=16, N=512, D=256, H=8, DH=32, E=16384
// d_out layout (floats):
//   attended_img   [0,        2097152)
//   attended_text  [2097152,  4194304)
//   cross_modal    [4194304,  6291456)
//   img_weights    [6291456, 10485760)
//   text_weights   [10485760,14680064)
//   img_cons       [14680064,14688256)
//   text_cons      [14688256,14696448)

#define OFF_WCAT   0u             // fp16 k-paired [128 k2][1280]: 163840 words
#define OFF_BIAS1  327680u        // 1280 fp32 (wq bias pre-scaled)
#define OFF_WOT    328960u        // fp16 k-paired [128 k2][256]
#define OFF_PROJ   394496u        // qkvh fp16 [16384][1280]
#define OFF_HBUF   13107200u      // H fp32 16384x256 (consistency)
#define OFF_CTX    21366016u      // fp16 16384x256 (attn out)
#define OFF_QC     25560320u      // fp16 8192x256 (qch)
#define OFF_KVC    27657472u      // fp16 8192x512 (kvch)
#define OFF_CTX2   31851776u      // fp16 8192x256
#define OFF_INT    38143232u      // fp16 img|txt 16384x256
#define OFF_ATTF   46531840u      // fp16 att_img|att_txt 16384x256
#define OFF_CW1T   50726144u      // fp16 k-paired cw1
#define SCRATCH_FLOATS 50791680u

__device__ float g_scratch[SCRATCH_FLOATS];

// ---------------------------------------------------------------------------
__device__ __forceinline__ uint32_t pack_h2(float a, float b) {
    __half2 h = __floats2half2_rn(a, b);
    return *reinterpret_cast<uint32_t*>(&h);
}

// fp16 mma m16n8k16, fp32 accumulate
__device__ __forceinline__ void mma_f16(float& d0, float& d1, float& d2, float& d3,
                                        uint32_t a0, uint32_t a1, uint32_t a2, uint32_t a3,
                                        uint32_t b0, uint32_t b1)
{
    asm volatile(
        "mma.sync.aligned.m16n8k16.row.col.f32.f16.f16.f32 "
        "{%0,%1,%2,%3}, {%4,%5,%6,%7}, {%8,%9}, {%0,%1,%2,%3};"
        : "+f"(d0), "+f"(d1), "+f"(d2), "+f"(d3)
        : "r"(a0), "r"(a1), "r"(a2), "r"(a3), "r"(b0), "r"(b1));
}

__device__ __forceinline__ void cp16(uint32_t smem, const void* g) {
    asm volatile("cp.async.ca.shared.global [%0], [%1], 16;" :: "r"(smem), "l"(g));
}

// ---------------------------------------------------------------------------
// prep: blocks [0,4096): img|txt -> fp16 intf; rest: fp16 k-paired weights.
// wq columns [512,768) and their bias pre-scaled by 1/sqrt(32).
// ---------------------------------------------------------------------------
__device__ __forceinline__ float wcat_src(const float* w1, const float* in_w,
                                          int k, int c)
{
    if (c < 256)  return w1[k * 256 + c];
    if (c < 512)  return w1[(256 + k) * 256 + (c - 256)];
    if (c < 768)  return in_w[(c - 512) * 256 + k];
    if (c < 1024) return in_w[(c - 768 + 256) * 256 + k];
    return in_w[(c - 1024 + 512) * 256 + k];
}

__global__ void prep_kernel(const float* __restrict__ img, const float* __restrict__ txt,
                            uint32_t* __restrict__ intf,
                            const float* __restrict__ w1, const float* __restrict__ b1,
                            const float* __restrict__ in_w, const float* __restrict__ in_b,
                            const float* __restrict__ out_w, const float* __restrict__ cw1,
                            uint32_t* __restrict__ wcat, float* __restrict__ bias1,
                            uint32_t* __restrict__ wot, uint32_t* __restrict__ cw1t)
{
    const float qscale = 0.17677669529663687f;  // 1/sqrt(32)
    if (blockIdx.x < 4096) {
        int i = blockIdx.x * 256 + threadIdx.x;
        const float* srcp = (i < 524288) ? img : txt;
        int j = (i < 524288) ? i : i - 524288;
        float4 v0 = ((const float4*)srcp)[j * 2];
        float4 v1 = ((const float4*)srcp)[j * 2 + 1];
        uint4 u;
        u.x = pack_h2(v0.x, v0.y); u.y = pack_h2(v0.z, v0.w);
        u.z = pack_h2(v1.x, v1.y); u.w = pack_h2(v1.z, v1.w);
        ((uint4*)intf)[i] = u;
        return;
    }
    int idx = (blockIdx.x - 4096) * 256 + threadIdx.x;
    if (idx < 163840) {
        int k2 = idx / 1280, c = idx % 1280;
        float sc = (c >= 512 && c < 768) ? qscale : 1.0f;
        float v0 = wcat_src(w1, in_w, 2 * k2, c) * sc;
        float v1 = wcat_src(w1, in_w, 2 * k2 + 1, c) * sc;
        wcat[idx] = pack_h2(v0, v1);
    } else if (idx < 165120) {
        int c = idx - 163840;
        float v = (c < 256) ? b1[c] : (c < 512 ? 0.0f : in_b[c - 512]);
        if (c >= 512 && c < 768) v *= qscale;
        bias1[c] = v;
    } else if (idx < 197888) {
        int i = idx - 165120;
        int k2 = i >> 8, n = i & 255;
        float2 v = *(const float2*)(out_w + n * 256 + 2 * k2);
        wot[i] = pack_h2(v.x, v.y);
    } else if (idx < 230656) {
        int i = idx - 197888;
        int k2 = i >> 8, n = i & 255;
        cw1t[i] = pack_h2(cw1[(2 * k2) * 256 + n], cw1[(2 * k2 + 1) * 256 + n]);
    }
}

// ---------------------------------------------------------------------------
// fp16 tensor-core GEMM. C (fp32) optional; f16aux optional full-width fp16.
// ---------------------------------------------------------------------------
__global__ __launch_bounds__(256, 2)
void gemm_f16(const uint32_t* __restrict__ X0, const uint32_t* __restrict__ X1,
              int ldx,
              const uint32_t* __restrict__ W, int ldw, int woff,
              const float* __restrict__ bias, int boff,
              float* __restrict__ C, int ldc, size_t czstride, int relu,
              __half* __restrict__ f16aux, size_t auxzstride)
{
    __shared__ __align__(16) uint32_t As[2][2560];   // 128 x 20
    __shared__ __align__(16) uint32_t Bs[2][2176];   // 16 x 136

    int z = blockIdx.z;
    const uint32_t* X = z ? X1 : X0;
    float* Cz = C ? C + (size_t)z * czstride : nullptr;
    __half* Az = f16aux ? f16aux + (size_t)z * auxzstride : nullptr;

    int t = threadIdx.x;
    int lane = t & 31, w = t >> 5;
    int gid = lane >> 2, tig = lane & 3;
    int wm = w >> 2, wn = w & 3;
    int m0 = blockIdx.x * 128, n0 = blockIdx.y * 128;

    int ar[2], ac[2], br[2], bc[2];
    #pragma unroll
    for (int i = 0; i < 2; i++) {
        int lin = i * 1024 + t * 4;
        ar[i] = lin >> 4;  ac[i] = lin & 15;
        br[i] = lin >> 7;  bc[i] = lin & 127;
    }

    float acc[4][4][4];
    #pragma unroll
    for (int mi = 0; mi < 4; mi++)
        #pragma unroll
        for (int ni = 0; ni < 4; ni++)
            #pragma unroll
            for (int q = 0; q < 4; q++) acc[mi][ni][q] = 0.0f;

    #pragma unroll
    for (int i = 0; i < 2; i++) {
        cp16((uint32_t)__cvta_generic_to_shared(&As[0][ar[i] * 20 + ac[i]]),
             X + (size_t)(m0 + ar[i]) * ldx + ac[i]);
        cp16((uint32_t)__cvta_generic_to_shared(&Bs[0][br[i] * 136 + bc[i]]),
             W + (size_t)br[i] * ldw + woff + n0 + bc[i]);
    }
    asm volatile("cp.async.commit_group;");

    for (int ch = 0; ch < 8; ch++) {
        if (ch < 7) {
            int k0w = (ch + 1) * 16;
            int buf = (ch + 1) & 1;
            #pragma unroll
            for (int i = 0; i < 2; i++) {
                cp16((uint32_t)__cvta_generic_to_shared(&As[buf][ar[i] * 20 + ac[i]]),
                     X + (size_t)(m0 + ar[i]) * ldx + k0w + ac[i]);
                cp16((uint32_t)__cvta_generic_to_shared(&Bs[buf][br[i] * 136 + bc[i]]),
                     W + (size_t)(k0w + br[i]) * ldw + woff + n0 + bc[i]);
            }
            asm volatile("cp.async.commit_group;");
            asm volatile("cp.async.wait_group 1;");
        } else {
            asm volatile("cp.async.wait_group 0;");
        }
        __syncthreads();

        const uint32_t* A = As[ch & 1];
        const uint32_t* B = Bs[ch & 1];

        #pragma unroll
        for (int ks = 0; ks < 2; ks++) {
            int kk = ks * 8;
            uint32_t a[4][4], b[4][2];
            #pragma unroll
            for (int mi = 0; mi < 4; mi++) {
                int rb = wm * 64 + mi * 16 + gid;
                a[mi][0] = A[rb * 20 + kk + tig];
                a[mi][1] = A[(rb + 8) * 20 + kk + tig];
                a[mi][2] = A[rb * 20 + kk + tig + 4];
                a[mi][3] = A[(rb + 8) * 20 + kk + tig + 4];
            }
            #pragma unroll
            for (int ni = 0; ni < 4; ni++) {
                int cb = wn * 32 + ni * 8 + gid;
                b[ni][0] = B[(kk + tig) * 136 + cb];
                b[ni][1] = B[(kk + tig + 4) * 136 + cb];
            }
            #pragma unroll
            for (int mi = 0; mi < 4; mi++)
                #pragma unroll
                for (int ni = 0; ni < 4; ni++)
                    mma_f16(acc[mi][ni][0], acc[mi][ni][1], acc[mi][ni][2], acc[mi][ni][3],
                            a[mi][0], a[mi][1], a[mi][2], a[mi][3],
                            b[ni][0], b[ni][1]);
        }
        __syncthreads();
    }

    #pragma unroll
    for (int mi = 0; mi < 4; mi++) {
        int r0 = m0 + wm * 64 + mi * 16 + gid;
        #pragma unroll
        for (int ni = 0; ni < 4; ni++) {
            int col = n0 + wn * 32 + ni * 8 + 2 * tig;
            float bb0 = bias ? bias[boff + col]     : 0.0f;
            float bb1 = bias ? bias[boff + col + 1] : 0.0f;
            float2 v0, v1;
            v0.x = acc[mi][ni][0] + bb0; v0.y = acc[mi][ni][1] + bb1;
            v1.x = acc[mi][ni][2] + bb0; v1.y = acc[mi][ni][3] + bb1;
            if (relu) {
                v0.x = fmaxf(v0.x, 0.0f); v0.y = fmaxf(v0.y, 0.0f);
                v1.x = fmaxf(v1.x, 0.0f); v1.y = fmaxf(v1.y, 0.0f);
            }
            if (Cz) {
                *(float2*)(Cz + (size_t)r0 * ldc + col)       = v0;
                *(float2*)(Cz + (size_t)(r0 + 8) * ldc + col) = v1;
            }
            if (Az) {
                *(__half2*)(Az + (size_t)r0 * ldc + col)       = __floats2half2_rn(v0.x, v0.y);
                *(__half2*)(Az + (size_t)(r0 + 8) * ldc + col) = __floats2half2_rn(v1.x, v1.y);
            }
        }
    }
}

// ---------------------------------------------------------------------------
// Edge scatter: one warp per (batch, edge), both modalities. fp16 SIMD.
// ---------------------------------------------------------------------------
__device__ __forceinline__ float dot8_h(uint4 av, uint4 bv,
                                        float4 wlo, float4 whi)
{
    const __half2* a2 = reinterpret_cast<const __half2*>(&av);
    const __half2* b2 = reinterpret_cast<const __half2*>(&bv);
    __half2 z2 = __floats2half2_rn(0.0f, 0.0f);
    float2 f0 = __half22float2(__hmax2(__hadd2(a2[0], b2[0]), z2));
    float2 f1 = __half22float2(__hmax2(__hadd2(a2[1], b2[1]), z2));
    float2 f2 = __half22float2(__hmax2(__hadd2(a2[2], b2[2]), z2));
    float2 f3 = __half22float2(__hmax2(__hadd2(a2[3], b2[3]), z2));
    float p = f0.x * wlo.x + f0.y * wlo.y;
    p += f1.x * wlo.z + f1.y * wlo.w;
    p += f2.x * whi.x + f2.y * whi.y;
    p += f3.x * whi.z + f3.y * whi.w;
    return p;
}

__global__ void edge_kernel(const __half* __restrict__ qkvh,
                            const int* __restrict__ src, const int* __restrict__ dst,
                            const float* __restrict__ w2, const float* __restrict__ b2p,
                            float* __restrict__ wout)
{
    int gw   = (blockIdx.x * blockDim.x + threadIdx.x) >> 5;
    int lane = threadIdx.x & 31;
    int e = gw & 16383;
    int b = gw >> 14;
    int s = src[e], d = dst[e];

    const size_t rowA = ((size_t)b * 512 + s) * 1280;
    const size_t rowB = ((size_t)b * 512 + d) * 1280 + 256;
    const size_t MOFF = (size_t)8192 * 1280;

    uint4 avi = *(const uint4*)(qkvh + rowA + lane * 8);
    uint4 bvi = *(const uint4*)(qkvh + rowB + lane * 8);
    uint4 avt = *(const uint4*)(qkvh + MOFF + rowA + lane * 8);
    uint4 bvt = *(const uint4*)(qkvh + MOFF + rowB + lane * 8);
    float4 wlo = *(const float4*)(w2 + lane * 8);
    float4 whi = *(const float4*)(w2 + lane * 8 + 4);

    float pi = dot8_h(avi, bvi, wlo, whi);
    float pt = dot8_h(avt, bvt, wlo, whi);

    #pragma unroll
    for (int off = 16; off > 0; off >>= 1) {
        pi += __shfl_xor_sync(0xFFFFFFFFu, pi, off);
        pt += __shfl_xor_sync(0xFFFFFFFFu, pt, off);
    }
    if (lane == 0) {
        float bb = b2p[0];
        size_t base = (size_t)b * 262144 + (size_t)s * 512 + d;
        wout[base]           = 1.0f / (1.0f + __expf(-(pi + bb)));
        wout[base + 4194304] = 1.0f / (1.0f + __expf(-(pt + bb)));
    }
}

// ---------------------------------------------------------------------------
// FP16 tensor-core attention. 512 threads / 16 warps (256 query rows).
// K via cp.async [512][20]w; V transposed [32][260]w via byte_perm;
// P fp16 [16][20]w per warp (stride 20 = conflict-free, 16 data words/row).
// Smem 94720 B dynamic.
// ---------------------------------------------------------------------------
__global__ __launch_bounds__(512, 1)
void attn_f16(const __half* __restrict__ qbuf, int qld, size_t qzs,
              const __half* __restrict__ kbuf, int kld, size_t kzs,
              const __half* __restrict__ vbuf, int vld, size_t vzs,
              const float* __restrict__ mask, size_t mzs,
              __half* __restrict__ ctx, size_t czs)
{
    extern __shared__ uint32_t sm[];
    uint32_t* Ks = sm;               // [512 key][20]w (16 data + 4 pad)
    uint32_t* Vt = sm + 10240;       // [32 d][260]w (256 keypair words + 4 pad)
    uint32_t* Pw = sm + 18560;       // 16 warps x [16 row][20]w

    int zb = blockIdx.z;
    int b = zb & 15, mz = zb >> 4;
    int h = blockIdx.y, chunk = blockIdx.x;
    int t = threadIdx.x, lane = t & 31, w = t >> 5;
    int gid = lane >> 2, tig = lane & 3;

    const __half* Qp = qbuf + (size_t)mz * qzs + h * 32;
    const __half* Kp = kbuf + (size_t)mz * kzs + (size_t)(b * 512) * kld + h * 32;
    const __half* Vp = vbuf + (size_t)mz * vzs + (size_t)(b * 512) * vld + h * 32;
    const float*  M  = mask ? mask + (size_t)mz * mzs + (size_t)b * 262144 : nullptr;
    __half* O = ctx + (size_t)mz * czs;

    uint32_t* Ps = Pw + w * 320;
    int i0 = chunk * 256 + w * 16;

    // K staging via cp.async (fp16, no cvt): 2048 16B chunks
    for (int i = t; i < 2048; i += 512) {
        int key = i >> 2, c = i & 3;
        cp16((uint32_t)__cvta_generic_to_shared(&Ks[key * 20 + c * 4]),
             Kp + (size_t)key * kld + c * 8);
    }
    asm volatile("cp.async.commit_group;");

    // V transpose staging: 1024 tasks (256 keypairs x 4 d-chunks)
    for (int id = t; id < 1024; id += 512) {
        int j2 = id & 255, c = id >> 8;
        uint4 A  = *(const uint4*)(Vp + (size_t)(2 * j2) * vld + c * 8);
        uint4 Bv = *(const uint4*)(Vp + (size_t)(2 * j2 + 1) * vld + c * 8);
        uint32_t* vt = Vt + (c * 8) * 260 + j2;
        vt[0 * 260] = __byte_perm(A.x, Bv.x, 0x5410);
        vt[1 * 260] = __byte_perm(A.x, Bv.x, 0x7632);
        vt[2 * 260] = __byte_perm(A.y, Bv.y, 0x5410);
        vt[3 * 260] = __byte_perm(A.y, Bv.y, 0x7632);
        vt[4 * 260] = __byte_perm(A.z, Bv.z, 0x5410);
        vt[5 * 260] = __byte_perm(A.z, Bv.z, 0x7632);
        vt[6 * 260] = __byte_perm(A.w, Bv.w, 0x5410);
        vt[7 * 260] = __byte_perm(A.w, Bv.w, 0x7632);
    }

    // Q fragments (fp16, pre-scaled): rows i0+gid, i0+gid+8
    uint32_t qa[2][4];
    {
        const uint32_t* q0 = (const uint32_t*)(Qp + (size_t)(b * 512 + i0 + gid) * qld);
        const uint32_t* q1 = (const uint32_t*)(Qp + (size_t)(b * 512 + i0 + gid + 8) * qld);
        #pragma unroll
        for (int ks = 0; ks < 2; ks++) {
            qa[ks][0] = q0[ks * 8 + tig];
            qa[ks][1] = q1[ks * 8 + tig];
            qa[ks][2] = q0[ks * 8 + tig + 4];
            qa[ks][3] = q1[ks * 8 + tig + 4];
        }
    }

    const float* mrow0 = M ? M + (size_t)(i0 + gid) * 512 : nullptr;
    const float* mrow1 = mrow0 ? mrow0 + 8 * 512 : nullptr;

    float2 mv0[8], mv1[8];
    if (mrow0) {
        #pragma unroll
        for (int nt = 0; nt < 8; nt++) {
            int col = nt * 8 + 2 * tig;
            mv0[nt] = *(const float2*)(mrow0 + col);
            mv1[nt] = *(const float2*)(mrow1 + col);
        }
    }

    asm volatile("cp.async.wait_group 0;");
    __syncthreads();

    float oacc[4][4];
    #pragma unroll
    for (int vt = 0; vt < 4; vt++)
        #pragma unroll
        for (int q = 0; q < 4; q++) oacc[vt][q] = 0.0f;
    float rsum0 = 0.0f, rsum1 = 0.0f;

    for (int kc = 0; kc < 8; kc++) {
        float sacc[8][4];
        #pragma unroll
        for (int nt = 0; nt < 8; nt++)
            #pragma unroll
            for (int q = 0; q < 4; q++) sacc[nt][q] = 0.0f;

        // S = Q K^T (fp16): 2 ksteps x 8 nt
        #pragma unroll
        for (int ks = 0; ks < 2; ks++) {
            #pragma unroll
            for (int nt = 0; nt < 8; nt++) {
                int key = kc * 64 + nt * 8 + gid;
                uint32_t b0 = Ks[key * 20 + ks * 8 + tig];
                uint32_t b1 = Ks[key * 20 + ks * 8 + tig + 4];
                mma_f16(sacc[nt][0], sacc[nt][1], sacc[nt][2], sacc[nt][3],
                        qa[ks][0], qa[ks][1], qa[ks][2], qa[ks][3], b0, b1);
            }
        }

        // two 32-key halves: exp + P(fp16, stride 20) store + PV(fp16)
        #pragma unroll
        for (int hh = 0; hh < 2; hh++) {
            #pragma unroll
            for (int nt2 = 0; nt2 < 4; nt2++) {
                int nt = hh * 4 + nt2;
                float s0 = sacc[nt][0], s1 = sacc[nt][1];
                float s2 = sacc[nt][2], s3 = sacc[nt][3];
                if (mrow0) {
                    s0 += mv0[nt].x; s1 += mv0[nt].y;
                    s2 += mv1[nt].x; s3 += mv1[nt].y;
                }
                float p0 = __expf(s0), p1 = __expf(s1);
                float p2 = __expf(s2), p3 = __expf(s3);
                rsum0 += p0 + p1;
                rsum1 += p2 + p3;
                Ps[gid * 20 + nt2 * 4 + tig]       = pack_h2(p0, p1);
                Ps[(gid + 8) * 20 + nt2 * 4 + tig] = pack_h2(p2, p3);
            }
            if (hh == 1 && mrow0 && kc < 7) {
                #pragma unroll
                for (int nt = 0; nt < 8; nt++) {
                    int col = (kc + 1) * 64 + nt * 8 + 2 * tig;
                    mv0[nt] = *(const float2*)(mrow0 + col);
                    mv1[nt] = *(const float2*)(mrow1 + col);
                }
            }
            __syncwarp();

            // O += P V : 2 ksteps (16 keys each) x 4 d-tiles
            int kb2base = kc * 32 + hh * 16;   // keypair-word base
            #pragma unroll
            for (int s = 0; s < 2; s++) {
                uint32_t a0 = Ps[gid * 20 + s * 8 + tig];
                uint32_t a1 = Ps[(gid + 8) * 20 + s * 8 + tig];
                uint32_t a2 = Ps[gid * 20 + s * 8 + tig + 4];
                uint32_t a3 = Ps[(gid + 8) * 20 + s * 8 + tig + 4];
                int kb2 = kb2base + s * 8;
                #pragma unroll
                for (int vt = 0; vt < 4; vt++) {
                    int d = vt * 8 + gid;
                    uint32_t b0 = Vt[d * 260 + kb2 + tig];
                    uint32_t b1 = Vt[d * 260 + kb2 + tig + 4];
                    mma_f16(oacc[vt][0], oacc[vt][1], oacc[vt][2], oacc[vt][3],
                            a0, a1, a2, a3, b0, b1);
                }
            }
            __syncwarp();
        }
    }

    rsum0 += __shfl_xor_sync(0xFFFFFFFFu, rsum0, 1);
    rsum0 += __shfl_xor_sync(0xFFFFFFFFu, rsum0, 2);
    rsum1 += __shfl_xor_sync(0xFFFFFFFFu, rsum1, 1);
    rsum1 += __shfl_xor_sync(0xFFFFFFFFu, rsum1, 2);
    float inv0 = 1.0f / rsum0, inv1 = 1.0f / rsum1;

    size_t r0 = (size_t)(b * 512 + i0 + gid) * 256 + h * 32;
    size_t r1 = r0 + (size_t)8 * 256;
    #pragma unroll
    for (int vt = 0; vt < 4; vt++) {
        *(__half2*)(O + r0 + vt * 8 + 2 * tig) =
            __floats2half2_rn(oacc[vt][0] * inv0, oacc[vt][1] * inv0);
        *(__half2*)(O + r1 + vt * 8 + 2 * tig) =
            __floats2half2_rn(oacc[vt][2] * inv1, oacc[vt][3] * inv1);
    }
}

// ---------------------------------------------------------------------------
__global__ void cons_reduce(const float* __restrict__ H, const float* __restrict__ cw2,
                            const float* __restrict__ cb2, float* __restrict__ out)
{
    int gw   = (blockIdx.x * blockDim.x + threadIdx.x) >> 5;
    int lane = threadIdx.x & 31;
    const float4* h4 = (const float4*)(H + (size_t)gw * 256);
    const float4* w4 = (const float4*)cw2;
    float p = 0.0f;
    #pragma unroll
    for (int u = 0; u < 2; u++) {
        int idx = u * 32 + lane;
        float4 a = h4[idx], w = w4[idx];
        p += a.x * w.x + a.y * w.y + a.z * w.z + a.w * w.w;
    }
    #pragma unroll
    for (int off = 16; off > 0; off >>= 1)
        p += __shfl_xor_sync(0xFFFFFFFFu, p, off);
    if (lane == 0)
        out[gw] = 1.0f / (1.0f + __expf(-(p + cb2[0])));
}

// ---------------------------------------------------------------------------
extern "C" void kernel_launch(void* const* d_in, const int* in_sizes, int n_in,
                              void* d_out, int out_size)
{
    const float* img   = (const float*)d_in[0];
    const float* txt   = (const float*)d_in[1];
    const int*   src   = (const int*)  d_in[2];
    const int*   dst   = (const int*)  d_in[3];
    const float* w1    = (const float*)d_in[4];
    const float* b1    = (const float*)d_in[5];
    const float* w2    = (const float*)d_in[6];
    const float* b2    = (const float*)d_in[7];
    const float* in_w  = (const float*)d_in[8];
    const float* in_b  = (const float*)d_in[9];
    const float* out_w = (const float*)d_in[10];
    const float* out_b = (const float*)d_in[11];
    const float* cw1   = (const float*)d_in[12];
    const float* cb1   = (const float*)d_in[13];
    const float* cw2   = (const float*)d_in[14];
    const float* cb2   = (const float*)d_in[15];
    float* out = (float*)d_out;

    float* S = nullptr;
    cudaGetSymbolAddress((void**)&S, g_scratch);

    uint32_t* wcat  = (uint32_t*)(S + OFF_WCAT);
    float*    bias1 = S + OFF_BIAS1;
    uint32_t* wot   = (uint32_t*)(S + OFF_WOT);
    __half*   qkvh  = (__half*)(S + OFF_PROJ);     // [2*8192][1280]
    float*    Hbuf  = S + OFF_HBUF;
    __half*   ctx   = (__half*)(S + OFF_CTX);
    __half*   qch   = (__half*)(S + OFF_QC);
    __half*   kvch  = (__half*)(S + OFF_KVC);
    __half*   ctx2  = (__half*)(S + OFF_CTX2);
    uint32_t* intf  = (uint32_t*)(S + OFF_INT);
    __half*   attf  = (__half*)(S + OFF_ATTF);
    uint32_t* cw1t  = (uint32_t*)(S + OFF_CW1T);

    float* att_img = out;
    float* att_txt = out + 2097152;
    float* cross   = out + 4194304;
    float* wimg    = out + 6291456;
    float* cons    = out + 14680064;

    const int ATTN_SMEM = 94720;
    cudaFuncSetAttribute(attn_f16, cudaFuncAttributeMaxDynamicSharedMemorySize, ATTN_SMEM);

    const size_t QKVZS = (size_t)8192 * 1280;   // qkvh per-modality (halfs)
    const size_t CSTRIDE = (size_t)8192 * 256;  // ctx per-modality (halfs)
    const size_t MSTRIDE = (size_t)4194304;

    // 1. prep (wq/bq pre-scaled by 1/sqrt(32))
    prep_kernel<<<4997, 256>>>(img, txt, intf,
                               w1, b1, in_w, in_b, out_w, cw1,
                               wcat, bias1, wot, cw1t);

    // 2. zero both weight matrices
    cudaMemsetAsync(wimg, 0, (size_t)8388608 * 4);

    // 3. projections -> qkvh fp16 only (no fp32 C)
    gemm_f16<<<dim3(64, 10, 2), 256>>>(intf, intf + (size_t)8192 * 128, 128,
                                       wcat, 1280, 0, bias1, 0,
                                       nullptr, 1280, 0, 0, qkvh, QKVZS);

    // 4. per-edge causal weights (fp16 reads)
    edge_kernel<<<32768, 256>>>(qkvh, src, dst, w2, b2, wimg);

    // 5. masked self-attention (fp16), both modalities
    attn_f16<<<dim3(2, 8, 32), 512, ATTN_SMEM>>>(
        qkvh + 512, 1280, QKVZS,
        qkvh + 768, 1280, QKVZS,
        qkvh + 1024, 1280, QKVZS,
        wimg, MSTRIDE,
        ctx, CSTRIDE);

    // 6. out-proj -> attended_* (fp32) + fp16 attf
    gemm_f16<<<dim3(128, 2, 1), 256>>>((const uint32_t*)ctx, (const uint32_t*)ctx, 128,
                                       wot, 256, 0, out_b, 0,
                                       att_img, 256, 0, 0, attf, 0);

    // 7. consistency
    gemm_f16<<<dim3(128, 2, 1), 256>>>((const uint32_t*)attf, (const uint32_t*)attf, 128,
                                       cw1t, 256, 0, cb1, 0,
                                       Hbuf, 256, 0, 1, nullptr, 0);
    cons_reduce<<<2048, 256>>>(Hbuf, cw2, cb2, cons);

    // 8. cross-modal: qch (pre-scaled via wcat) + kvch, both fp16 only
    gemm_f16<<<dim3(64, 2, 1), 256>>>((const uint32_t*)attf, (const uint32_t*)attf, 128,
                                      wcat, 1280, 512, bias1, 512,
                                      nullptr, 256, 0, 0, qch, 0);
    gemm_f16<<<dim3(64, 4, 1), 256>>>((const uint32_t*)(attf + (size_t)8192 * 256),
                                      (const uint32_t*)attf, 128,
                                      wcat, 1280, 768, bias1, 768,
                                      nullptr, 512, 0, 0, kvch, 0);
    attn_f16<<<dim3(2, 8, 16), 512, ATTN_SMEM>>>(
        qch, 256, 0,
        kvch, 512, 0,
        kvch + 256, 512, 0,
        nullptr, 0,
        ctx2, 0);
    gemm_f16<<<dim3(64, 2, 1), 256>>>((const uint32_t*)ctx2, (const uint32_t*)ctx2, 128,
                                      wot, 256, 0, out_b, 0,
                                      cross, 256, 0, 0, nullptr, 0);
}

// round 16
// speedup vs baseline: 1.8305x; 1.0008x over previous
#include <cuda_runtime.h>
#include <cuda_bf16.h>
#include <cuda_fp16.h>
#include <cstddef>
#include <cstdint>

// Problem constants: B=16, N=512, D=256, H=8, DH=32, E=16384
// d_out layout (floats):
//   attended_img   [0,        2097152)
//   attended_text  [2097152,  4194304)
//   cross_modal    [4194304,  6291456)
//   img_weights    [6291456, 10485760)
//   text_weights   [10485760,14680064)
//   img_cons       [14680064,14688256)
//   text_cons      [14688256,14696448)

#define OFF_WCAT   0u             // fp16 k-paired [128 k2][1280]
#define OFF_BIAS1  327680u        // 1280 fp32 (wq bias pre-scaled)
#define OFF_WOT    328960u        // fp16 k-paired [128 k2][256]
#define OFF_PROJ   394496u        // qkvh fp16 [16384][1280]
#define OFF_HBUF   13107200u      // H fp32 16384x256 (consistency)
#define OFF_CTX    21366016u      // fp16 16384x256 (attn out)
#define OFF_QC     25560320u      // fp16 8192x256 (qch)
#define OFF_KVC    27657472u      // fp16 8192x512 (kvch)
#define OFF_CTX2   31851776u      // fp16 8192x256
#define OFF_INT    38143232u      // fp16 img|txt 16384x256
#define OFF_ATTF   46531840u      // fp16 att_img|att_txt 16384x256
#define OFF_CW1T   50726144u      // fp16 k-paired cw1
#define SCRATCH_FLOATS 50791680u

__device__ float g_scratch[SCRATCH_FLOATS];

// ---------------------------------------------------------------------------
__device__ __forceinline__ uint32_t pack_h2(float a, float b) {
    __half2 h = __floats2half2_rn(a, b);
    return *reinterpret_cast<uint32_t*>(&h);
}

__device__ __forceinline__ uint32_t h2exp2u(uint32_t x) {
    uint32_t r;
    asm("ex2.approx.f16x2 %0, %1;" : "=r"(r) : "r"(x));
    return r;
}

// fp16 mma m16n8k16, fp32 accumulate
__device__ __forceinline__ void mma_f16(float& d0, float& d1, float& d2, float& d3,
                                        uint32_t a0, uint32_t a1, uint32_t a2, uint32_t a3,
                                        uint32_t b0, uint32_t b1)
{
    asm volatile(
        "mma.sync.aligned.m16n8k16.row.col.f32.f16.f16.f32 "
        "{%0,%1,%2,%3}, {%4,%5,%6,%7}, {%8,%9}, {%0,%1,%2,%3};"
        : "+f"(d0), "+f"(d1), "+f"(d2), "+f"(d3)
        : "r"(a0), "r"(a1), "r"(a2), "r"(a3), "r"(b0), "r"(b1));
}

__device__ __forceinline__ void cp16(uint32_t smem, const void* g) {
    asm volatile("cp.async.ca.shared.global [%0], [%1], 16;" :: "r"(smem), "l"(g));
}

// ---------------------------------------------------------------------------
// prep: blocks [0,4096): img|txt -> fp16 intf; rest: fp16 k-paired weights.
// wq columns [512,768) and their bias pre-scaled by 1/sqrt(32).
// ---------------------------------------------------------------------------
__device__ __forceinline__ float wcat_src(const float* w1, const float* in_w,
                                          int k, int c)
{
    if (c < 256)  return w1[k * 256 + c];
    if (c < 512)  return w1[(256 + k) * 256 + (c - 256)];
    if (c < 768)  return in_w[(c - 512) * 256 + k];
    if (c < 1024) return in_w[(c - 768 + 256) * 256 + k];
    return in_w[(c - 1024 + 512) * 256 + k];
}

__global__ void prep_kernel(const float* __restrict__ img, const float* __restrict__ txt,
                            uint32_t* __restrict__ intf,
                            const float* __restrict__ w1, const float* __restrict__ b1,
                            const float* __restrict__ in_w, const float* __restrict__ in_b,
                            const float* __restrict__ out_w, const float* __restrict__ cw1,
                            uint32_t* __restrict__ wcat, float* __restrict__ bias1,
                            uint32_t* __restrict__ wot, uint32_t* __restrict__ cw1t)
{
    const float qscale = 0.17677669529663687f;  // 1/sqrt(32)
    if (blockIdx.x < 4096) {
        int i = blockIdx.x * 256 + threadIdx.x;
        const float* srcp = (i < 524288) ? img : txt;
        int j = (i < 524288) ? i : i - 524288;
        float4 v0 = ((const float4*)srcp)[j * 2];
        float4 v1 = ((const float4*)srcp)[j * 2 + 1];
        uint4 u;
        u.x = pack_h2(v0.x, v0.y); u.y = pack_h2(v0.z, v0.w);
        u.z = pack_h2(v1.x, v1.y); u.w = pack_h2(v1.z, v1.w);
        ((uint4*)intf)[i] = u;
        return;
    }
    int idx = (blockIdx.x - 4096) * 256 + threadIdx.x;
    if (idx < 163840) {
        int k2 = idx / 1280, c = idx % 1280;
        float sc = (c >= 512 && c < 768) ? qscale : 1.0f;
        float v0 = wcat_src(w1, in_w, 2 * k2, c) * sc;
        float v1 = wcat_src(w1, in_w, 2 * k2 + 1, c) * sc;
        wcat[idx] = pack_h2(v0, v1);
    } else if (idx < 165120) {
        int c = idx - 163840;
        float v = (c < 256) ? b1[c] : (c < 512 ? 0.0f : in_b[c - 512]);
        if (c >= 512 && c < 768) v *= qscale;
        bias1[c] = v;
    } else if (idx < 197888) {
        int i = idx - 165120;
        int k2 = i >> 8, n = i & 255;
        float2 v = *(const float2*)(out_w + n * 256 + 2 * k2);
        wot[i] = pack_h2(v.x, v.y);
    } else if (idx < 230656) {
        int i = idx - 197888;
        int k2 = i >> 8, n = i & 255;
        cw1t[i] = pack_h2(cw1[(2 * k2) * 256 + n], cw1[(2 * k2 + 1) * 256 + n]);
    }
}

// ---------------------------------------------------------------------------
// fp16 tensor-core GEMM. C (fp32) optional; f16aux optional full-width fp16.
// ---------------------------------------------------------------------------
__global__ __launch_bounds__(256, 2)
void gemm_f16(const uint32_t* __restrict__ X0, const uint32_t* __restrict__ X1,
              int ldx,
              const uint32_t* __restrict__ W, int ldw, int woff,
              const float* __restrict__ bias, int boff,
              float* __restrict__ C, int ldc, size_t czstride, int relu,
              __half* __restrict__ f16aux, size_t auxzstride)
{
    __shared__ __align__(16) uint32_t As[2][2560];   // 128 x 20
    __shared__ __align__(16) uint32_t Bs[2][2176];   // 16 x 136

    int z = blockIdx.z;
    const uint32_t* X = z ? X1 : X0;
    float* Cz = C ? C + (size_t)z * czstride : nullptr;
    __half* Az = f16aux ? f16aux + (size_t)z * auxzstride : nullptr;

    int t = threadIdx.x;
    int lane = t & 31, w = t >> 5;
    int gid = lane >> 2, tig = lane & 3;
    int wm = w >> 2, wn = w & 3;
    int m0 = blockIdx.x * 128, n0 = blockIdx.y * 128;

    int ar[2], ac[2], br[2], bc[2];
    #pragma unroll
    for (int i = 0; i < 2; i++) {
        int lin = i * 1024 + t * 4;
        ar[i] = lin >> 4;  ac[i] = lin & 15;
        br[i] = lin >> 7;  bc[i] = lin & 127;
    }

    float acc[4][4][4];
    #pragma unroll
    for (int mi = 0; mi < 4; mi++)
        #pragma unroll
        for (int ni = 0; ni < 4; ni++)
            #pragma unroll
            for (int q = 0; q < 4; q++) acc[mi][ni][q] = 0.0f;

    #pragma unroll
    for (int i = 0; i < 2; i++) {
        cp16((uint32_t)__cvta_generic_to_shared(&As[0][ar[i] * 20 + ac[i]]),
             X + (size_t)(m0 + ar[i]) * ldx + ac[i]);
        cp16((uint32_t)__cvta_generic_to_shared(&Bs[0][br[i] * 136 + bc[i]]),
             W + (size_t)br[i] * ldw + woff + n0 + bc[i]);
    }
    asm volatile("cp.async.commit_group;");

    for (int ch = 0; ch < 8; ch++) {
        if (ch < 7) {
            int k0w = (ch + 1) * 16;
            int buf = (ch + 1) & 1;
            #pragma unroll
            for (int i = 0; i < 2; i++) {
                cp16((uint32_t)__cvta_generic_to_shared(&As[buf][ar[i] * 20 + ac[i]]),
                     X + (size_t)(m0 + ar[i]) * ldx + k0w + ac[i]);
                cp16((uint32_t)__cvta_generic_to_shared(&Bs[buf][br[i] * 136 + bc[i]]),
                     W + (size_t)(k0w + br[i]) * ldw + woff + n0 + bc[i]);
            }
            asm volatile("cp.async.commit_group;");
            asm volatile("cp.async.wait_group 1;");
        } else {
            asm volatile("cp.async.wait_group 0;");
        }
        __syncthreads();

        const uint32_t* A = As[ch & 1];
        const uint32_t* B = Bs[ch & 1];

        #pragma unroll
        for (int ks = 0; ks < 2; ks++) {
            int kk = ks * 8;
            uint32_t a[4][4], b[4][2];
            #pragma unroll
            for (int mi = 0; mi < 4; mi++) {
                int rb = wm * 64 + mi * 16 + gid;
                a[mi][0] = A[rb * 20 + kk + tig];
                a[mi][1] = A[(rb + 8) * 20 + kk + tig];
                a[mi][2] = A[rb * 20 + kk + tig + 4];
                a[mi][3] = A[(rb + 8) * 20 + kk + tig + 4];
            }
            #pragma unroll
            for (int ni = 0; ni < 4; ni++) {
                int cb = wn * 32 + ni * 8 + gid;
                b[ni][0] = B[(kk + tig) * 136 + cb];
                b[ni][1] = B[(kk + tig + 4) * 136 + cb];
            }
            #pragma unroll
            for (int mi = 0; mi < 4; mi++)
                #pragma unroll
                for (int ni = 0; ni < 4; ni++)
                    mma_f16(acc[mi][ni][0], acc[mi][ni][1], acc[mi][ni][2], acc[mi][ni][3],
                            a[mi][0], a[mi][1], a[mi][2], a[mi][3],
                            b[ni][0], b[ni][1]);
        }
        __syncthreads();
    }

    #pragma unroll
    for (int mi = 0; mi < 4; mi++) {
        int r0 = m0 + wm * 64 + mi * 16 + gid;
        #pragma unroll
        for (int ni = 0; ni < 4; ni++) {
            int col = n0 + wn * 32 + ni * 8 + 2 * tig;
            float bb0 = bias ? bias[boff + col]     : 0.0f;
            float bb1 = bias ? bias[boff + col + 1] : 0.0f;
            float2 v0, v1;
            v0.x = acc[mi][ni][0] + bb0; v0.y = acc[mi][ni][1] + bb1;
            v1.x = acc[mi][ni][2] + bb0; v1.y = acc[mi][ni][3] + bb1;
            if (relu) {
                v0.x = fmaxf(v0.x, 0.0f); v0.y = fmaxf(v0.y, 0.0f);
                v1.x = fmaxf(v1.x, 0.0f); v1.y = fmaxf(v1.y, 0.0f);
            }
            if (Cz) {
                *(float2*)(Cz + (size_t)r0 * ldc + col)       = v0;
                *(float2*)(Cz + (size_t)(r0 + 8) * ldc + col) = v1;
            }
            if (Az) {
                *(__half2*)(Az + (size_t)r0 * ldc + col)       = __floats2half2_rn(v0.x, v0.y);
                *(__half2*)(Az + (size_t)(r0 + 8) * ldc + col) = __floats2half2_rn(v1.x, v1.y);
            }
        }
    }
}

// ---------------------------------------------------------------------------
// Edge scatter: one warp per (batch, edge), both modalities. fp16 SIMD.
// ---------------------------------------------------------------------------
__device__ __forceinline__ float dot8_h(uint4 av, uint4 bv,
                                        float4 wlo, float4 whi)
{
    const __half2* a2 = reinterpret_cast<const __half2*>(&av);
    const __half2* b2 = reinterpret_cast<const __half2*>(&bv);
    __half2 z2 = __floats2half2_rn(0.0f, 0.0f);
    float2 f0 = __half22float2(__hmax2(__hadd2(a2[0], b2[0]), z2));
    float2 f1 = __half22float2(__hmax2(__hadd2(a2[1], b2[1]), z2));
    float2 f2 = __half22float2(__hmax2(__hadd2(a2[2], b2[2]), z2));
    float2 f3 = __half22float2(__hmax2(__hadd2(a2[3], b2[3]), z2));
    float p = f0.x * wlo.x + f0.y * wlo.y;
    p += f1.x * wlo.z + f1.y * wlo.w;
    p += f2.x * whi.x + f2.y * whi.y;
    p += f3.x * whi.z + f3.y * whi.w;
    return p;
}

__global__ void edge_kernel(const __half* __restrict__ qkvh,
                            const int* __restrict__ src, const int* __restrict__ dst,
                            const float* __restrict__ w2, const float* __restrict__ b2p,
                            float* __restrict__ wout)
{
    int gw   = (blockIdx.x * blockDim.x + threadIdx.x) >> 5;
    int lane = threadIdx.x & 31;
    int e = gw & 16383;
    int b = gw >> 14;
    int s = src[e], d = dst[e];

    const size_t rowA = ((size_t)b * 512 + s) * 1280;
    const size_t rowB = ((size_t)b * 512 + d) * 1280 + 256;
    const size_t MOFF = (size_t)8192 * 1280;

    uint4 avi = *(const uint4*)(qkvh + rowA + lane * 8);
    uint4 bvi = *(const uint4*)(qkvh + rowB + lane * 8);
    uint4 avt = *(const uint4*)(qkvh + MOFF + rowA + lane * 8);
    uint4 bvt = *(const uint4*)(qkvh + MOFF + rowB + lane * 8);
    float4 wlo = *(const float4*)(w2 + lane * 8);
    float4 whi = *(const float4*)(w2 + lane * 8 + 4);

    float pi = dot8_h(avi, bvi, wlo, whi);
    float pt = dot8_h(avt, bvt, wlo, whi);

    #pragma unroll
    for (int off = 16; off > 0; off >>= 1) {
        pi += __shfl_xor_sync(0xFFFFFFFFu, pi, off);
        pt += __shfl_xor_sync(0xFFFFFFFFu, pt, off);
    }
    if (lane == 0) {
        float bb = b2p[0];
        size_t base = (size_t)b * 262144 + (size_t)s * 512 + d;
        wout[base]           = 1.0f / (1.0f + __expf(-(pi + bb)));
        wout[base + 4194304] = 1.0f / (1.0f + __expf(-(pt + bb)));
    }
}

// ---------------------------------------------------------------------------
// FP16 tensor-core attention. 512 threads / 16 warps (256 query rows).
// K via cp.async [512][20]w; V transposed [40][260]w (rows 0-31 = data,
// row 32 = ones for mma-computed row sums, 33-39 = zero); P fp16 [16][20]w.
// exp via ex2.approx.f16x2 (softmax normalization cancels systematic bias).
// Smem 103040 B dynamic.
// ---------------------------------------------------------------------------
__global__ __launch_bounds__(512, 1)
void attn_f16(const __half* __restrict__ qbuf, int qld, size_t qzs,
              const __half* __restrict__ kbuf, int kld, size_t kzs,
              const __half* __restrict__ vbuf, int vld, size_t vzs,
              const float* __restrict__ mask, size_t mzs,
              __half* __restrict__ ctx, size_t czs)
{
    extern __shared__ uint32_t sm[];
    uint32_t* Ks = sm;               // [512 key][20]w
    uint32_t* Vt = sm + 10240;       // [40 d][260]w
    uint32_t* Pw = sm + 20640;       // 16 warps x [16 row][20]w

    int zb = blockIdx.z;
    int b = zb & 15, mz = zb >> 4;
    int h = blockIdx.y, chunk = blockIdx.x;
    int t = threadIdx.x, lane = t & 31, w = t >> 5;
    int gid = lane >> 2, tig = lane & 3;

    const __half* Qp = qbuf + (size_t)mz * qzs + h * 32;
    const __half* Kp = kbuf + (size_t)mz * kzs + (size_t)(b * 512) * kld + h * 32;
    const __half* Vp = vbuf + (size_t)mz * vzs + (size_t)(b * 512) * vld + h * 32;
    const float*  M  = mask ? mask + (size_t)mz * mzs + (size_t)b * 262144 : nullptr;
    __half* O = ctx + (size_t)mz * czs;

    uint32_t* Ps = Pw + w * 320;
    int i0 = chunk * 256 + w * 16;

    // K staging via cp.async (fp16, no cvt)
    for (int i = t; i < 2048; i += 512) {
        int key = i >> 2, c = i & 3;
        cp16((uint32_t)__cvta_generic_to_shared(&Ks[key * 20 + c * 4]),
             Kp + (size_t)key * kld + c * 8);
    }
    asm volatile("cp.async.commit_group;");

    // V transpose staging (rows 0-31)
    for (int id = t; id < 1024; id += 512) {
        int j2 = id & 255, c = id >> 8;
        uint4 A  = *(const uint4*)(Vp + (size_t)(2 * j2) * vld + c * 8);
        uint4 Bv = *(const uint4*)(Vp + (size_t)(2 * j2 + 1) * vld + c * 8);
        uint32_t* vt = Vt + (c * 8) * 260 + j2;
        vt[0 * 260] = __byte_perm(A.x, Bv.x, 0x5410);
        vt[1 * 260] = __byte_perm(A.x, Bv.x, 0x7632);
        vt[2 * 260] = __byte_perm(A.y, Bv.y, 0x5410);
        vt[3 * 260] = __byte_perm(A.y, Bv.y, 0x7632);
        vt[4 * 260] = __byte_perm(A.z, Bv.z, 0x5410);
        vt[5 * 260] = __byte_perm(A.z, Bv.z, 0x7632);
        vt[6 * 260] = __byte_perm(A.w, Bv.w, 0x5410);
        vt[7 * 260] = __byte_perm(A.w, Bv.w, 0x7632);
    }
    // rows 32 (ones) and 33-39 (zero)
    for (int i = t; i < 2080; i += 512)
        Vt[32 * 260 + i] = (i < 260) ? 0x3C003C00u : 0u;

    // Q fragments (fp16, pre-scaled)
    uint32_t qa[2][4];
    {
        const uint32_t* q0 = (const uint32_t*)(Qp + (size_t)(b * 512 + i0 + gid) * qld);
        const uint32_t* q1 = (const uint32_t*)(Qp + (size_t)(b * 512 + i0 + gid + 8) * qld);
        #pragma unroll
        for (int ks = 0; ks < 2; ks++) {
            qa[ks][0] = q0[ks * 8 + tig];
            qa[ks][1] = q1[ks * 8 + tig];
            qa[ks][2] = q0[ks * 8 + tig + 4];
            qa[ks][3] = q1[ks * 8 + tig + 4];
        }
    }

    const float* mrow0 = M ? M + (size_t)(i0 + gid) * 512 : nullptr;
    const float* mrow1 = mrow0 ? mrow0 + 8 * 512 : nullptr;

    float2 mv0[8], mv1[8];
    if (mrow0) {
        #pragma unroll
        for (int nt = 0; nt < 8; nt++) {
            int col = nt * 8 + 2 * tig;
            mv0[nt] = *(const float2*)(mrow0 + col);
            mv1[nt] = *(const float2*)(mrow1 + col);
        }
    }

    asm volatile("cp.async.wait_group 0;");
    __syncthreads();

    float oacc[4][4];
    #pragma unroll
    for (int vt = 0; vt < 4; vt++)
        #pragma unroll
        for (int q = 0; q < 4; q++) oacc[vt][q] = 0.0f;
    float rsacc[4] = {0.0f, 0.0f, 0.0f, 0.0f};

    const float L2E = 1.4426950408889634f;

    for (int kc = 0; kc < 8; kc++) {
        float sacc[8][4];
        #pragma unroll
        for (int nt = 0; nt < 8; nt++)
            #pragma unroll
            for (int q = 0; q < 4; q++) sacc[nt][q] = 0.0f;

        // S = Q K^T (fp16)
        #pragma unroll
        for (int ks = 0; ks < 2; ks++) {
            #pragma unroll
            for (int nt = 0; nt < 8; nt++) {
                int key = kc * 64 + nt * 8 + gid;
                uint32_t b0 = Ks[key * 20 + ks * 8 + tig];
                uint32_t b1 = Ks[key * 20 + ks * 8 + tig + 4];
                mma_f16(sacc[nt][0], sacc[nt][1], sacc[nt][2], sacc[nt][3],
                        qa[ks][0], qa[ks][1], qa[ks][2], qa[ks][3], b0, b1);
            }
        }

        // two 32-key halves: exp2.f16x2 -> P store -> PV (incl. ones column)
        #pragma unroll
        for (int hh = 0; hh < 2; hh++) {
            #pragma unroll
            for (int nt2 = 0; nt2 < 4; nt2++) {
                int nt = hh * 4 + nt2;
                float s0 = sacc[nt][0], s1 = sacc[nt][1];
                float s2 = sacc[nt][2], s3 = sacc[nt][3];
                if (mrow0) {
                    s0 += mv0[nt].x; s1 += mv0[nt].y;
                    s2 += mv1[nt].x; s3 += mv1[nt].y;
                }
                Ps[gid * 20 + nt2 * 4 + tig]       = h2exp2u(pack_h2(s0 * L2E, s1 * L2E));
                Ps[(gid + 8) * 20 + nt2 * 4 + tig] = h2exp2u(pack_h2(s2 * L2E, s3 * L2E));
            }
            if (hh == 1 && mrow0 && kc < 7) {
                #pragma unroll
                for (int nt = 0; nt < 8; nt++) {
                    int col = (kc + 1) * 64 + nt * 8 + 2 * tig;
                    mv0[nt] = *(const float2*)(mrow0 + col);
                    mv1[nt] = *(const float2*)(mrow1 + col);
                }
            }
            __syncwarp();

            int kb2base = kc * 32 + hh * 16;
            #pragma unroll
            for (int s = 0; s < 2; s++) {
                uint32_t a0 = Ps[gid * 20 + s * 8 + tig];
                uint32_t a1 = Ps[(gid + 8) * 20 + s * 8 + tig];
                uint32_t a2 = Ps[gid * 20 + s * 8 + tig + 4];
                uint32_t a3 = Ps[(gid + 8) * 20 + s * 8 + tig + 4];
                int kb2 = kb2base + s * 8;
                #pragma unroll
                for (int vt = 0; vt < 4; vt++) {
                    int d = vt * 8 + gid;
                    uint32_t b0 = Vt[d * 260 + kb2 + tig];
                    uint32_t b1 = Vt[d * 260 + kb2 + tig + 4];
                    mma_f16(oacc[vt][0], oacc[vt][1], oacc[vt][2], oacc[vt][3],
                            a0, a1, a2, a3, b0, b1);
                }
                // ones-column tile: row-sum accumulates in col 32 (tig==0, d0/d2)
                {
                    uint32_t b0 = Vt[(32 + gid) * 260 + kb2 + tig];
                    uint32_t b1 = Vt[(32 + gid) * 260 + kb2 + tig + 4];
                    mma_f16(rsacc[0], rsacc[1], rsacc[2], rsacc[3],
                            a0, a1, a2, a3, b0, b1);
                }
            }
            __syncwarp();
        }
    }

    // broadcast row sums from tig==0 within each quad
    float rsum0 = __shfl_sync(0xFFFFFFFFu, rsacc[0], lane & 28);
    float rsum1 = __shfl_sync(0xFFFFFFFFu, rsacc[2], lane & 28);
    float inv0 = 1.0f / rsum0, inv1 = 1.0f / rsum1;

    size_t r0 = (size_t)(b * 512 + i0 + gid) * 256 + h * 32;
    size_t r1 = r0 + (size_t)8 * 256;
    #pragma unroll
    for (int vt = 0; vt < 4; vt++) {
        *(__half2*)(O + r0 + vt * 8 + 2 * tig) =
            __floats2half2_rn(oacc[vt][0] * inv0, oacc[vt][1] * inv0);
        *(__half2*)(O + r1 + vt * 8 + 2 * tig) =
            __floats2half2_rn(oacc[vt][2] * inv1, oacc[vt][3] * inv1);
    }
}

// ---------------------------------------------------------------------------
__global__ void cons_reduce(const float* __restrict__ H, const float* __restrict__ cw2,
                            const float* __restrict__ cb2, float* __restrict__ out)
{
    int gw   = (blockIdx.x * blockDim.x + threadIdx.x) >> 5;
    int lane = threadIdx.x & 31;
    const float4* h4 = (const float4*)(H + (size_t)gw * 256);
    const float4* w4 = (const float4*)cw2;
    float p = 0.0f;
    #pragma unroll
    for (int u = 0; u < 2; u++) {
        int idx = u * 32 + lane;
        float4 a = h4[idx], w = w4[idx];
        p += a.x * w.x + a.y * w.y + a.z * w.z + a.w * w.w;
    }
    #pragma unroll
    for (int off = 16; off > 0; off >>= 1)
        p += __shfl_xor_sync(0xFFFFFFFFu, p, off);
    if (lane == 0)
        out[gw] = 1.0f / (1.0f + __expf(-(p + cb2[0])));
}

// ---------------------------------------------------------------------------
extern "C" void kernel_launch(void* const* d_in, const int* in_sizes, int n_in,
                              void* d_out, int out_size)
{
    const float* img   = (const float*)d_in[0];
    const float* txt   = (const float*)d_in[1];
    const int*   src   = (const int*)  d_in[2];
    const int*   dst   = (const int*)  d_in[3];
    const float* w1    = (const float*)d_in[4];
    const float* b1    = (const float*)d_in[5];
    const float* w2    = (const float*)d_in[6];
    const float* b2    = (const float*)d_in[7];
    const float* in_w  = (const float*)d_in[8];
    const float* in_b  = (const float*)d_in[9];
    const float* out_w = (const float*)d_in[10];
    const float* out_b = (const float*)d_in[11];
    const float* cw1   = (const float*)d_in[12];
    const float* cb1   = (const float*)d_in[13];
    const float* cw2   = (const float*)d_in[14];
    const float* cb2   = (const float*)d_in[15];
    float* out = (float*)d_out;

    float* S = nullptr;
    cudaGetSymbolAddress((void**)&S, g_scratch);

    uint32_t* wcat  = (uint32_t*)(S + OFF_WCAT);
    float*    bias1 = S + OFF_BIAS1;
    uint32_t* wot   = (uint32_t*)(S + OFF_WOT);
    __half*   qkvh  = (__half*)(S + OFF_PROJ);
    float*    Hbuf  = S + OFF_HBUF;
    __half*   ctx   = (__half*)(S + OFF_CTX);
    __half*   qch   = (__half*)(S + OFF_QC);
    __half*   kvch  = (__half*)(S + OFF_KVC);
    __half*   ctx2  = (__half*)(S + OFF_CTX2);
    uint32_t* intf  = (uint32_t*)(S + OFF_INT);
    __half*   attf  = (__half*)(S + OFF_ATTF);
    uint32_t* cw1t  = (uint32_t*)(S + OFF_CW1T);

    float* att_img = out;
    float* att_txt = out + 2097152;
    float* cross   = out + 4194304;
    float* wimg    = out + 6291456;
    float* cons    = out + 14680064;

    const int ATTN_SMEM = 103040;
    cudaFuncSetAttribute(attn_f16, cudaFuncAttributeMaxDynamicSharedMemorySize, ATTN_SMEM);

    const size_t QKVZS = (size_t)8192 * 1280;
    const size_t CSTRIDE = (size_t)8192 * 256;
    const size_t MSTRIDE = (size_t)4194304;

    // 1. prep (wq/bq pre-scaled by 1/sqrt(32))
    prep_kernel<<<4997, 256>>>(img, txt, intf,
                               w1, b1, in_w, in_b, out_w, cw1,
                               wcat, bias1, wot, cw1t);

    // 2. zero both weight matrices
    cudaMemsetAsync(wimg, 0, (size_t)8388608 * 4);

    // 3. projections -> qkvh fp16
    gemm_f16<<<dim3(64, 10, 2), 256>>>(intf, intf + (size_t)8192 * 128, 128,
                                       wcat, 1280, 0, bias1, 0,
                                       nullptr, 1280, 0, 0, qkvh, QKVZS);

    // 4. per-edge causal weights
    edge_kernel<<<32768, 256>>>(qkvh, src, dst, w2, b2, wimg);

    // 5. masked self-attention (fp16), both modalities
    attn_f16<<<dim3(2, 8, 32), 512, ATTN_SMEM>>>(
        qkvh + 512, 1280, QKVZS,
        qkvh + 768, 1280, QKVZS,
        qkvh + 1024, 1280, QKVZS,
        wimg, MSTRIDE,
        ctx, CSTRIDE);

    // 6. out-proj -> attended_* (fp32) + fp16 attf
    gemm_f16<<<dim3(128, 2, 1), 256>>>((const uint32_t*)ctx, (const uint32_t*)ctx, 128,
                                       wot, 256, 0, out_b, 0,
                                       att_img, 256, 0, 0, attf, 0);

    // 7. consistency
    gemm_f16<<<dim3(128, 2, 1), 256>>>((const uint32_t*)attf, (const uint32_t*)attf, 128,
                                       cw1t, 256, 0, cb1, 0,
                                       Hbuf, 256, 0, 1, nullptr, 0);
    cons_reduce<<<2048, 256>>>(Hbuf, cw2, cb2, cons);

    // 8. cross-modal
    gemm_f16<<<dim3(64, 2, 1), 256>>>((const uint32_t*)attf, (const uint32_t*)attf, 128,
                                      wcat, 1280, 512, bias1, 512,
                                      nullptr, 256, 0, 0, qch, 0);
    gemm_f16<<<dim3(64, 4, 1), 256>>>((const uint32_t*)(attf + (size_t)8192 * 256),
                                      (const uint32_t*)attf, 128,
                                      wcat, 1280, 768, bias1, 768,
                                      nullptr, 512, 0, 0, kvch, 0);
    attn_f16<<<dim3(2, 8, 16), 512, ATTN_SMEM>>>(
        qch, 256, 0,
        kvch, 512, 0,
        kvch + 256, 512, 0,
        nullptr, 0,
        ctx2, 0);
    gemm_f16<<<dim3(64, 2, 1), 256>>>((const uint32_t*)ctx2, (const uint32_t*)ctx2, 128,
                                      wot, 256, 0, out_b, 0,
                                      cross, 256, 0, 0, nullptr, 0);
}